// round 11
// baseline (speedup 1.0000x reference)
#include <cuda_runtime.h>
#include <cuda_fp16.h>
#include <cstdint>

#define MTOK   65536
#define HDIM   1024
#define KSEL   256

// ---------------------------------------------------------------------------
// Static scratch. Halves: splits of (value*512). fp32 ping-pong: true values.
// ---------------------------------------------------------------------------
__device__ __half g_a0[(size_t)MTOK * HDIM];
__device__ __half g_a1[(size_t)MTOK * HDIM];
__device__ __half g_a2[(size_t)MTOK * HDIM];
__device__ __half g_b0[(size_t)MTOK * HDIM];
__device__ __half g_b1[(size_t)MTOK * HDIM];
__device__ __half g_b2[(size_t)MTOK * HDIM];
__device__ float  g_hF[(size_t)MTOK * HDIM];
__device__ float  g_f0[(size_t)MTOK * HDIM];
__device__ float  g_f1[(size_t)MTOK * HDIM];
#define WT_TOTAL 2621440
__device__ __half g_w0[WT_TOTAL];
__device__ __half g_w1[WT_TOTAL];
__device__ __half g_w2[WT_TOTAL];

// ---------------------------------------------------------------------------
// Helpers
// ---------------------------------------------------------------------------
__device__ __forceinline__ uint32_t smem_u32(const void* p) {
    uint32_t a;
    asm("{ .reg .u64 t; cvta.to.shared.u64 t, %1; cvt.u32.u64 %0, t; }" : "=r"(a) : "l"(p));
    return a;
}
__device__ __forceinline__ void ldsm4(uint32_t* r, uint32_t addr) {
    asm volatile("ldmatrix.sync.aligned.m8n8.x4.shared.b16 {%0,%1,%2,%3}, [%4];"
                 : "=r"(r[0]), "=r"(r[1]), "=r"(r[2]), "=r"(r[3]) : "r"(addr));
}
__device__ __forceinline__ float lds32f(uint32_t a) {
    float v;
    asm volatile("ld.shared.f32 %0, [%1];" : "=f"(v) : "r"(a));
    return v;
}
__device__ __forceinline__ float4 lds128f(uint32_t a) {
    float4 v;
    asm volatile("ld.shared.v4.f32 {%0,%1,%2,%3}, [%4];"
                 : "=f"(v.x), "=f"(v.y), "=f"(v.z), "=f"(v.w) : "r"(a));
    return v;
}
__device__ __forceinline__ void cp16(uint32_t dst, const void* src) {
    asm volatile("cp.async.cg.shared.global [%0], [%1], 16;" :: "r"(dst), "l"(src) : "memory");
}
__device__ __forceinline__ void mma16816(float* c, const uint32_t* a, uint32_t b0, uint32_t b1) {
    asm volatile(
        "mma.sync.aligned.m16n8k16.row.col.f32.f16.f16.f32 "
        "{%0,%1,%2,%3}, {%4,%5,%6,%7}, {%8,%9}, {%0,%1,%2,%3};"
        : "+f"(c[0]), "+f"(c[1]), "+f"(c[2]), "+f"(c[3])
        : "r"(a[0]), "r"(a[1]), "r"(a[2]), "r"(a[3]), "r"(b0), "r"(b1));
}
__device__ __forceinline__ void mma16816_z(float* d, const uint32_t* a, uint32_t b0, uint32_t b1) {
    asm volatile(
        "mma.sync.aligned.m16n8k16.row.col.f32.f16.f16.f32 "
        "{%0,%1,%2,%3}, {%4,%5,%6,%7}, {%8,%9}, {%10,%11,%12,%13};"
        : "=f"(d[0]), "=f"(d[1]), "=f"(d[2]), "=f"(d[3])
        : "r"(a[0]), "r"(a[1]), "r"(a[2]), "r"(a[3]), "r"(b0), "r"(b1),
          "f"(0.0f), "f"(0.0f), "f"(0.0f), "f"(0.0f));
}
__device__ __forceinline__ uint32_t pack_h2(__half a, __half b) {
    __half2 h2 = __halves2half2(a, b);
    return *reinterpret_cast<uint32_t*>(&h2);
}

// ---------------------------------------------------------------------------
// Hybrid GEMM: per 128x128 CTA tile,
//   cols 0..95  : HMMA split-fp16 (numerics identical to Rounds 7-10),
//   cols 96..127: true fp32 FFMA GEMM (A from fp32 copy, W from original fp32),
// overlapping the tensor pipe (rt=16) with the otherwise-idle FMA pipe.
// 16 warps; warp_m = wid&3 (so each SMSP gets 3 mma warps + 1 ffma warp).
// 2-stage cp.async. Every non-final layer writes halves splits + fp32 copy FO.
// ---------------------------------------------------------------------------
template<int MODE>   // 0 = encoder (3 parts, 6 terms), 1 = decoder (2 parts, 3 terms)
__global__ __launch_bounds__(512, 1)
void gemm_hyb(const __half* __restrict__ A0, const __half* __restrict__ A1,
              const __half* __restrict__ A2,
              const __half* __restrict__ W0, const __half* __restrict__ W1,
              const __half* __restrict__ W2,
              const float* __restrict__ AF,   // fp32 activations [M,K]
              const float* __restrict__ WF,   // original fp32 weights [K,N]
              const float* __restrict__ bias, const float* __restrict__ mask,
              __half* __restrict__ O0, __half* __restrict__ O1,
              __half* __restrict__ O2, float* __restrict__ FO,
              float* __restrict__ OF,
              int N, int K, int relu)
{
    constexpr int NPA = (MODE == 0) ? 3 : 2;
    constexpr int NT  = (MODE == 0) ? 6 : 3;
    constexpr int NPARTS = 2 * NPA;
    constexpr uint32_t PART  = 10240;              // 128 rows * 80B halves
    constexpr uint32_t AOFF  = NPARTS * PART;      // fp32 A tile [m:128][k:36f] 144B rows
    constexpr uint32_t BOFF  = AOFF + 128u * 144u; // fp32 W tile [k:32][n:36f] 144B rows
    constexpr uint32_t STAGE = BOFF + 32u * 144u;
    constexpr int TOT = NPARTS * 512 + 1024 + 256; // cp16 per stage
    constexpr int PA_[2][6] = {{0, 1, 0, 2, 1, 0}, {0, 1, 0, 0, 0, 0}};
    constexpr int PB_[2][6] = {{0, 0, 1, 0, 1, 2}, {0, 0, 1, 0, 0, 0}};

    extern __shared__ __align__(16) char smem_raw[];
    const uint32_t smb = smem_u32(smem_raw);

    const int tid    = threadIdx.x;
    const int wid    = tid >> 5;
    const int lane   = tid & 31;
    const int warp_m = wid & 3;      // 0..3  (SMSP-spread)
    const int warp_n = wid >> 2;     // 0..3  (3 = ffma warp)
    const int g      = lane >> 2;
    const int tg     = lane & 3;
    const int bm     = blockIdx.y * 128;
    const int bn     = blockIdx.x * 128;
    const int C      = K >> 5;

    const __half* Pp[6];
    Pp[0] = A0; Pp[1] = A1; Pp[2] = (MODE == 0) ? A2 : W0;
    if (MODE == 0) { Pp[3] = W0; Pp[4] = W1; Pp[5] = W2; }
    else           { Pp[3] = W1; }

    auto load_stage = [&](int c, int slot) {
        const uint32_t sbase = smb + (uint32_t)slot * STAGE;
        for (int i = tid; i < TOT; i += 512) {
            const void* src;
            uint32_t dst;
            if (i < NPARTS * 512) {
                int p = i >> 9, j = i & 511;
                int row = j >> 2, ch = j & 3;
                src = Pp[p] + (size_t)((p < NPA ? bm : bn) + row) * K + c * 32 + ch * 8;
                dst = sbase + (uint32_t)p * PART + (uint32_t)row * 80u + (uint32_t)ch * 16u;
            } else if (i < NPARTS * 512 + 1024) {
                int j = i - NPARTS * 512;
                int row = j >> 3, ch = j & 7;
                src = AF + (size_t)(bm + row) * K + c * 32 + ch * 4;
                dst = sbase + AOFF + (uint32_t)row * 144u + (uint32_t)ch * 16u;
            } else {
                int j = i - NPARTS * 512 - 1024;
                int row = j >> 3, ch = j & 7;
                src = WF + (size_t)(c * 32 + row) * N + bn + 96 + ch * 4;
                dst = sbase + BOFF + (uint32_t)row * 144u + (uint32_t)ch * 16u;
            }
            cp16(dst, src);
        }
        asm volatile("cp.async.commit_group;" ::: "memory");
    };

    load_stage(0, 0);
    if (C > 1) load_stage(1, 1);

    // 32 accumulators shared by both paths:
    //   hmma: acc[mt*16 + nt*4 + e]   ffma: acc[i*4 + j]
    float acc[32];
    #pragma unroll
    for (int i = 0; i < 32; i++) acc[i] = 0.0f;

    // ldmatrix lane offsets (hmma path)
    const uint32_t laneAoff =
        (uint32_t)(((lane & 7) + ((lane >> 3) & 1) * 8) * 80 + ((lane >> 4) & 1) * 16);
    const uint32_t laneBoff =
        (uint32_t)(((lane & 7) + ((lane >> 4) & 1) * 8) * 80 + ((lane >> 3) & 1) * 16);
    const uint32_t aWarpOff = (uint32_t)(warp_m * 32) * 80u + laneAoff;
    const uint32_t bWarpOff = (uint32_t)(warp_n * 32) * 80u + laneBoff;

    // ffma lane mapping: tx = n-group (0..7), ty = m-phase (0..3); m = wm*32+ty+4i
    const int tx = lane & 7;
    const int ty = lane >> 3;

    for (int c = 0; c < C; c++) {
        if (c + 1 < C) asm volatile("cp.async.wait_group 1;" ::: "memory");
        else           asm volatile("cp.async.wait_group 0;" ::: "memory");
        __syncthreads();

        const uint32_t sb0 = smb + (uint32_t)(c & 1) * STAGE;

        if (warp_n == 3) {
            // ---------------- fp32 FFMA path (cols 96..127) ----------------
            const uint32_t As = sb0 + AOFF + (uint32_t)(warp_m * 32 + ty) * 144u;
            const uint32_t Bs = sb0 + BOFF + (uint32_t)tx * 16u;
            #pragma unroll
            for (int k = 0; k < 32; k++) {
                float4 bv = lds128f(Bs + (uint32_t)k * 144u);
                #pragma unroll
                for (int i = 0; i < 8; i++) {
                    float av = lds32f(As + (uint32_t)(4 * i) * 144u + (uint32_t)k * 4u);
                    acc[i * 4 + 0] = fmaf(av, bv.x, acc[i * 4 + 0]);
                    acc[i * 4 + 1] = fmaf(av, bv.y, acc[i * 4 + 1]);
                    acc[i * 4 + 2] = fmaf(av, bv.z, acc[i * 4 + 2]);
                    acc[i * 4 + 3] = fmaf(av, bv.w, acc[i * 4 + 3]);
                }
            }
        } else if (MODE == 0) {
            // ---------------- HMMA encoder (debiased) ----------------
            #pragma unroll
            for (int kh = 0; kh < 2; kh++) {
                float tmp[2][4][4];
                #pragma unroll
                for (int t = 0; t < NT; t++) {
                    const uint32_t aBase = sb0 + (uint32_t)PA_[0][t] * PART + aWarpOff
                                         + (uint32_t)kh * 32u;
                    const uint32_t bBase = sb0 + (uint32_t)(NPA + PB_[0][t]) * PART + bWarpOff
                                         + (uint32_t)kh * 32u;
                    uint32_t af[2][4], bf[2][4];
                    ldsm4(af[0], aBase);
                    ldsm4(af[1], aBase + 16u * 80u);
                    ldsm4(bf[0], bBase);
                    ldsm4(bf[1], bBase + 16u * 80u);
                    #pragma unroll
                    for (int nt = 0; nt < 4; nt++) {
                        uint32_t b0 = bf[nt >> 1][(nt & 1) * 2];
                        uint32_t b1 = bf[nt >> 1][(nt & 1) * 2 + 1];
                        #pragma unroll
                        for (int mt = 0; mt < 2; mt++) {
                            if (t == 0) mma16816_z(tmp[mt][nt], af[mt], b0, b1);
                            else        mma16816(tmp[mt][nt], af[mt], b0, b1);
                        }
                    }
                }
                #pragma unroll
                for (int mt = 0; mt < 2; mt++)
                    #pragma unroll
                    for (int nt = 0; nt < 4; nt++)
                        #pragma unroll
                        for (int e = 0; e < 4; e++)
                            acc[mt * 16 + nt * 4 + e] += tmp[mt][nt][e];
            }
        } else {
            // ---------------- HMMA decoder (chained) ----------------
            #pragma unroll
            for (int t = 0; t < NT; t++) {
                #pragma unroll
                for (int kh = 0; kh < 2; kh++) {
                    const uint32_t aBase = sb0 + (uint32_t)PA_[1][t] * PART + aWarpOff
                                         + (uint32_t)kh * 32u;
                    const uint32_t bBase = sb0 + (uint32_t)(NPA + PB_[1][t]) * PART + bWarpOff
                                         + (uint32_t)kh * 32u;
                    uint32_t af[2][4], bf[2][4];
                    ldsm4(af[0], aBase);
                    ldsm4(af[1], aBase + 16u * 80u);
                    ldsm4(bf[0], bBase);
                    ldsm4(bf[1], bBase + 16u * 80u);
                    #pragma unroll
                    for (int nt = 0; nt < 4; nt++) {
                        uint32_t b0 = bf[nt >> 1][(nt & 1) * 2];
                        uint32_t b1 = bf[nt >> 1][(nt & 1) * 2 + 1];
                        #pragma unroll
                        for (int mt = 0; mt < 2; mt++) {
                            float* cc = &acc[mt * 16 + nt * 4];
                            mma16816(cc, af[mt], b0, b1);
                        }
                    }
                }
            }
        }
        __syncthreads();
        if (c + 2 < C) load_stage(c + 2, c & 1);
    }

    // ---------------- epilogues ----------------
    if (warp_n == 3) {
        // fp32 path: true values already (no scaling)
        #pragma unroll
        for (int i = 0; i < 8; i++) {
            const int row = bm + warp_m * 32 + ty + 4 * i;
            const int col = bn + 96 + tx * 4;
            const size_t idx = (size_t)row * N + col;
            float v[4];
            #pragma unroll
            for (int j = 0; j < 4; j++) {
                float x = acc[i * 4 + j] + __ldg(bias + col + j);
                if (relu) x = fmaxf(x, 0.0f);
                v[j] = x;
            }
            if (OF) {
                if (mask) {
                    const float4 m = *(const float4*)(mask + idx);
                    if (m.x > 0.f) v[0] = 0.f;
                    if (m.y > 0.f) v[1] = 0.f;
                    if (m.z > 0.f) v[2] = 0.f;
                    if (m.w > 0.f) v[3] = 0.f;
                }
                *(float4*)(OF + idx) = make_float4(v[0], v[1], v[2], v[3]);
            } else {
                uint32_t p0[2], p1[2], p2[2];
                #pragma unroll
                for (int e = 0; e < 2; e++) {
                    float s0 = v[2 * e] * 512.f, s1 = v[2 * e + 1] * 512.f;
                    __half h0 = __float2half_rn(s0), h1 = __float2half_rn(s1);
                    float r0 = s0 - __half2float(h0), r1 = s1 - __half2float(h1);
                    __half q0 = __float2half_rn(r0), q1 = __float2half_rn(r1);
                    p0[e] = pack_h2(h0, h1);
                    p1[e] = pack_h2(q0, q1);
                    if (MODE == 0)
                        p2[e] = pack_h2(__float2half_rn(r0 - __half2float(q0)),
                                        __float2half_rn(r1 - __half2float(q1)));
                }
                *(uint2*)(O0 + idx) = make_uint2(p0[0], p0[1]);
                *(uint2*)(O1 + idx) = make_uint2(p1[0], p1[1]);
                if (MODE == 0) *(uint2*)(O2 + idx) = make_uint2(p2[0], p2[1]);
                *(float4*)(FO + idx) = make_float4(v[0], v[1], v[2], v[3]);
            }
        }
    } else {
        const float SCL = 1.0f / 262144.0f;   // 2^-18
        #pragma unroll
        for (int mt = 0; mt < 2; mt++) {
            #pragma unroll
            for (int nt = 0; nt < 4; nt++) {
                const int row = bm + warp_m * 32 + mt * 16 + g;
                const int col = bn + warp_n * 32 + nt * 8 + tg * 2;
                const float bz0 = __ldg(bias + col);
                const float bz1 = __ldg(bias + col + 1);
                const float* a4 = &acc[mt * 16 + nt * 4];
                float v0 = a4[0] * SCL + bz0;
                float v1 = a4[1] * SCL + bz1;
                float v2 = a4[2] * SCL + bz0;   // row + 8
                float v3 = a4[3] * SCL + bz1;
                if (relu) {
                    v0 = fmaxf(v0, 0.f); v1 = fmaxf(v1, 0.f);
                    v2 = fmaxf(v2, 0.f); v3 = fmaxf(v3, 0.f);
                }
                const size_t i0 = (size_t)row * N + col;
                const size_t i1 = (size_t)(row + 8) * N + col;
                if (OF) {
                    if (mask) {
                        const float2 m0 = *(const float2*)(mask + i0);
                        const float2 m1 = *(const float2*)(mask + i1);
                        if (m0.x > 0.f) v0 = 0.f;
                        if (m0.y > 0.f) v1 = 0.f;
                        if (m1.x > 0.f) v2 = 0.f;
                        if (m1.y > 0.f) v3 = 0.f;
                    }
                    *(float2*)(OF + i0) = make_float2(v0, v1);
                    *(float2*)(OF + i1) = make_float2(v2, v3);
                } else {
                    float s0 = v0 * 512.f, s1 = v1 * 512.f;
                    float s2 = v2 * 512.f, s3 = v3 * 512.f;
                    __half h0 = __float2half_rn(s0), h1 = __float2half_rn(s1);
                    __half h2 = __float2half_rn(s2), h3 = __float2half_rn(s3);
                    float r0 = s0 - __half2float(h0), r1 = s1 - __half2float(h1);
                    float r2 = s2 - __half2float(h2), r3 = s3 - __half2float(h3);
                    __half q0 = __float2half_rn(r0), q1 = __float2half_rn(r1);
                    __half q2 = __float2half_rn(r2), q3 = __float2half_rn(r3);
                    *(uint32_t*)(O0 + i0) = pack_h2(h0, h1);
                    *(uint32_t*)(O0 + i1) = pack_h2(h2, h3);
                    *(uint32_t*)(O1 + i0) = pack_h2(q0, q1);
                    *(uint32_t*)(O1 + i1) = pack_h2(q2, q3);
                    if (MODE == 0) {
                        *(uint32_t*)(O2 + i0) = pack_h2(__float2half_rn(r0 - __half2float(q0)),
                                                        __float2half_rn(r1 - __half2float(q1)));
                        *(uint32_t*)(O2 + i1) = pack_h2(__float2half_rn(r2 - __half2float(q2)),
                                                        __float2half_rn(r3 - __half2float(q3)));
                    }
                    *(float2*)(FO + i0) = make_float2(v0, v1);
                    *(float2*)(FO + i1) = make_float2(v2, v3);
                }
            }
        }
    }
}

// ---------------------------------------------------------------------------
// x -> 3-way fp16 split (scaled by 512)
// ---------------------------------------------------------------------------
__global__ void conv_x_kernel(const float* __restrict__ x,
                              __half* __restrict__ o0, __half* __restrict__ o1,
                              __half* __restrict__ o2)
{
    size_t i = ((size_t)blockIdx.x * blockDim.x + threadIdx.x) * 2;
    float x0 = x[i] * 512.f, x1 = x[i + 1] * 512.f;
    __half h0 = __float2half_rn(x0), h1 = __float2half_rn(x1);
    float r0 = x0 - __half2float(h0), r1 = x1 - __half2float(h1);
    __half q0 = __float2half_rn(r0), q1 = __float2half_rn(r1);
    __half u0 = __float2half_rn(r0 - __half2float(q0));
    __half u1 = __float2half_rn(r1 - __half2float(q1));
    *(uint32_t*)(o0 + i) = pack_h2(h0, h1);
    *(uint32_t*)(o1 + i) = pack_h2(q0, q1);
    *(uint32_t*)(o2 + i) = pack_h2(u0, u1);
}

// ---------------------------------------------------------------------------
// Fused weight conversion: all 8 layers in ONE launch (so ncu -s 5 lands on a
// GEMM). W[K,N] -> transposed split parts (scaled by 512): o[n*K+k].
// ---------------------------------------------------------------------------
struct WArgs {
    const float* src[8];
    unsigned off[8];
    int ksh[8];
    int N[8];
    int np[8];
};
__global__ void conv_w_all(WArgs A, __half* __restrict__ o0,
                           __half* __restrict__ o1, __half* __restrict__ o2)
{
    const int l = blockIdx.y;
    const int tot = A.N[l] << A.ksh[l];
    const int idx = blockIdx.x * blockDim.x + threadIdx.x;
    if (idx >= tot) return;
    const int n = idx >> A.ksh[l];
    const int k = idx & ((1 << A.ksh[l]) - 1);
    float w = A.src[l][(size_t)k * A.N[l] + n] * 512.f;
    __half h = __float2half_rn(w);
    float r = w - __half2float(h);
    __half q = __float2half_rn(r);
    const unsigned o = A.off[l] + idx;
    o0[o] = h;
    o1[o] = q;
    if (A.np[l] == 3) o2[o] = __float2half_rn(r - __half2float(q));
}

// ---------------------------------------------------------------------------
// Exact per-token top-256-of-1024 by h^2 (radix select on float bit pattern).
// Outputs: 2-way fp16 split (scaled 512) AND true fp32 copy.
// ---------------------------------------------------------------------------
__global__ __launch_bounds__(256)
void topk_mask_kernel(const float* __restrict__ H,
                      __half* __restrict__ o0, __half* __restrict__ o1,
                      float* __restrict__ oF)
{
    const int tid = threadIdx.x;
    const size_t row = (size_t)blockIdx.x * HDIM;

    __shared__ unsigned ebits[HDIM];
    __shared__ unsigned hist[256];
    __shared__ unsigned sc[256];
    __shared__ unsigned s_pref, s_r;

    float4 hv = ((const float4*)(H + row))[tid];
    unsigned v0 = __float_as_uint(hv.x * hv.x);
    unsigned v1 = __float_as_uint(hv.y * hv.y);
    unsigned v2 = __float_as_uint(hv.z * hv.z);
    unsigned v3 = __float_as_uint(hv.w * hv.w);
    ebits[4 * tid + 0] = v0; ebits[4 * tid + 1] = v1;
    ebits[4 * tid + 2] = v2; ebits[4 * tid + 3] = v3;
    if (tid == 0) { s_pref = 0u; s_r = KSEL; }
    __syncthreads();

    #pragma unroll
    for (int pass = 0; pass < 4; pass++) {
        const int shift = 24 - 8 * pass;
        const unsigned pref = s_pref;
        const unsigned r    = s_r;
        hist[tid] = 0u;
        __syncthreads();
        #pragma unroll
        for (int j = 0; j < 4; j++) {
            unsigned v = ebits[4 * tid + j];
            bool cand = (pass == 0) || ((v >> (shift + 8)) == (pref >> (shift + 8)));
            if (cand) atomicAdd(&hist[(v >> shift) & 0xFFu], 1u);
        }
        __syncthreads();
        sc[tid] = hist[tid];
        __syncthreads();
        for (int off = 1; off < 256; off <<= 1) {
            unsigned add = (tid + off < 256) ? sc[tid + off] : 0u;
            __syncthreads();
            sc[tid] += add;
            __syncthreads();
        }
        unsigned above = (tid == 255) ? 0u : sc[tid + 1];
        if (sc[tid] >= r && above < r) {
            s_pref = pref | ((unsigned)tid << shift);
            s_r    = r - above;
        }
        __syncthreads();
    }

    const unsigned thr  = s_pref;
    const unsigned need = s_r;

    unsigned vv[4] = {v0, v1, v2, v3};
    unsigned pos[4];
    unsigned myc = 0;
    #pragma unroll
    for (int j = 0; j < 4; j++) { pos[j] = myc; myc += (vv[j] == thr) ? 1u : 0u; }
    sc[tid] = myc;
    __syncthreads();
    for (int off = 1; off < 256; off <<= 1) {
        unsigned add = (tid >= off) ? sc[tid - off] : 0u;
        __syncthreads();
        sc[tid] += add;
        __syncthreads();
    }
    const unsigned base = sc[tid] - myc;

    float h[4] = {hv.x, hv.y, hv.z, hv.w};
    uint32_t w0[2], w1[2];
    float of[4];
    #pragma unroll
    for (int e = 0; e < 2; e++) {
        __half hh[2], ll[2];
        #pragma unroll
        for (int q = 0; q < 2; q++) {
            int j = 2 * e + q;
            bool keep = (vv[j] > thr) || (vv[j] == thr && (base + pos[j]) < need);
            float t = keep ? h[j] : 0.0f;
            of[j] = t;
            float o = t * 512.f;
            hh[q] = __float2half_rn(o);
            ll[q] = __float2half_rn(o - __half2float(hh[q]));
        }
        w0[e] = pack_h2(hh[0], hh[1]);
        w1[e] = pack_h2(ll[0], ll[1]);
    }
    ((uint2*)(o0 + row))[tid] = make_uint2(w0[0], w0[1]);
    ((uint2*)(o1 + row))[tid] = make_uint2(w1[0], w1[1]);
    ((float4*)(oF + row))[tid] = make_float4(of[0], of[1], of[2], of[3]);
}

// ---------------------------------------------------------------------------
// kernel_launch
// ---------------------------------------------------------------------------
extern "C" void kernel_launch(void* const* d_in, const int* in_sizes, int n_in,
                              void* d_out, int out_size)
{
    const float* x         = (const float*)d_in[0];
    const float* mask_prev = (const float*)d_in[1];
    const bool inter = (in_sizes[4] == HDIM * 512);

    const float *ew[4], *eb[4], *dw[4], *db[4];
    for (int i = 0; i < 4; i++) {
        if (inter) {
            ew[i] = (const float*)d_in[2 + 4 * i]; eb[i] = (const float*)d_in[3 + 4 * i];
            dw[i] = (const float*)d_in[4 + 4 * i]; db[i] = (const float*)d_in[5 + 4 * i];
        } else {
            ew[i] = (const float*)d_in[2 + 2 * i]; eb[i] = (const float*)d_in[3 + 2 * i];
            dw[i] = (const float*)d_in[10 + 2 * i]; db[i] = (const float*)d_in[11 + 2 * i];
        }
    }

    __half *a0, *a1, *a2, *b0, *b1, *b2, *w0, *w1, *w2;
    float *hF, *f0, *f1;
    cudaGetSymbolAddress((void**)&a0, g_a0); cudaGetSymbolAddress((void**)&a1, g_a1);
    cudaGetSymbolAddress((void**)&a2, g_a2); cudaGetSymbolAddress((void**)&b0, g_b0);
    cudaGetSymbolAddress((void**)&b1, g_b1); cudaGetSymbolAddress((void**)&b2, g_b2);
    cudaGetSymbolAddress((void**)&w0, g_w0); cudaGetSymbolAddress((void**)&w1, g_w1);
    cudaGetSymbolAddress((void**)&w2, g_w2); cudaGetSymbolAddress((void**)&hF, g_hF);
    cudaGetSymbolAddress((void**)&f0, g_f0); cudaGetSymbolAddress((void**)&f1, g_f1);

    // stage = NPARTS*10240 + 128*144 + 32*144 ; two stages
    const int SM_ENC = 2 * (6 * 10240 + 128 * 144 + 32 * 144);   // 168960
    const int SM_DEC = 2 * (4 * 10240 + 128 * 144 + 32 * 144);   // 128000
    cudaFuncSetAttribute(gemm_hyb<0>, cudaFuncAttributeMaxDynamicSharedMemorySize, SM_ENC);
    cudaFuncSetAttribute(gemm_hyb<1>, cudaFuncAttributeMaxDynamicSharedMemorySize, SM_DEC);

    // ---- weight conversion (one fused launch) ----
    struct { const float* w; int K, N; unsigned off; int np; } L[8] = {
        {ew[0], 512, 512, 0, 3},        {ew[1], 512, 512, 262144, 3},
        {ew[2], 512, 512, 524288, 3},   {ew[3], 512, 1024, 786432, 3},
        {dw[0], 1024, 512, 1310720, 2}, {dw[1], 512, 512, 1835008, 2},
        {dw[2], 512, 512, 2097152, 2},  {dw[3], 512, 512, 2359296, 2}};
    WArgs wa;
    for (int l = 0; l < 8; l++) {
        wa.src[l] = L[l].w;
        wa.off[l] = L[l].off;
        wa.ksh[l] = (L[l].K == 1024) ? 10 : 9;
        wa.N[l]   = L[l].N;
        wa.np[l]  = L[l].np;
    }
    conv_w_all<<<dim3(2048, 8), 256>>>(wa, w0, w1, w2);

    // ---- x split ----
    conv_x_kernel<<<(MTOK * 512 / 2) / 256, 256>>>(x, a0, a1, a2);

    const dim3 blk(512);
    // ---- encoder ----
    gemm_hyb<0><<<dim3(4, 512), blk, SM_ENC>>>(a0, a1, a2,
        w0 + L[0].off, w1 + L[0].off, w2 + L[0].off,
        x, ew[0], eb[0], nullptr,
        b0, b1, b2, f0, nullptr, 512, 512, 1);
    gemm_hyb<0><<<dim3(4, 512), blk, SM_ENC>>>(b0, b1, b2,
        w0 + L[1].off, w1 + L[1].off, w2 + L[1].off,
        f0, ew[1], eb[1], nullptr,
        a0, a1, a2, f1, nullptr, 512, 512, 1);
    gemm_hyb<0><<<dim3(4, 512), blk, SM_ENC>>>(a0, a1, a2,
        w0 + L[2].off, w1 + L[2].off, w2 + L[2].off,
        f1, ew[2], eb[2], nullptr,
        b0, b1, b2, f0, nullptr, 512, 512, 1);
    gemm_hyb<0><<<dim3(8, 512), blk, SM_ENC>>>(b0, b1, b2,
        w0 + L[3].off, w1 + L[3].off, w2 + L[3].off,
        f0, ew[3], eb[3], mask_prev,
        nullptr, nullptr, nullptr, nullptr, hF, 1024, 512, 0);

    // ---- top-k sparsify ----
    topk_mask_kernel<<<MTOK, 256>>>(hF, a0, a1, f1);

    // ---- decoder ----
    gemm_hyb<1><<<dim3(4, 512), blk, SM_DEC>>>(a0, a1, nullptr,
        w0 + L[4].off, w1 + L[4].off, nullptr,
        f1, dw[0], db[0], nullptr,
        b0, b1, nullptr, f0, nullptr, 512, 1024, 1);
    gemm_hyb<1><<<dim3(4, 512), blk, SM_DEC>>>(b0, b1, nullptr,
        w0 + L[5].off, w1 + L[5].off, nullptr,
        f0, dw[1], db[1], nullptr,
        a0, a1, nullptr, f1, nullptr, 512, 512, 1);
    gemm_hyb<1><<<dim3(4, 512), blk, SM_DEC>>>(a0, a1, nullptr,
        w0 + L[6].off, w1 + L[6].off, nullptr,
        f1, dw[2], db[2], nullptr,
        b0, b1, nullptr, f0, nullptr, 512, 512, 1);
    gemm_hyb<1><<<dim3(4, 512), blk, SM_DEC>>>(b0, b1, nullptr,
        w0 + L[7].off, w1 + L[7].off, nullptr,
        f0, dw[3], db[3], nullptr,
        nullptr, nullptr, nullptr, nullptr, (float*)d_out, 512, 512, 0);
}

// round 12
// speedup vs baseline: 1.6567x; 1.6567x over previous
#include <cuda_runtime.h>
#include <cuda_fp16.h>
#include <cstdint>

#define MTOK   65536
#define HDIM   1024
#define KSEL   256

// ---------------------------------------------------------------------------
// Static scratch. Activations: splits of (value * 512), parts fp16.
// Weights: transposed [N,K] splits of (value * 512), parts fp16.
// ---------------------------------------------------------------------------
__device__ __half g_a0[(size_t)MTOK * HDIM];
__device__ __half g_a1[(size_t)MTOK * HDIM];
__device__ __half g_a2[(size_t)MTOK * HDIM];
__device__ __half g_b0[(size_t)MTOK * HDIM];
__device__ __half g_b1[(size_t)MTOK * HDIM];
__device__ __half g_b2[(size_t)MTOK * HDIM];
__device__ float  g_hF[(size_t)MTOK * HDIM];
#define WT_TOTAL 2621440
__device__ __half g_w0[WT_TOTAL];
__device__ __half g_w1[WT_TOTAL];
__device__ __half g_w2[WT_TOTAL];

// ---------------------------------------------------------------------------
// Helpers
// ---------------------------------------------------------------------------
__device__ __forceinline__ uint32_t smem_u32(const void* p) {
    uint32_t a;
    asm("{ .reg .u64 t; cvta.to.shared.u64 t, %1; cvt.u32.u64 %0, t; }" : "=r"(a) : "l"(p));
    return a;
}
__device__ __forceinline__ void ldsm4(uint32_t* r, uint32_t addr) {
    asm volatile("ldmatrix.sync.aligned.m8n8.x4.shared.b16 {%0,%1,%2,%3}, [%4];"
                 : "=r"(r[0]), "=r"(r[1]), "=r"(r[2]), "=r"(r[3]) : "r"(addr));
}
__device__ __forceinline__ void cp16(uint32_t dst, const void* src) {
    asm volatile("cp.async.cg.shared.global [%0], [%1], 16;" :: "r"(dst), "l"(src) : "memory");
}
__device__ __forceinline__ void mma16816(float* c, const uint32_t* a, uint32_t b0, uint32_t b1) {
    asm volatile(
        "mma.sync.aligned.m16n8k16.row.col.f32.f16.f16.f32 "
        "{%0,%1,%2,%3}, {%4,%5,%6,%7}, {%8,%9}, {%0,%1,%2,%3};"
        : "+f"(c[0]), "+f"(c[1]), "+f"(c[2]), "+f"(c[3])
        : "r"(a[0]), "r"(a[1]), "r"(a[2]), "r"(a[3]), "r"(b0), "r"(b1));
}
// D = A*B + 0  (fresh accumulator: no inherited C-chain truncation bias)
__device__ __forceinline__ void mma16816_z(float* d, const uint32_t* a, uint32_t b0, uint32_t b1) {
    asm volatile(
        "mma.sync.aligned.m16n8k16.row.col.f32.f16.f16.f32 "
        "{%0,%1,%2,%3}, {%4,%5,%6,%7}, {%8,%9}, {%10,%11,%12,%13};"
        : "=f"(d[0]), "=f"(d[1]), "=f"(d[2]), "=f"(d[3])
        : "r"(a[0]), "r"(a[1]), "r"(a[2]), "r"(a[3]), "r"(b0), "r"(b1),
          "f"(0.0f), "f"(0.0f), "f"(0.0f), "f"(0.0f));
}
__device__ __forceinline__ uint32_t pack_h2(__half a, __half b) {
    __half2 h2 = __halves2half2(a, b);
    return *reinterpret_cast<uint32_t*>(&h2);
}
// 64B-row smem swizzle: 16B-chunk ch of row -> ch ^ ((row>>1)&3).
// Conflict-free for ldmatrix 8-row groups AND invariant under +16-row shifts.
__device__ __forceinline__ uint32_t sw64(uint32_t row, uint32_t ch) {
    return row * 64u + ((ch ^ ((row >> 1) & 3u)) << 4);
}

// ---------------------------------------------------------------------------
// HMMA split-fp16 GEMM.  true C = act( 2^-18 * sum_t A_pa @ B_pb^T + bias )
// MODE 0 (encoder): 3 parts, 6 terms; per-k16 fresh-accumulator extraction +
//                   RN FADD folding. MODE 1 (decoder): 2 parts, 3 terms, chained.
// CTA tile 128x64, 256 threads (8 warps, warp tile 32x32), k-chunk 32,
// 2-stage cp.async, swizzled 64B-row smem -> 2 CTAs/SM (regs AND smem).
// Per-element mma chains identical to Rounds 7-10 (numerics frozen).
// ---------------------------------------------------------------------------
template<int MODE>
__global__ __launch_bounds__(256, 2)
void gemm_hmma(const __half* __restrict__ A0, const __half* __restrict__ A1,
               const __half* __restrict__ A2,
               const __half* __restrict__ W0, const __half* __restrict__ W1,
               const __half* __restrict__ W2,
               const float* __restrict__ bias, const float* __restrict__ mask,
               __half* __restrict__ O0, __half* __restrict__ O1,
               __half* __restrict__ O2, float* __restrict__ OF,
               int N, int K, int relu)
{
    constexpr int NPA = (MODE == 0) ? 3 : 2;
    constexpr int NT  = (MODE == 0) ? 6 : 3;
    constexpr uint32_t PARTA = 8192;     // 128 rows * 64B
    constexpr uint32_t PARTB = 4096;     // 64 rows * 64B
    constexpr uint32_t BOFF  = NPA * PARTA;
    constexpr uint32_t STAGE = NPA * (PARTA + PARTB);
    constexpr int TOT = NPA * 512 + NPA * 256;    // cp16 ops per stage
    constexpr int PA_[2][6] = {{0, 1, 0, 2, 1, 0}, {0, 1, 0, 0, 0, 0}};
    constexpr int PB_[2][6] = {{0, 0, 1, 0, 1, 2}, {0, 0, 1, 0, 0, 0}};

    extern __shared__ __align__(16) char smem_raw[];
    const uint32_t smb = smem_u32(smem_raw);

    const int tid    = threadIdx.x;
    const int wid    = tid >> 5;
    const int lane   = tid & 31;
    const int warp_m = wid & 3;      // 0..3 (SMSP-spread)
    const int warp_n = wid >> 2;     // 0..1
    const int g      = lane >> 2;
    const int tg     = lane & 3;
    const int bm     = blockIdx.y * 128;
    const int bn     = blockIdx.x * 64;
    const int C      = K >> 5;

    const __half* Pp[6];
    Pp[0] = A0; Pp[1] = A1; Pp[2] = (MODE == 0) ? A2 : W0;
    if (MODE == 0) { Pp[3] = W0; Pp[4] = W1; Pp[5] = W2; }
    else           { Pp[3] = W1; }

    auto load_stage = [&](int c, int slot) {
        const uint32_t sbase = smb + (uint32_t)slot * STAGE;
        #pragma unroll
        for (int s = 0; s < TOT / 256; s++) {
            int i = s * 256 + tid;
            const __half* src;
            uint32_t dst;
            if (i < NPA * 512) {                      // A parts: 128 rows x 4 ch
                int p = i >> 9, j = i & 511;
                uint32_t row = (uint32_t)(j >> 2), ch = (uint32_t)(j & 3);
                src = Pp[p] + (size_t)(bm + row) * K + c * 32 + ch * 8;
                dst = sbase + (uint32_t)p * PARTA + sw64(row, ch);
            } else {                                  // W parts: 64 rows x 4 ch
                int q = i - NPA * 512;
                int p = q >> 8, j = q & 255;
                uint32_t row = (uint32_t)(j >> 2), ch = (uint32_t)(j & 3);
                src = Pp[NPA + p] + (size_t)(bn + row) * K + c * 32 + ch * 8;
                dst = sbase + BOFF + (uint32_t)p * PARTB + sw64(row, ch);
            }
            cp16(dst, src);
        }
        asm volatile("cp.async.commit_group;" ::: "memory");
    };

    load_stage(0, 0);
    if (C > 1) load_stage(1, 1);

    float acc[2][4][4];
    #pragma unroll
    for (int i = 0; i < 2; i++)
        #pragma unroll
        for (int j = 0; j < 4; j++)
            #pragma unroll
            for (int e = 0; e < 4; e++) acc[i][j][e] = 0.0f;

    // Per-lane ldmatrix offsets for kh=0/1 (swizzle folds into lane constants;
    // +16/+32-row shifts leave the swizzle bits unchanged).
    const uint32_t lrA = (uint32_t)((lane & 7) + ((lane >> 3) & 1) * 8);
    const uint32_t lcA = (uint32_t)((lane >> 4) & 1);
    const uint32_t lrB = (uint32_t)((lane & 7) + ((lane >> 4) & 1) * 8);
    const uint32_t lcB = (uint32_t)((lane >> 3) & 1);
    uint32_t laneA[2], laneB[2];
    #pragma unroll
    for (int kh = 0; kh < 2; kh++) {
        laneA[kh] = (uint32_t)(warp_m * 32) * 64u + sw64(lrA, lcA + 2u * kh);
        laneB[kh] = (uint32_t)(warp_n * 32) * 64u + sw64(lrB, lcB + 2u * kh);
    }

    for (int c = 0; c < C; c++) {
        if (c + 1 < C) asm volatile("cp.async.wait_group 1;" ::: "memory");
        else           asm volatile("cp.async.wait_group 0;" ::: "memory");
        __syncthreads();

        const uint32_t sb0 = smb + (uint32_t)(c & 1) * STAGE;

        if (MODE == 0) {
            // Encoder: per k16-half, all terms into a FRESH accumulator, then
            // fold into master with RN FADDs. Order: c -> kh -> t (frozen).
            #pragma unroll
            for (int kh = 0; kh < 2; kh++) {
                float tmp[2][4][4];
                #pragma unroll
                for (int t = 0; t < NT; t++) {
                    const uint32_t aBase = sb0 + (uint32_t)PA_[0][t] * PARTA + laneA[kh];
                    const uint32_t bBase = sb0 + BOFF + (uint32_t)PB_[0][t] * PARTB + laneB[kh];
                    uint32_t af[2][4], bf[2][4];
                    ldsm4(af[0], aBase);
                    ldsm4(af[1], aBase + 16u * 64u);
                    ldsm4(bf[0], bBase);
                    ldsm4(bf[1], bBase + 16u * 64u);
                    #pragma unroll
                    for (int nt = 0; nt < 4; nt++) {
                        uint32_t b0 = bf[nt >> 1][(nt & 1) * 2];
                        uint32_t b1 = bf[nt >> 1][(nt & 1) * 2 + 1];
                        #pragma unroll
                        for (int mt = 0; mt < 2; mt++) {
                            if (t == 0) mma16816_z(tmp[mt][nt], af[mt], b0, b1);
                            else        mma16816(tmp[mt][nt], af[mt], b0, b1);
                        }
                    }
                }
                #pragma unroll
                for (int mt = 0; mt < 2; mt++)
                    #pragma unroll
                    for (int nt = 0; nt < 4; nt++)
                        #pragma unroll
                        for (int e = 0; e < 4; e++)
                            acc[mt][nt][e] += tmp[mt][nt][e];
            }
        } else {
            // Decoder: direct HW chaining. Order: c -> t -> kh (frozen).
            #pragma unroll
            for (int t = 0; t < NT; t++) {
                #pragma unroll
                for (int kh = 0; kh < 2; kh++) {
                    const uint32_t aBase = sb0 + (uint32_t)PA_[1][t] * PARTA + laneA[kh];
                    const uint32_t bBase = sb0 + BOFF + (uint32_t)PB_[1][t] * PARTB + laneB[kh];
                    uint32_t af[2][4], bf[2][4];
                    ldsm4(af[0], aBase);
                    ldsm4(af[1], aBase + 16u * 64u);
                    ldsm4(bf[0], bBase);
                    ldsm4(bf[1], bBase + 16u * 64u);
                    #pragma unroll
                    for (int nt = 0; nt < 4; nt++) {
                        uint32_t b0 = bf[nt >> 1][(nt & 1) * 2];
                        uint32_t b1 = bf[nt >> 1][(nt & 1) * 2 + 1];
                        #pragma unroll
                        for (int mt = 0; mt < 2; mt++)
                            mma16816(acc[mt][nt], af[mt], b0, b1);
                    }
                }
            }
        }
        __syncthreads();
        if (c + 2 < C) load_stage(c + 2, c & 1);
    }

    // ---- epilogue (identical per-element math to Rounds 7-10) ----
    const float SCL = 1.0f / 262144.0f;       // 2^-18
    #pragma unroll
    for (int mt = 0; mt < 2; mt++) {
        #pragma unroll
        for (int nt = 0; nt < 4; nt++) {
            const int row = bm + warp_m * 32 + mt * 16 + g;
            const int col = bn + warp_n * 32 + nt * 8 + tg * 2;
            const float bz0 = __ldg(bias + col);
            const float bz1 = __ldg(bias + col + 1);
            float v0 = acc[mt][nt][0] * SCL + bz0;
            float v1 = acc[mt][nt][1] * SCL + bz1;
            float v2 = acc[mt][nt][2] * SCL + bz0;   // row + 8
            float v3 = acc[mt][nt][3] * SCL + bz1;
            if (relu) {
                v0 = fmaxf(v0, 0.f); v1 = fmaxf(v1, 0.f);
                v2 = fmaxf(v2, 0.f); v3 = fmaxf(v3, 0.f);
            }
            const size_t i0 = (size_t)row * N + col;
            const size_t i1 = (size_t)(row + 8) * N + col;
            if (OF) {
                if (mask) {
                    const float2 m0 = *(const float2*)(mask + i0);
                    const float2 m1 = *(const float2*)(mask + i1);
                    if (m0.x > 0.f) v0 = 0.f;
                    if (m0.y > 0.f) v1 = 0.f;
                    if (m1.x > 0.f) v2 = 0.f;
                    if (m1.y > 0.f) v3 = 0.f;
                }
                *(float2*)(OF + i0) = make_float2(v0, v1);
                *(float2*)(OF + i1) = make_float2(v2, v3);
            } else {
                float s0 = v0 * 512.f, s1 = v1 * 512.f;
                float s2 = v2 * 512.f, s3 = v3 * 512.f;
                __half h0 = __float2half_rn(s0), h1 = __float2half_rn(s1);
                __half h2 = __float2half_rn(s2), h3 = __float2half_rn(s3);
                float r0 = s0 - __half2float(h0), r1 = s1 - __half2float(h1);
                float r2 = s2 - __half2float(h2), r3 = s3 - __half2float(h3);
                __half q0 = __float2half_rn(r0), q1 = __float2half_rn(r1);
                __half q2 = __float2half_rn(r2), q3 = __float2half_rn(r3);
                *(uint32_t*)(O0 + i0) = pack_h2(h0, h1);
                *(uint32_t*)(O0 + i1) = pack_h2(h2, h3);
                *(uint32_t*)(O1 + i0) = pack_h2(q0, q1);
                *(uint32_t*)(O1 + i1) = pack_h2(q2, q3);
                if (MODE == 0) {
                    *(uint32_t*)(O2 + i0) = pack_h2(__float2half_rn(r0 - __half2float(q0)),
                                                    __float2half_rn(r1 - __half2float(q1)));
                    *(uint32_t*)(O2 + i1) = pack_h2(__float2half_rn(r2 - __half2float(q2)),
                                                    __float2half_rn(r3 - __half2float(q3)));
                }
            }
        }
    }
}

// ---------------------------------------------------------------------------
// x -> 3-way fp16 split (scaled by 512)
// ---------------------------------------------------------------------------
__global__ void conv_x_kernel(const float* __restrict__ x,
                              __half* __restrict__ o0, __half* __restrict__ o1,
                              __half* __restrict__ o2)
{
    size_t i = ((size_t)blockIdx.x * blockDim.x + threadIdx.x) * 2;
    float x0 = x[i] * 512.f, x1 = x[i + 1] * 512.f;
    __half h0 = __float2half_rn(x0), h1 = __float2half_rn(x1);
    float r0 = x0 - __half2float(h0), r1 = x1 - __half2float(h1);
    __half q0 = __float2half_rn(r0), q1 = __float2half_rn(r1);
    __half u0 = __float2half_rn(r0 - __half2float(q0));
    __half u1 = __float2half_rn(r1 - __half2float(q1));
    *(uint32_t*)(o0 + i) = pack_h2(h0, h1);
    *(uint32_t*)(o1 + i) = pack_h2(q0, q1);
    *(uint32_t*)(o2 + i) = pack_h2(u0, u1);
}

// ---------------------------------------------------------------------------
// Fused weight conversion (one launch): W[K,N] -> transposed split parts.
// ---------------------------------------------------------------------------
struct WArgs {
    const float* src[8];
    unsigned off[8];
    int ksh[8];
    int N[8];
    int np[8];
};
__global__ void conv_w_all(WArgs A, __half* __restrict__ o0,
                           __half* __restrict__ o1, __half* __restrict__ o2)
{
    const int l = blockIdx.y;
    const int tot = A.N[l] << A.ksh[l];
    const int idx = blockIdx.x * blockDim.x + threadIdx.x;
    if (idx >= tot) return;
    const int n = idx >> A.ksh[l];
    const int k = idx & ((1 << A.ksh[l]) - 1);
    float w = A.src[l][(size_t)k * A.N[l] + n] * 512.f;
    __half h = __float2half_rn(w);
    float r = w - __half2float(h);
    __half q = __float2half_rn(r);
    const unsigned o = A.off[l] + idx;
    o0[o] = h;
    o1[o] = q;
    if (A.np[l] == 3) o2[o] = __float2half_rn(r - __half2float(q));
}

// ---------------------------------------------------------------------------
// Exact per-token top-256-of-1024 by h^2 (radix select on float bit pattern).
// Output = 2-way fp16 split (scaled by 512) of (kept ? h : 0).
// ---------------------------------------------------------------------------
__global__ __launch_bounds__(256)
void topk_mask_kernel(const float* __restrict__ H,
                      __half* __restrict__ o0, __half* __restrict__ o1)
{
    const int tid = threadIdx.x;
    const size_t row = (size_t)blockIdx.x * HDIM;

    __shared__ unsigned ebits[HDIM];
    __shared__ unsigned hist[256];
    __shared__ unsigned sc[256];
    __shared__ unsigned s_pref, s_r;

    float4 hv = ((const float4*)(H + row))[tid];
    unsigned v0 = __float_as_uint(hv.x * hv.x);
    unsigned v1 = __float_as_uint(hv.y * hv.y);
    unsigned v2 = __float_as_uint(hv.z * hv.z);
    unsigned v3 = __float_as_uint(hv.w * hv.w);
    ebits[4 * tid + 0] = v0; ebits[4 * tid + 1] = v1;
    ebits[4 * tid + 2] = v2; ebits[4 * tid + 3] = v3;
    if (tid == 0) { s_pref = 0u; s_r = KSEL; }
    __syncthreads();

    #pragma unroll
    for (int pass = 0; pass < 4; pass++) {
        const int shift = 24 - 8 * pass;
        const unsigned pref = s_pref;
        const unsigned r    = s_r;
        hist[tid] = 0u;
        __syncthreads();
        #pragma unroll
        for (int j = 0; j < 4; j++) {
            unsigned v = ebits[4 * tid + j];
            bool cand = (pass == 0) || ((v >> (shift + 8)) == (pref >> (shift + 8)));
            if (cand) atomicAdd(&hist[(v >> shift) & 0xFFu], 1u);
        }
        __syncthreads();
        sc[tid] = hist[tid];
        __syncthreads();
        for (int off = 1; off < 256; off <<= 1) {
            unsigned add = (tid + off < 256) ? sc[tid + off] : 0u;
            __syncthreads();
            sc[tid] += add;
            __syncthreads();
        }
        unsigned above = (tid == 255) ? 0u : sc[tid + 1];
        if (sc[tid] >= r && above < r) {
            s_pref = pref | ((unsigned)tid << shift);
            s_r    = r - above;
        }
        __syncthreads();
    }

    const unsigned thr  = s_pref;
    const unsigned need = s_r;

    unsigned vv[4] = {v0, v1, v2, v3};
    unsigned pos[4];
    unsigned myc = 0;
    #pragma unroll
    for (int j = 0; j < 4; j++) { pos[j] = myc; myc += (vv[j] == thr) ? 1u : 0u; }
    sc[tid] = myc;
    __syncthreads();
    for (int off = 1; off < 256; off <<= 1) {
        unsigned add = (tid >= off) ? sc[tid - off] : 0u;
        __syncthreads();
        sc[tid] += add;
        __syncthreads();
    }
    const unsigned base = sc[tid] - myc;

    float h[4] = {hv.x, hv.y, hv.z, hv.w};
    uint32_t w0[2], w1[2];
    #pragma unroll
    for (int e = 0; e < 2; e++) {
        __half hh[2], ll[2];
        #pragma unroll
        for (int q = 0; q < 2; q++) {
            int j = 2 * e + q;
            bool keep = (vv[j] > thr) || (vv[j] == thr && (base + pos[j]) < need);
            float o = (keep ? h[j] : 0.0f) * 512.f;
            hh[q] = __float2half_rn(o);
            ll[q] = __float2half_rn(o - __half2float(hh[q]));
        }
        w0[e] = pack_h2(hh[0], hh[1]);
        w1[e] = pack_h2(ll[0], ll[1]);
    }
    ((uint2*)(o0 + row))[tid] = make_uint2(w0[0], w0[1]);
    ((uint2*)(o1 + row))[tid] = make_uint2(w1[0], w1[1]);
}

// ---------------------------------------------------------------------------
// kernel_launch
// ---------------------------------------------------------------------------
extern "C" void kernel_launch(void* const* d_in, const int* in_sizes, int n_in,
                              void* d_out, int out_size)
{
    const float* x         = (const float*)d_in[0];
    const float* mask_prev = (const float*)d_in[1];
    const bool inter = (in_sizes[4] == HDIM * 512);

    const float *ew[4], *eb[4], *dw[4], *db[4];
    for (int i = 0; i < 4; i++) {
        if (inter) {
            ew[i] = (const float*)d_in[2 + 4 * i]; eb[i] = (const float*)d_in[3 + 4 * i];
            dw[i] = (const float*)d_in[4 + 4 * i]; db[i] = (const float*)d_in[5 + 4 * i];
        } else {
            ew[i] = (const float*)d_in[2 + 2 * i]; eb[i] = (const float*)d_in[3 + 2 * i];
            dw[i] = (const float*)d_in[10 + 2 * i]; db[i] = (const float*)d_in[11 + 2 * i];
        }
    }

    __half *a0, *a1, *a2, *b0, *b1, *b2, *w0, *w1, *w2;
    float* hF;
    cudaGetSymbolAddress((void**)&a0, g_a0); cudaGetSymbolAddress((void**)&a1, g_a1);
    cudaGetSymbolAddress((void**)&a2, g_a2); cudaGetSymbolAddress((void**)&b0, g_b0);
    cudaGetSymbolAddress((void**)&b1, g_b1); cudaGetSymbolAddress((void**)&b2, g_b2);
    cudaGetSymbolAddress((void**)&w0, g_w0); cudaGetSymbolAddress((void**)&w1, g_w1);
    cudaGetSymbolAddress((void**)&w2, g_w2); cudaGetSymbolAddress((void**)&hF, g_hF);

    const int SM_ENC = 2 * 3 * (8192 + 4096);   // 73728
    const int SM_DEC = 2 * 2 * (8192 + 4096);   // 49152
    cudaFuncSetAttribute(gemm_hmma<0>, cudaFuncAttributeMaxDynamicSharedMemorySize, SM_ENC);
    cudaFuncSetAttribute(gemm_hmma<1>, cudaFuncAttributeMaxDynamicSharedMemorySize, SM_DEC);

    // ---- weight conversion (one fused launch) ----
    struct { const float* w; int K, N; unsigned off; int np; } L[8] = {
        {ew[0], 512, 512, 0, 3},        {ew[1], 512, 512, 262144, 3},
        {ew[2], 512, 512, 524288, 3},   {ew[3], 512, 1024, 786432, 3},
        {dw[0], 1024, 512, 1310720, 2}, {dw[1], 512, 512, 1835008, 2},
        {dw[2], 512, 512, 2097152, 2},  {dw[3], 512, 512, 2359296, 2}};
    WArgs wa;
    for (int l = 0; l < 8; l++) {
        wa.src[l] = L[l].w;
        wa.off[l] = L[l].off;
        wa.ksh[l] = (L[l].K == 1024) ? 10 : 9;
        wa.N[l]   = L[l].N;
        wa.np[l]  = L[l].np;
    }
    conv_w_all<<<dim3(2048, 8), 256>>>(wa, w0, w1, w2);

    // ---- x split ----
    conv_x_kernel<<<(MTOK * 512 / 2) / 256, 256>>>(x, a0, a1, a2);

    const dim3 blk(256);
    // ---- encoder (3-way split, 6 terms, debiased accumulation) ----
    gemm_hmma<0><<<dim3(8, 512), blk, SM_ENC>>>(a0, a1, a2,
        w0 + L[0].off, w1 + L[0].off, w2 + L[0].off, eb[0], nullptr,
        b0, b1, b2, nullptr, 512, 512, 1);
    gemm_hmma<0><<<dim3(8, 512), blk, SM_ENC>>>(b0, b1, b2,
        w0 + L[1].off, w1 + L[1].off, w2 + L[1].off, eb[1], nullptr,
        a0, a1, a2, nullptr, 512, 512, 1);
    gemm_hmma<0><<<dim3(8, 512), blk, SM_ENC>>>(a0, a1, a2,
        w0 + L[2].off, w1 + L[2].off, w2 + L[2].off, eb[2], nullptr,
        b0, b1, b2, nullptr, 512, 512, 1);
    gemm_hmma<0><<<dim3(16, 512), blk, SM_ENC>>>(b0, b1, b2,
        w0 + L[3].off, w1 + L[3].off, w2 + L[3].off, eb[3], mask_prev,
        nullptr, nullptr, nullptr, hF, 1024, 512, 0);

    // ---- top-k sparsify -> split decoder input ----
    topk_mask_kernel<<<MTOK, 256>>>(hF, a0, a1);

    // ---- decoder (2-way split, 3 terms) ----
    gemm_hmma<1><<<dim3(8, 512), blk, SM_DEC>>>(a0, a1, nullptr,
        w0 + L[4].off, w1 + L[4].off, nullptr, db[0], nullptr,
        b0, b1, nullptr, nullptr, 512, 1024, 1);
    gemm_hmma<1><<<dim3(8, 512), blk, SM_DEC>>>(b0, b1, nullptr,
        w0 + L[5].off, w1 + L[5].off, nullptr, db[1], nullptr,
        a0, a1, nullptr, nullptr, 512, 512, 1);
    gemm_hmma<1><<<dim3(8, 512), blk, SM_DEC>>>(a0, a1, nullptr,
        w0 + L[6].off, w1 + L[6].off, nullptr, db[2], nullptr,
        b0, b1, nullptr, nullptr, 512, 512, 1);
    gemm_hmma<1><<<dim3(8, 512), blk, SM_DEC>>>(b0, b1, nullptr,
        w0 + L[7].off, w1 + L[7].off, nullptr, db[3], nullptr,
        nullptr, nullptr, nullptr, (float*)d_out, 512, 512, 0);
}

// round 13
// speedup vs baseline: 1.6924x; 1.0216x over previous
#include <cuda_runtime.h>
#include <cuda_fp16.h>
#include <cstdint>

#define MTOK   65536
#define HDIM   1024
#define KSEL   256

// ---------------------------------------------------------------------------
// Static scratch. Activations: splits of (value * 512), parts fp16.
// Weights: transposed [N,K] splits of (value * 512), parts fp16.
// ---------------------------------------------------------------------------
__device__ __half g_a0[(size_t)MTOK * HDIM];
__device__ __half g_a1[(size_t)MTOK * HDIM];
__device__ __half g_a2[(size_t)MTOK * HDIM];
__device__ __half g_b0[(size_t)MTOK * HDIM];
__device__ __half g_b1[(size_t)MTOK * HDIM];
__device__ __half g_b2[(size_t)MTOK * HDIM];
__device__ float  g_hF[(size_t)MTOK * HDIM];
#define WT_TOTAL 2621440
__device__ __half g_w0[WT_TOTAL];
__device__ __half g_w1[WT_TOTAL];
__device__ __half g_w2[WT_TOTAL];

// ---------------------------------------------------------------------------
// Helpers
// ---------------------------------------------------------------------------
__device__ __forceinline__ uint32_t smem_u32(const void* p) {
    uint32_t a;
    asm("{ .reg .u64 t; cvta.to.shared.u64 t, %1; cvt.u32.u64 %0, t; }" : "=r"(a) : "l"(p));
    return a;
}
__device__ __forceinline__ void ldsm4(uint32_t* r, uint32_t addr) {
    asm volatile("ldmatrix.sync.aligned.m8n8.x4.shared.b16 {%0,%1,%2,%3}, [%4];"
                 : "=r"(r[0]), "=r"(r[1]), "=r"(r[2]), "=r"(r[3]) : "r"(addr));
}
__device__ __forceinline__ void cp16(uint32_t dst, const void* src) {
    asm volatile("cp.async.cg.shared.global [%0], [%1], 16;" :: "r"(dst), "l"(src) : "memory");
}
__device__ __forceinline__ void mma16816(float* c, const uint32_t* a, uint32_t b0, uint32_t b1) {
    asm volatile(
        "mma.sync.aligned.m16n8k16.row.col.f32.f16.f16.f32 "
        "{%0,%1,%2,%3}, {%4,%5,%6,%7}, {%8,%9}, {%0,%1,%2,%3};"
        : "+f"(c[0]), "+f"(c[1]), "+f"(c[2]), "+f"(c[3])
        : "r"(a[0]), "r"(a[1]), "r"(a[2]), "r"(a[3]), "r"(b0), "r"(b1));
}
// D = A*B + 0  (fresh accumulator: no inherited C-chain truncation bias)
__device__ __forceinline__ void mma16816_z(float* d, const uint32_t* a, uint32_t b0, uint32_t b1) {
    asm volatile(
        "mma.sync.aligned.m16n8k16.row.col.f32.f16.f16.f32 "
        "{%0,%1,%2,%3}, {%4,%5,%6,%7}, {%8,%9}, {%10,%11,%12,%13};"
        : "=f"(d[0]), "=f"(d[1]), "=f"(d[2]), "=f"(d[3])
        : "r"(a[0]), "r"(a[1]), "r"(a[2]), "r"(a[3]), "r"(b0), "r"(b1),
          "f"(0.0f), "f"(0.0f), "f"(0.0f), "f"(0.0f));
}
__device__ __forceinline__ uint32_t pack_h2(__half a, __half b) {
    __half2 h2 = __halves2half2(a, b);
    return *reinterpret_cast<uint32_t*>(&h2);
}
// 64B-row smem swizzle: 16B-chunk ch of row -> ch ^ ((row>>1)&3).
// Conflict-free for ldmatrix 8-row groups AND invariant under +16-row shifts.
__device__ __forceinline__ uint32_t sw64(uint32_t row, uint32_t ch) {
    return row * 64u + ((ch ^ ((row >> 1) & 3u)) << 4);
}

// ---------------------------------------------------------------------------
// HMMA split-fp16 GEMM.  true C = act( 2^-18 * sum_t A_pa @ B_pb^T + bias )
// MODE 0 (encoder): 3 parts, 6 terms; per-k16 fresh-accumulator extraction +
//                   RN FADD folding. MODE 1 (decoder): 2 parts, 3 terms, chained.
// CTA tile 128x64, 256 threads (8 warps, warp tile 32x32), k-chunk 32,
// THREE-stage cp.async pipeline with ONE __syncthreads per chunk:
//   the buffer refilled at chunk c ((c+2)%3) was consumed at chunk c-1, so the
//   single barrier at the top of chunk c already proves it is free; the refill
//   issues BEFORE the mma burst and overlaps it.
// 2 CTAs/SM (regs and smem). Per-element mma chains identical to R7-12.
// ---------------------------------------------------------------------------
template<int MODE>
__global__ __launch_bounds__(256, 2)
void gemm_hmma(const __half* __restrict__ A0, const __half* __restrict__ A1,
               const __half* __restrict__ A2,
               const __half* __restrict__ W0, const __half* __restrict__ W1,
               const __half* __restrict__ W2,
               const float* __restrict__ bias, const float* __restrict__ mask,
               __half* __restrict__ O0, __half* __restrict__ O1,
               __half* __restrict__ O2, float* __restrict__ OF,
               int N, int K, int relu)
{
    constexpr int NPA = (MODE == 0) ? 3 : 2;
    constexpr int NT  = (MODE == 0) ? 6 : 3;
    constexpr uint32_t PARTA = 8192;     // 128 rows * 64B
    constexpr uint32_t PARTB = 4096;     // 64 rows * 64B
    constexpr uint32_t BOFF  = NPA * PARTA;
    constexpr uint32_t STAGE = NPA * (PARTA + PARTB);
    constexpr int TOT = NPA * 512 + NPA * 256;    // cp16 ops per stage
    constexpr int PA_[2][6] = {{0, 1, 0, 2, 1, 0}, {0, 1, 0, 0, 0, 0}};
    constexpr int PB_[2][6] = {{0, 0, 1, 0, 1, 2}, {0, 0, 1, 0, 0, 0}};

    extern __shared__ __align__(16) char smem_raw[];
    const uint32_t smb = smem_u32(smem_raw);

    const int tid    = threadIdx.x;
    const int wid    = tid >> 5;
    const int lane   = tid & 31;
    const int warp_m = wid & 3;      // 0..3 (SMSP-spread)
    const int warp_n = wid >> 2;     // 0..1
    const int g      = lane >> 2;
    const int tg     = lane & 3;
    const int bm     = blockIdx.y * 128;
    const int bn     = blockIdx.x * 64;
    const int C      = K >> 5;

    const __half* Pp[6];
    Pp[0] = A0; Pp[1] = A1; Pp[2] = (MODE == 0) ? A2 : W0;
    if (MODE == 0) { Pp[3] = W0; Pp[4] = W1; Pp[5] = W2; }
    else           { Pp[3] = W1; }

    auto load_stage = [&](int c, int slot) {
        const uint32_t sbase = smb + (uint32_t)slot * STAGE;
        #pragma unroll
        for (int s = 0; s < TOT / 256; s++) {
            int i = s * 256 + tid;
            const __half* src;
            uint32_t dst;
            if (i < NPA * 512) {                      // A parts: 128 rows x 4 ch
                int p = i >> 9, j = i & 511;
                uint32_t row = (uint32_t)(j >> 2), ch = (uint32_t)(j & 3);
                src = Pp[p] + (size_t)(bm + row) * K + c * 32 + ch * 8;
                dst = sbase + (uint32_t)p * PARTA + sw64(row, ch);
            } else {                                  // W parts: 64 rows x 4 ch
                int q = i - NPA * 512;
                int p = q >> 8, j = q & 255;
                uint32_t row = (uint32_t)(j >> 2), ch = (uint32_t)(j & 3);
                src = Pp[NPA + p] + (size_t)(bn + row) * K + c * 32 + ch * 8;
                dst = sbase + BOFF + (uint32_t)p * PARTB + sw64(row, ch);
            }
            cp16(dst, src);
        }
        asm volatile("cp.async.commit_group;" ::: "memory");
    };

    load_stage(0, 0);
    if (C > 1) load_stage(1, 1);

    float acc[2][4][4];
    #pragma unroll
    for (int i = 0; i < 2; i++)
        #pragma unroll
        for (int j = 0; j < 4; j++)
            #pragma unroll
            for (int e = 0; e < 4; e++) acc[i][j][e] = 0.0f;

    // Per-lane ldmatrix offsets for kh=0/1 (swizzle folds into lane constants;
    // +16/+32-row shifts leave the swizzle bits unchanged).
    const uint32_t lrA = (uint32_t)((lane & 7) + ((lane >> 3) & 1) * 8);
    const uint32_t lcA = (uint32_t)((lane >> 4) & 1);
    const uint32_t lrB = (uint32_t)((lane & 7) + ((lane >> 4) & 1) * 8);
    const uint32_t lcB = (uint32_t)((lane >> 3) & 1);
    uint32_t laneA[2], laneB[2];
    #pragma unroll
    for (int kh = 0; kh < 2; kh++) {
        laneA[kh] = (uint32_t)(warp_m * 32) * 64u + sw64(lrA, lcA + 2u * kh);
        laneB[kh] = (uint32_t)(warp_n * 32) * 64u + sw64(lrB, lcB + 2u * kh);
    }

    for (int c = 0; c < C; c++) {
        // Stage c is the oldest of <=2 pending groups at this point.
        if (c + 1 < C) asm volatile("cp.async.wait_group 1;" ::: "memory");
        else           asm volatile("cp.async.wait_group 0;" ::: "memory");
        __syncthreads();   // all warps finished chunk c-1; buffer (c+2)%3 free

        // Refill next-next stage BEFORE the mma burst (overlaps compute).
        if (c + 2 < C) load_stage(c + 2, (c + 2) % 3);

        const uint32_t sb0 = smb + (uint32_t)(c % 3) * STAGE;

        if (MODE == 0) {
            // Encoder: per k16-half, all terms into a FRESH accumulator, then
            // fold into master with RN FADDs. Order: c -> kh -> t (frozen).
            #pragma unroll
            for (int kh = 0; kh < 2; kh++) {
                float tmp[2][4][4];
                #pragma unroll
                for (int t = 0; t < NT; t++) {
                    const uint32_t aBase = sb0 + (uint32_t)PA_[0][t] * PARTA + laneA[kh];
                    const uint32_t bBase = sb0 + BOFF + (uint32_t)PB_[0][t] * PARTB + laneB[kh];
                    uint32_t af[2][4], bf[2][4];
                    ldsm4(af[0], aBase);
                    ldsm4(af[1], aBase + 16u * 64u);
                    ldsm4(bf[0], bBase);
                    ldsm4(bf[1], bBase + 16u * 64u);
                    #pragma unroll
                    for (int nt = 0; nt < 4; nt++) {
                        uint32_t b0 = bf[nt >> 1][(nt & 1) * 2];
                        uint32_t b1 = bf[nt >> 1][(nt & 1) * 2 + 1];
                        #pragma unroll
                        for (int mt = 0; mt < 2; mt++) {
                            if (t == 0) mma16816_z(tmp[mt][nt], af[mt], b0, b1);
                            else        mma16816(tmp[mt][nt], af[mt], b0, b1);
                        }
                    }
                }
                #pragma unroll
                for (int mt = 0; mt < 2; mt++)
                    #pragma unroll
                    for (int nt = 0; nt < 4; nt++)
                        #pragma unroll
                        for (int e = 0; e < 4; e++)
                            acc[mt][nt][e] += tmp[mt][nt][e];
            }
        } else {
            // Decoder: direct HW chaining. Order: c -> t -> kh (frozen).
            #pragma unroll
            for (int t = 0; t < NT; t++) {
                #pragma unroll
                for (int kh = 0; kh < 2; kh++) {
                    const uint32_t aBase = sb0 + (uint32_t)PA_[1][t] * PARTA + laneA[kh];
                    const uint32_t bBase = sb0 + BOFF + (uint32_t)PB_[1][t] * PARTB + laneB[kh];
                    uint32_t af[2][4], bf[2][4];
                    ldsm4(af[0], aBase);
                    ldsm4(af[1], aBase + 16u * 64u);
                    ldsm4(bf[0], bBase);
                    ldsm4(bf[1], bBase + 16u * 64u);
                    #pragma unroll
                    for (int nt = 0; nt < 4; nt++) {
                        uint32_t b0 = bf[nt >> 1][(nt & 1) * 2];
                        uint32_t b1 = bf[nt >> 1][(nt & 1) * 2 + 1];
                        #pragma unroll
                        for (int mt = 0; mt < 2; mt++)
                            mma16816(acc[mt][nt], af[mt], b0, b1);
                    }
                }
            }
        }
    }

    // ---- epilogue (identical per-element math to Rounds 7-12) ----
    const float SCL = 1.0f / 262144.0f;       // 2^-18
    #pragma unroll
    for (int mt = 0; mt < 2; mt++) {
        #pragma unroll
        for (int nt = 0; nt < 4; nt++) {
            const int row = bm + warp_m * 32 + mt * 16 + g;
            const int col = bn + warp_n * 32 + nt * 8 + tg * 2;
            const float bz0 = __ldg(bias + col);
            const float bz1 = __ldg(bias + col + 1);
            float v0 = acc[mt][nt][0] * SCL + bz0;
            float v1 = acc[mt][nt][1] * SCL + bz1;
            float v2 = acc[mt][nt][2] * SCL + bz0;   // row + 8
            float v3 = acc[mt][nt][3] * SCL + bz1;
            if (relu) {
                v0 = fmaxf(v0, 0.f); v1 = fmaxf(v1, 0.f);
                v2 = fmaxf(v2, 0.f); v3 = fmaxf(v3, 0.f);
            }
            const size_t i0 = (size_t)row * N + col;
            const size_t i1 = (size_t)(row + 8) * N + col;
            if (OF) {
                if (mask) {
                    const float2 m0 = *(const float2*)(mask + i0);
                    const float2 m1 = *(const float2*)(mask + i1);
                    if (m0.x > 0.f) v0 = 0.f;
                    if (m0.y > 0.f) v1 = 0.f;
                    if (m1.x > 0.f) v2 = 0.f;
                    if (m1.y > 0.f) v3 = 0.f;
                }
                *(float2*)(OF + i0) = make_float2(v0, v1);
                *(float2*)(OF + i1) = make_float2(v2, v3);
            } else {
                float s0 = v0 * 512.f, s1 = v1 * 512.f;
                float s2 = v2 * 512.f, s3 = v3 * 512.f;
                __half h0 = __float2half_rn(s0), h1 = __float2half_rn(s1);
                __half h2 = __float2half_rn(s2), h3 = __float2half_rn(s3);
                float r0 = s0 - __half2float(h0), r1 = s1 - __half2float(h1);
                float r2 = s2 - __half2float(h2), r3 = s3 - __half2float(h3);
                __half q0 = __float2half_rn(r0), q1 = __float2half_rn(r1);
                __half q2 = __float2half_rn(r2), q3 = __float2half_rn(r3);
                *(uint32_t*)(O0 + i0) = pack_h2(h0, h1);
                *(uint32_t*)(O0 + i1) = pack_h2(h2, h3);
                *(uint32_t*)(O1 + i0) = pack_h2(q0, q1);
                *(uint32_t*)(O1 + i1) = pack_h2(q2, q3);
                if (MODE == 0) {
                    *(uint32_t*)(O2 + i0) = pack_h2(__float2half_rn(r0 - __half2float(q0)),
                                                    __float2half_rn(r1 - __half2float(q1)));
                    *(uint32_t*)(O2 + i1) = pack_h2(__float2half_rn(r2 - __half2float(q2)),
                                                    __float2half_rn(r3 - __half2float(q3)));
                }
            }
        }
    }
}

// ---------------------------------------------------------------------------
// x -> 3-way fp16 split (scaled by 512)
// ---------------------------------------------------------------------------
__global__ void conv_x_kernel(const float* __restrict__ x,
                              __half* __restrict__ o0, __half* __restrict__ o1,
                              __half* __restrict__ o2)
{
    size_t i = ((size_t)blockIdx.x * blockDim.x + threadIdx.x) * 2;
    float x0 = x[i] * 512.f, x1 = x[i + 1] * 512.f;
    __half h0 = __float2half_rn(x0), h1 = __float2half_rn(x1);
    float r0 = x0 - __half2float(h0), r1 = x1 - __half2float(h1);
    __half q0 = __float2half_rn(r0), q1 = __float2half_rn(r1);
    __half u0 = __float2half_rn(r0 - __half2float(q0));
    __half u1 = __float2half_rn(r1 - __half2float(q1));
    *(uint32_t*)(o0 + i) = pack_h2(h0, h1);
    *(uint32_t*)(o1 + i) = pack_h2(q0, q1);
    *(uint32_t*)(o2 + i) = pack_h2(u0, u1);
}

// ---------------------------------------------------------------------------
// Fused weight conversion (one launch): W[K,N] -> transposed split parts.
// ---------------------------------------------------------------------------
struct WArgs {
    const float* src[8];
    unsigned off[8];
    int ksh[8];
    int N[8];
    int np[8];
};
__global__ void conv_w_all(WArgs A, __half* __restrict__ o0,
                           __half* __restrict__ o1, __half* __restrict__ o2)
{
    const int l = blockIdx.y;
    const int tot = A.N[l] << A.ksh[l];
    const int idx = blockIdx.x * blockDim.x + threadIdx.x;
    if (idx >= tot) return;
    const int n = idx >> A.ksh[l];
    const int k = idx & ((1 << A.ksh[l]) - 1);
    float w = A.src[l][(size_t)k * A.N[l] + n] * 512.f;
    __half h = __float2half_rn(w);
    float r = w - __half2float(h);
    __half q = __float2half_rn(r);
    const unsigned o = A.off[l] + idx;
    o0[o] = h;
    o1[o] = q;
    if (A.np[l] == 3) o2[o] = __float2half_rn(r - __half2float(q));
}

// ---------------------------------------------------------------------------
// Exact per-token top-256-of-1024 by h^2 (radix select on float bit pattern).
// Output = 2-way fp16 split (scaled by 512) of (kept ? h : 0).
// ---------------------------------------------------------------------------
__global__ __launch_bounds__(256)
void topk_mask_kernel(const float* __restrict__ H,
                      __half* __restrict__ o0, __half* __restrict__ o1)
{
    const int tid = threadIdx.x;
    const size_t row = (size_t)blockIdx.x * HDIM;

    __shared__ unsigned ebits[HDIM];
    __shared__ unsigned hist[256];
    __shared__ unsigned sc[256];
    __shared__ unsigned s_pref, s_r;

    float4 hv = ((const float4*)(H + row))[tid];
    unsigned v0 = __float_as_uint(hv.x * hv.x);
    unsigned v1 = __float_as_uint(hv.y * hv.y);
    unsigned v2 = __float_as_uint(hv.z * hv.z);
    unsigned v3 = __float_as_uint(hv.w * hv.w);
    ebits[4 * tid + 0] = v0; ebits[4 * tid + 1] = v1;
    ebits[4 * tid + 2] = v2; ebits[4 * tid + 3] = v3;
    if (tid == 0) { s_pref = 0u; s_r = KSEL; }
    __syncthreads();

    #pragma unroll
    for (int pass = 0; pass < 4; pass++) {
        const int shift = 24 - 8 * pass;
        const unsigned pref = s_pref;
        const unsigned r    = s_r;
        hist[tid] = 0u;
        __syncthreads();
        #pragma unroll
        for (int j = 0; j < 4; j++) {
            unsigned v = ebits[4 * tid + j];
            bool cand = (pass == 0) || ((v >> (shift + 8)) == (pref >> (shift + 8)));
            if (cand) atomicAdd(&hist[(v >> shift) & 0xFFu], 1u);
        }
        __syncthreads();
        sc[tid] = hist[tid];
        __syncthreads();
        for (int off = 1; off < 256; off <<= 1) {
            unsigned add = (tid + off < 256) ? sc[tid + off] : 0u;
            __syncthreads();
            sc[tid] += add;
            __syncthreads();
        }
        unsigned above = (tid == 255) ? 0u : sc[tid + 1];
        if (sc[tid] >= r && above < r) {
            s_pref = pref | ((unsigned)tid << shift);
            s_r    = r - above;
        }
        __syncthreads();
    }

    const unsigned thr  = s_pref;
    const unsigned need = s_r;

    unsigned vv[4] = {v0, v1, v2, v3};
    unsigned pos[4];
    unsigned myc = 0;
    #pragma unroll
    for (int j = 0; j < 4; j++) { pos[j] = myc; myc += (vv[j] == thr) ? 1u : 0u; }
    sc[tid] = myc;
    __syncthreads();
    for (int off = 1; off < 256; off <<= 1) {
        unsigned add = (tid >= off) ? sc[tid - off] : 0u;
        __syncthreads();
        sc[tid] += add;
        __syncthreads();
    }
    const unsigned base = sc[tid] - myc;

    float h[4] = {hv.x, hv.y, hv.z, hv.w};
    uint32_t w0[2], w1[2];
    #pragma unroll
    for (int e = 0; e < 2; e++) {
        __half hh[2], ll[2];
        #pragma unroll
        for (int q = 0; q < 2; q++) {
            int j = 2 * e + q;
            bool keep = (vv[j] > thr) || (vv[j] == thr && (base + pos[j]) < need);
            float o = (keep ? h[j] : 0.0f) * 512.f;
            hh[q] = __float2half_rn(o);
            ll[q] = __float2half_rn(o - __half2float(hh[q]));
        }
        w0[e] = pack_h2(hh[0], hh[1]);
        w1[e] = pack_h2(ll[0], ll[1]);
    }
    ((uint2*)(o0 + row))[tid] = make_uint2(w0[0], w0[1]);
    ((uint2*)(o1 + row))[tid] = make_uint2(w1[0], w1[1]);
}

// ---------------------------------------------------------------------------
// kernel_launch
// ---------------------------------------------------------------------------
extern "C" void kernel_launch(void* const* d_in, const int* in_sizes, int n_in,
                              void* d_out, int out_size)
{
    const float* x         = (const float*)d_in[0];
    const float* mask_prev = (const float*)d_in[1];
    const bool inter = (in_sizes[4] == HDIM * 512);

    const float *ew[4], *eb[4], *dw[4], *db[4];
    for (int i = 0; i < 4; i++) {
        if (inter) {
            ew[i] = (const float*)d_in[2 + 4 * i]; eb[i] = (const float*)d_in[3 + 4 * i];
            dw[i] = (const float*)d_in[4 + 4 * i]; db[i] = (const float*)d_in[5 + 4 * i];
        } else {
            ew[i] = (const float*)d_in[2 + 2 * i]; eb[i] = (const float*)d_in[3 + 2 * i];
            dw[i] = (const float*)d_in[10 + 2 * i]; db[i] = (const float*)d_in[11 + 2 * i];
        }
    }

    __half *a0, *a1, *a2, *b0, *b1, *b2, *w0, *w1, *w2;
    float* hF;
    cudaGetSymbolAddress((void**)&a0, g_a0); cudaGetSymbolAddress((void**)&a1, g_a1);
    cudaGetSymbolAddress((void**)&a2, g_a2); cudaGetSymbolAddress((void**)&b0, g_b0);
    cudaGetSymbolAddress((void**)&b1, g_b1); cudaGetSymbolAddress((void**)&b2, g_b2);
    cudaGetSymbolAddress((void**)&w0, g_w0); cudaGetSymbolAddress((void**)&w1, g_w1);
    cudaGetSymbolAddress((void**)&w2, g_w2); cudaGetSymbolAddress((void**)&hF, g_hF);

    const int SM_ENC = 3 * 3 * (8192 + 4096);   // 110592 (x2 CTAs = 221184)
    const int SM_DEC = 3 * 2 * (8192 + 4096);   // 73728
    cudaFuncSetAttribute(gemm_hmma<0>, cudaFuncAttributeMaxDynamicSharedMemorySize, SM_ENC);
    cudaFuncSetAttribute(gemm_hmma<1>, cudaFuncAttributeMaxDynamicSharedMemorySize, SM_DEC);

    // ---- weight conversion (one fused launch) ----
    struct { const float* w; int K, N; unsigned off; int np; } L[8] = {
        {ew[0], 512, 512, 0, 3},        {ew[1], 512, 512, 262144, 3},
        {ew[2], 512, 512, 524288, 3},   {ew[3], 512, 1024, 786432, 3},
        {dw[0], 1024, 512, 1310720, 2}, {dw[1], 512, 512, 1835008, 2},
        {dw[2], 512, 512, 2097152, 2},  {dw[3], 512, 512, 2359296, 2}};
    WArgs wa;
    for (int l = 0; l < 8; l++) {
        wa.src[l] = L[l].w;
        wa.off[l] = L[l].off;
        wa.ksh[l] = (L[l].K == 1024) ? 10 : 9;
        wa.N[l]   = L[l].N;
        wa.np[l]  = L[l].np;
    }
    conv_w_all<<<dim3(2048, 8), 256>>>(wa, w0, w1, w2);

    // ---- x split ----
    conv_x_kernel<<<(MTOK * 512 / 2) / 256, 256>>>(x, a0, a1, a2);

    const dim3 blk(256);
    // ---- encoder (3-way split, 6 terms, debiased accumulation) ----
    gemm_hmma<0><<<dim3(8, 512), blk, SM_ENC>>>(a0, a1, a2,
        w0 + L[0].off, w1 + L[0].off, w2 + L[0].off, eb[0], nullptr,
        b0, b1, b2, nullptr, 512, 512, 1);
    gemm_hmma<0><<<dim3(8, 512), blk, SM_ENC>>>(b0, b1, b2,
        w0 + L[1].off, w1 + L[1].off, w2 + L[1].off, eb[1], nullptr,
        a0, a1, a2, nullptr, 512, 512, 1);
    gemm_hmma<0><<<dim3(8, 512), blk, SM_ENC>>>(a0, a1, a2,
        w0 + L[2].off, w1 + L[2].off, w2 + L[2].off, eb[2], nullptr,
        b0, b1, b2, nullptr, 512, 512, 1);
    gemm_hmma<0><<<dim3(16, 512), blk, SM_ENC>>>(b0, b1, b2,
        w0 + L[3].off, w1 + L[3].off, w2 + L[3].off, eb[3], mask_prev,
        nullptr, nullptr, nullptr, hF, 1024, 512, 0);

    // ---- top-k sparsify -> split decoder input ----
    topk_mask_kernel<<<MTOK, 256>>>(hF, a0, a1);

    // ---- decoder (2-way split, 3 terms) ----
    gemm_hmma<1><<<dim3(8, 512), blk, SM_DEC>>>(a0, a1, nullptr,
        w0 + L[4].off, w1 + L[4].off, nullptr, db[0], nullptr,
        b0, b1, nullptr, nullptr, 512, 1024, 1);
    gemm_hmma<1><<<dim3(8, 512), blk, SM_DEC>>>(b0, b1, nullptr,
        w0 + L[5].off, w1 + L[5].off, nullptr, db[1], nullptr,
        a0, a1, nullptr, nullptr, 512, 512, 1);
    gemm_hmma<1><<<dim3(8, 512), blk, SM_DEC>>>(a0, a1, nullptr,
        w0 + L[6].off, w1 + L[6].off, nullptr, db[2], nullptr,
        b0, b1, nullptr, nullptr, 512, 512, 1);
    gemm_hmma<1><<<dim3(8, 512), blk, SM_DEC>>>(b0, b1, nullptr,
        w0 + L[7].off, w1 + L[7].off, nullptr, db[3], nullptr,
        nullptr, nullptr, nullptr, (float*)d_out, 512, 512, 0);
}

// round 14
// speedup vs baseline: 1.7411x; 1.0288x over previous
#include <cuda_runtime.h>
#include <cuda_fp16.h>
#include <cstdint>

#define MTOK   65536
#define HDIM   1024
#define KSEL   256

// ---------------------------------------------------------------------------
// Static scratch. Activations: splits of (value * 512), parts fp16.
// Weights: transposed [N,K] splits of (value * 512), parts fp16.
// ---------------------------------------------------------------------------
__device__ __half g_a0[(size_t)MTOK * HDIM];
__device__ __half g_a1[(size_t)MTOK * HDIM];
__device__ __half g_a2[(size_t)MTOK * HDIM];
__device__ __half g_b0[(size_t)MTOK * HDIM];
__device__ __half g_b1[(size_t)MTOK * HDIM];
__device__ __half g_b2[(size_t)MTOK * HDIM];
__device__ float  g_hF[(size_t)MTOK * HDIM];
#define WT_TOTAL 2621440
__device__ __half g_w0[WT_TOTAL];
__device__ __half g_w1[WT_TOTAL];
__device__ __half g_w2[WT_TOTAL];

// ---------------------------------------------------------------------------
// Helpers
// ---------------------------------------------------------------------------
__device__ __forceinline__ uint32_t smem_u32(const void* p) {
    uint32_t a;
    asm("{ .reg .u64 t; cvta.to.shared.u64 t, %1; cvt.u32.u64 %0, t; }" : "=r"(a) : "l"(p));
    return a;
}
__device__ __forceinline__ void ldsm4(uint32_t* r, uint32_t addr) {
    asm volatile("ldmatrix.sync.aligned.m8n8.x4.shared.b16 {%0,%1,%2,%3}, [%4];"
                 : "=r"(r[0]), "=r"(r[1]), "=r"(r[2]), "=r"(r[3]) : "r"(addr));
}
__device__ __forceinline__ void cp16(uint32_t dst, const void* src) {
    asm volatile("cp.async.cg.shared.global [%0], [%1], 16;" :: "r"(dst), "l"(src) : "memory");
}
__device__ __forceinline__ void mma16816(float* c, const uint32_t* a, uint32_t b0, uint32_t b1) {
    asm volatile(
        "mma.sync.aligned.m16n8k16.row.col.f32.f16.f16.f32 "
        "{%0,%1,%2,%3}, {%4,%5,%6,%7}, {%8,%9}, {%0,%1,%2,%3};"
        : "+f"(c[0]), "+f"(c[1]), "+f"(c[2]), "+f"(c[3])
        : "r"(a[0]), "r"(a[1]), "r"(a[2]), "r"(a[3]), "r"(b0), "r"(b1));
}
// D = A*B + 0  (fresh accumulator: no inherited C-chain truncation bias)
__device__ __forceinline__ void mma16816_z(float* d, const uint32_t* a, uint32_t b0, uint32_t b1) {
    asm volatile(
        "mma.sync.aligned.m16n8k16.row.col.f32.f16.f16.f32 "
        "{%0,%1,%2,%3}, {%4,%5,%6,%7}, {%8,%9}, {%10,%11,%12,%13};"
        : "=f"(d[0]), "=f"(d[1]), "=f"(d[2]), "=f"(d[3])
        : "r"(a[0]), "r"(a[1]), "r"(a[2]), "r"(a[3]), "r"(b0), "r"(b1),
          "f"(0.0f), "f"(0.0f), "f"(0.0f), "f"(0.0f));
}
__device__ __forceinline__ uint32_t pack_h2(__half a, __half b) {
    __half2 h2 = __halves2half2(a, b);
    return *reinterpret_cast<uint32_t*>(&h2);
}
// 64B-row smem swizzle: 16B-chunk ch of row -> ch ^ ((row>>1)&3).
// Conflict-free for ldmatrix 8-row groups AND invariant under +16-row shifts.
__device__ __forceinline__ uint32_t sw64(uint32_t row, uint32_t ch) {
    return row * 64u + ((ch ^ ((row >> 1) & 3u)) << 4);
}

// ---------------------------------------------------------------------------
// ENCODER GEMM.  true C = act( 2^-18 * sum_{6 terms} A_pa @ B_pb^T + bias )
// 3 parts each side; per-k16 fresh-accumulator extraction + RN FADD folding.
// CTA 128x64, 256 threads, 3-stage cp.async, 1 barrier/chunk, 2 CTAs/SM.
// Per-element mma chains identical to Rounds 7-13 (numerics frozen).
// ---------------------------------------------------------------------------
__global__ __launch_bounds__(256, 2)
void gemm_enc(const __half* __restrict__ A0, const __half* __restrict__ A1,
              const __half* __restrict__ A2,
              const __half* __restrict__ W0, const __half* __restrict__ W1,
              const __half* __restrict__ W2,
              const float* __restrict__ bias, const float* __restrict__ mask,
              __half* __restrict__ O0, __half* __restrict__ O1,
              __half* __restrict__ O2, float* __restrict__ OF,
              int N, int K, int relu)
{
    constexpr int NPA = 3, NT = 6;
    constexpr uint32_t PARTA = 8192;
    constexpr uint32_t PARTB = 4096;
    constexpr uint32_t BOFF  = NPA * PARTA;
    constexpr uint32_t STAGE = NPA * (PARTA + PARTB);
    constexpr int TOT = NPA * 512 + NPA * 256;
    constexpr int PA_[6] = {0, 1, 0, 2, 1, 0};
    constexpr int PB_[6] = {0, 0, 1, 0, 1, 2};

    extern __shared__ __align__(16) char smem_raw[];
    const uint32_t smb = smem_u32(smem_raw);

    const int tid    = threadIdx.x;
    const int wid    = tid >> 5;
    const int lane   = tid & 31;
    const int warp_m = wid & 3;
    const int warp_n = wid >> 2;
    const int g      = lane >> 2;
    const int tg     = lane & 3;
    const int bm     = blockIdx.y * 128;
    const int bn     = blockIdx.x * 64;
    const int C      = K >> 5;

    const __half* Pp[6] = {A0, A1, A2, W0, W1, W2};

    auto load_stage = [&](int c, int slot) {
        const uint32_t sbase = smb + (uint32_t)slot * STAGE;
        #pragma unroll
        for (int s = 0; s < TOT / 256; s++) {
            int i = s * 256 + tid;
            const __half* src;
            uint32_t dst;
            if (i < NPA * 512) {
                int p = i >> 9, j = i & 511;
                uint32_t row = (uint32_t)(j >> 2), ch = (uint32_t)(j & 3);
                src = Pp[p] + (size_t)(bm + row) * K + c * 32 + ch * 8;
                dst = sbase + (uint32_t)p * PARTA + sw64(row, ch);
            } else {
                int q = i - NPA * 512;
                int p = q >> 8, j = q & 255;
                uint32_t row = (uint32_t)(j >> 2), ch = (uint32_t)(j & 3);
                src = Pp[NPA + p] + (size_t)(bn + row) * K + c * 32 + ch * 8;
                dst = sbase + BOFF + (uint32_t)p * PARTB + sw64(row, ch);
            }
            cp16(dst, src);
        }
        asm volatile("cp.async.commit_group;" ::: "memory");
    };

    load_stage(0, 0);
    if (C > 1) load_stage(1, 1);

    float acc[2][4][4];
    #pragma unroll
    for (int i = 0; i < 2; i++)
        #pragma unroll
        for (int j = 0; j < 4; j++)
            #pragma unroll
            for (int e = 0; e < 4; e++) acc[i][j][e] = 0.0f;

    const uint32_t lrA = (uint32_t)((lane & 7) + ((lane >> 3) & 1) * 8);
    const uint32_t lcA = (uint32_t)((lane >> 4) & 1);
    const uint32_t lrB = (uint32_t)((lane & 7) + ((lane >> 4) & 1) * 8);
    const uint32_t lcB = (uint32_t)((lane >> 3) & 1);
    uint32_t laneA[2], laneB[2];
    #pragma unroll
    for (int kh = 0; kh < 2; kh++) {
        laneA[kh] = (uint32_t)(warp_m * 32) * 64u + sw64(lrA, lcA + 2u * kh);
        laneB[kh] = (uint32_t)(warp_n * 32) * 64u + sw64(lrB, lcB + 2u * kh);
    }

    for (int c = 0; c < C; c++) {
        if (c + 1 < C) asm volatile("cp.async.wait_group 1;" ::: "memory");
        else           asm volatile("cp.async.wait_group 0;" ::: "memory");
        __syncthreads();

        if (c + 2 < C) load_stage(c + 2, (c + 2) % 3);

        const uint32_t sb0 = smb + (uint32_t)(c % 3) * STAGE;

        #pragma unroll
        for (int kh = 0; kh < 2; kh++) {
            float tmp[2][4][4];
            #pragma unroll
            for (int t = 0; t < NT; t++) {
                const uint32_t aBase = sb0 + (uint32_t)PA_[t] * PARTA + laneA[kh];
                const uint32_t bBase = sb0 + BOFF + (uint32_t)PB_[t] * PARTB + laneB[kh];
                uint32_t af[2][4], bf[2][4];
                ldsm4(af[0], aBase);
                ldsm4(af[1], aBase + 16u * 64u);
                ldsm4(bf[0], bBase);
                ldsm4(bf[1], bBase + 16u * 64u);
                #pragma unroll
                for (int nt = 0; nt < 4; nt++) {
                    uint32_t b0 = bf[nt >> 1][(nt & 1) * 2];
                    uint32_t b1 = bf[nt >> 1][(nt & 1) * 2 + 1];
                    #pragma unroll
                    for (int mt = 0; mt < 2; mt++) {
                        if (t == 0) mma16816_z(tmp[mt][nt], af[mt], b0, b1);
                        else        mma16816(tmp[mt][nt], af[mt], b0, b1);
                    }
                }
            }
            #pragma unroll
            for (int mt = 0; mt < 2; mt++)
                #pragma unroll
                for (int nt = 0; nt < 4; nt++)
                    #pragma unroll
                    for (int e = 0; e < 4; e++)
                        acc[mt][nt][e] += tmp[mt][nt][e];
        }
    }

    // ---- epilogue (identical per-element math to Rounds 7-13) ----
    const float SCL = 1.0f / 262144.0f;       // 2^-18
    #pragma unroll
    for (int mt = 0; mt < 2; mt++) {
        #pragma unroll
        for (int nt = 0; nt < 4; nt++) {
            const int row = bm + warp_m * 32 + mt * 16 + g;
            const int col = bn + warp_n * 32 + nt * 8 + tg * 2;
            const float bz0 = __ldg(bias + col);
            const float bz1 = __ldg(bias + col + 1);
            float v0 = acc[mt][nt][0] * SCL + bz0;
            float v1 = acc[mt][nt][1] * SCL + bz1;
            float v2 = acc[mt][nt][2] * SCL + bz0;   // row + 8
            float v3 = acc[mt][nt][3] * SCL + bz1;
            if (relu) {
                v0 = fmaxf(v0, 0.f); v1 = fmaxf(v1, 0.f);
                v2 = fmaxf(v2, 0.f); v3 = fmaxf(v3, 0.f);
            }
            const size_t i0 = (size_t)row * N + col;
            const size_t i1 = (size_t)(row + 8) * N + col;
            if (OF) {
                if (mask) {
                    const float2 m0 = *(const float2*)(mask + i0);
                    const float2 m1 = *(const float2*)(mask + i1);
                    if (m0.x > 0.f) v0 = 0.f;
                    if (m0.y > 0.f) v1 = 0.f;
                    if (m1.x > 0.f) v2 = 0.f;
                    if (m1.y > 0.f) v3 = 0.f;
                }
                *(float2*)(OF + i0) = make_float2(v0, v1);
                *(float2*)(OF + i1) = make_float2(v2, v3);
            } else {
                float s0 = v0 * 512.f, s1 = v1 * 512.f;
                float s2 = v2 * 512.f, s3 = v3 * 512.f;
                __half h0 = __float2half_rn(s0), h1 = __float2half_rn(s1);
                __half h2 = __float2half_rn(s2), h3 = __float2half_rn(s3);
                float r0 = s0 - __half2float(h0), r1 = s1 - __half2float(h1);
                float r2 = s2 - __half2float(h2), r3 = s3 - __half2float(h3);
                __half q0 = __float2half_rn(r0), q1 = __float2half_rn(r1);
                __half q2 = __float2half_rn(r2), q3 = __float2half_rn(r3);
                *(uint32_t*)(O0 + i0) = pack_h2(h0, h1);
                *(uint32_t*)(O0 + i1) = pack_h2(h2, h3);
                *(uint32_t*)(O1 + i0) = pack_h2(q0, q1);
                *(uint32_t*)(O1 + i1) = pack_h2(q2, q3);
                *(uint32_t*)(O2 + i0) = pack_h2(__float2half_rn(r0 - __half2float(q0)),
                                                __float2half_rn(r1 - __half2float(q1)));
                *(uint32_t*)(O2 + i1) = pack_h2(__float2half_rn(r2 - __half2float(q2)),
                                                __float2half_rn(r3 - __half2float(q3)));
            }
        }
    }
}

// ---------------------------------------------------------------------------
// DECODER GEMM.  3 terms, direct HW chaining (order c -> t -> kh, frozen).
// Same tile/pipeline as encoder but only 2 parts -> fits 3 CTAs/SM
// (__launch_bounds__(256,3): regs<=84, smem 3 stages x 24KB = 72KB/CTA).
// ---------------------------------------------------------------------------
__global__ __launch_bounds__(256, 3)
void gemm_dec(const __half* __restrict__ A0, const __half* __restrict__ A1,
              const __half* __restrict__ W0, const __half* __restrict__ W1,
              const float* __restrict__ bias,
              __half* __restrict__ O0, __half* __restrict__ O1,
              float* __restrict__ OF,
              int N, int K, int relu)
{
    constexpr int NPA = 2, NT = 3;
    constexpr uint32_t PARTA = 8192;
    constexpr uint32_t PARTB = 4096;
    constexpr uint32_t BOFF  = NPA * PARTA;
    constexpr uint32_t STAGE = NPA * (PARTA + PARTB);
    constexpr int TOT = NPA * 512 + NPA * 256;
    constexpr int PA_[3] = {0, 1, 0};
    constexpr int PB_[3] = {0, 0, 1};

    extern __shared__ __align__(16) char smem_raw[];
    const uint32_t smb = smem_u32(smem_raw);

    const int tid    = threadIdx.x;
    const int wid    = tid >> 5;
    const int lane   = tid & 31;
    const int warp_m = wid & 3;
    const int warp_n = wid >> 2;
    const int g      = lane >> 2;
    const int tg     = lane & 3;
    const int bm     = blockIdx.y * 128;
    const int bn     = blockIdx.x * 64;
    const int C      = K >> 5;

    const __half* Pp[4] = {A0, A1, W0, W1};

    auto load_stage = [&](int c, int slot) {
        const uint32_t sbase = smb + (uint32_t)slot * STAGE;
        #pragma unroll
        for (int s = 0; s < TOT / 256; s++) {
            int i = s * 256 + tid;
            const __half* src;
            uint32_t dst;
            if (i < NPA * 512) {
                int p = i >> 9, j = i & 511;
                uint32_t row = (uint32_t)(j >> 2), ch = (uint32_t)(j & 3);
                src = Pp[p] + (size_t)(bm + row) * K + c * 32 + ch * 8;
                dst = sbase + (uint32_t)p * PARTA + sw64(row, ch);
            } else {
                int q = i - NPA * 512;
                int p = q >> 8, j = q & 255;
                uint32_t row = (uint32_t)(j >> 2), ch = (uint32_t)(j & 3);
                src = Pp[NPA + p] + (size_t)(bn + row) * K + c * 32 + ch * 8;
                dst = sbase + BOFF + (uint32_t)p * PARTB + sw64(row, ch);
            }
            cp16(dst, src);
        }
        asm volatile("cp.async.commit_group;" ::: "memory");
    };

    load_stage(0, 0);
    if (C > 1) load_stage(1, 1);

    float acc[2][4][4];
    #pragma unroll
    for (int i = 0; i < 2; i++)
        #pragma unroll
        for (int j = 0; j < 4; j++)
            #pragma unroll
            for (int e = 0; e < 4; e++) acc[i][j][e] = 0.0f;

    const uint32_t lrA = (uint32_t)((lane & 7) + ((lane >> 3) & 1) * 8);
    const uint32_t lcA = (uint32_t)((lane >> 4) & 1);
    const uint32_t lrB = (uint32_t)((lane & 7) + ((lane >> 4) & 1) * 8);
    const uint32_t lcB = (uint32_t)((lane >> 3) & 1);
    uint32_t laneA[2], laneB[2];
    #pragma unroll
    for (int kh = 0; kh < 2; kh++) {
        laneA[kh] = (uint32_t)(warp_m * 32) * 64u + sw64(lrA, lcA + 2u * kh);
        laneB[kh] = (uint32_t)(warp_n * 32) * 64u + sw64(lrB, lcB + 2u * kh);
    }

    for (int c = 0; c < C; c++) {
        if (c + 1 < C) asm volatile("cp.async.wait_group 1;" ::: "memory");
        else           asm volatile("cp.async.wait_group 0;" ::: "memory");
        __syncthreads();

        if (c + 2 < C) load_stage(c + 2, (c + 2) % 3);

        const uint32_t sb0 = smb + (uint32_t)(c % 3) * STAGE;

        #pragma unroll
        for (int t = 0; t < NT; t++) {
            #pragma unroll
            for (int kh = 0; kh < 2; kh++) {
                const uint32_t aBase = sb0 + (uint32_t)PA_[t] * PARTA + laneA[kh];
                const uint32_t bBase = sb0 + BOFF + (uint32_t)PB_[t] * PARTB + laneB[kh];
                uint32_t af[2][4], bf[2][4];
                ldsm4(af[0], aBase);
                ldsm4(af[1], aBase + 16u * 64u);
                ldsm4(bf[0], bBase);
                ldsm4(bf[1], bBase + 16u * 64u);
                #pragma unroll
                for (int nt = 0; nt < 4; nt++) {
                    uint32_t b0 = bf[nt >> 1][(nt & 1) * 2];
                    uint32_t b1 = bf[nt >> 1][(nt & 1) * 2 + 1];
                    #pragma unroll
                    for (int mt = 0; mt < 2; mt++)
                        mma16816(acc[mt][nt], af[mt], b0, b1);
                }
            }
        }
    }

    // ---- epilogue (identical per-element math to Rounds 7-13) ----
    const float SCL = 1.0f / 262144.0f;       // 2^-18
    #pragma unroll
    for (int mt = 0; mt < 2; mt++) {
        #pragma unroll
        for (int nt = 0; nt < 4; nt++) {
            const int row = bm + warp_m * 32 + mt * 16 + g;
            const int col = bn + warp_n * 32 + nt * 8 + tg * 2;
            const float bz0 = __ldg(bias + col);
            const float bz1 = __ldg(bias + col + 1);
            float v0 = acc[mt][nt][0] * SCL + bz0;
            float v1 = acc[mt][nt][1] * SCL + bz1;
            float v2 = acc[mt][nt][2] * SCL + bz0;   // row + 8
            float v3 = acc[mt][nt][3] * SCL + bz1;
            if (relu) {
                v0 = fmaxf(v0, 0.f); v1 = fmaxf(v1, 0.f);
                v2 = fmaxf(v2, 0.f); v3 = fmaxf(v3, 0.f);
            }
            const size_t i0 = (size_t)row * N + col;
            const size_t i1 = (size_t)(row + 8) * N + col;
            if (OF) {
                *(float2*)(OF + i0) = make_float2(v0, v1);
                *(float2*)(OF + i1) = make_float2(v2, v3);
            } else {
                float s0 = v0 * 512.f, s1 = v1 * 512.f;
                float s2 = v2 * 512.f, s3 = v3 * 512.f;
                __half h0 = __float2half_rn(s0), h1 = __float2half_rn(s1);
                __half h2 = __float2half_rn(s2), h3 = __float2half_rn(s3);
                float r0 = s0 - __half2float(h0), r1 = s1 - __half2float(h1);
                float r2 = s2 - __half2float(h2), r3 = s3 - __half2float(h3);
                __half q0 = __float2half_rn(r0), q1 = __float2half_rn(r1);
                __half q2 = __float2half_rn(r2), q3 = __float2half_rn(r3);
                *(uint32_t*)(O0 + i0) = pack_h2(h0, h1);
                *(uint32_t*)(O0 + i1) = pack_h2(h2, h3);
                *(uint32_t*)(O1 + i0) = pack_h2(q0, q1);
                *(uint32_t*)(O1 + i1) = pack_h2(q2, q3);
            }
        }
    }
}

// ---------------------------------------------------------------------------
// x -> 3-way fp16 split (scaled by 512)
// ---------------------------------------------------------------------------
__global__ void conv_x_kernel(const float* __restrict__ x,
                              __half* __restrict__ o0, __half* __restrict__ o1,
                              __half* __restrict__ o2)
{
    size_t i = ((size_t)blockIdx.x * blockDim.x + threadIdx.x) * 2;
    float x0 = x[i] * 512.f, x1 = x[i + 1] * 512.f;
    __half h0 = __float2half_rn(x0), h1 = __float2half_rn(x1);
    float r0 = x0 - __half2float(h0), r1 = x1 - __half2float(h1);
    __half q0 = __float2half_rn(r0), q1 = __float2half_rn(r1);
    __half u0 = __float2half_rn(r0 - __half2float(q0));
    __half u1 = __float2half_rn(r1 - __half2float(q1));
    *(uint32_t*)(o0 + i) = pack_h2(h0, h1);
    *(uint32_t*)(o1 + i) = pack_h2(q0, q1);
    *(uint32_t*)(o2 + i) = pack_h2(u0, u1);
}

// ---------------------------------------------------------------------------
// Fused weight conversion (one launch): W[K,N] -> transposed split parts.
// ---------------------------------------------------------------------------
struct WArgs {
    const float* src[8];
    unsigned off[8];
    int ksh[8];
    int N[8];
    int np[8];
};
__global__ void conv_w_all(WArgs A, __half* __restrict__ o0,
                           __half* __restrict__ o1, __half* __restrict__ o2)
{
    const int l = blockIdx.y;
    const int tot = A.N[l] << A.ksh[l];
    const int idx = blockIdx.x * blockDim.x + threadIdx.x;
    if (idx >= tot) return;
    const int n = idx >> A.ksh[l];
    const int k = idx & ((1 << A.ksh[l]) - 1);
    float w = A.src[l][(size_t)k * A.N[l] + n] * 512.f;
    __half h = __float2half_rn(w);
    float r = w - __half2float(h);
    __half q = __float2half_rn(r);
    const unsigned o = A.off[l] + idx;
    o0[o] = h;
    o1[o] = q;
    if (A.np[l] == 3) o2[o] = __float2half_rn(r - __half2float(q));
}

// ---------------------------------------------------------------------------
// Exact per-token top-256-of-1024 by h^2 (radix select on float bit pattern).
// Output = 2-way fp16 split (scaled by 512) of (kept ? h : 0).
// ---------------------------------------------------------------------------
__global__ __launch_bounds__(256)
void topk_mask_kernel(const float* __restrict__ H,
                      __half* __restrict__ o0, __half* __restrict__ o1)
{
    const int tid = threadIdx.x;
    const size_t row = (size_t)blockIdx.x * HDIM;

    __shared__ unsigned ebits[HDIM];
    __shared__ unsigned hist[256];
    __shared__ unsigned sc[256];
    __shared__ unsigned s_pref, s_r;

    float4 hv = ((const float4*)(H + row))[tid];
    unsigned v0 = __float_as_uint(hv.x * hv.x);
    unsigned v1 = __float_as_uint(hv.y * hv.y);
    unsigned v2 = __float_as_uint(hv.z * hv.z);
    unsigned v3 = __float_as_uint(hv.w * hv.w);
    ebits[4 * tid + 0] = v0; ebits[4 * tid + 1] = v1;
    ebits[4 * tid + 2] = v2; ebits[4 * tid + 3] = v3;
    if (tid == 0) { s_pref = 0u; s_r = KSEL; }
    __syncthreads();

    #pragma unroll
    for (int pass = 0; pass < 4; pass++) {
        const int shift = 24 - 8 * pass;
        const unsigned pref = s_pref;
        const unsigned r    = s_r;
        hist[tid] = 0u;
        __syncthreads();
        #pragma unroll
        for (int j = 0; j < 4; j++) {
            unsigned v = ebits[4 * tid + j];
            bool cand = (pass == 0) || ((v >> (shift + 8)) == (pref >> (shift + 8)));
            if (cand) atomicAdd(&hist[(v >> shift) & 0xFFu], 1u);
        }
        __syncthreads();
        sc[tid] = hist[tid];
        __syncthreads();
        for (int off = 1; off < 256; off <<= 1) {
            unsigned add = (tid + off < 256) ? sc[tid + off] : 0u;
            __syncthreads();
            sc[tid] += add;
            __syncthreads();
        }
        unsigned above = (tid == 255) ? 0u : sc[tid + 1];
        if (sc[tid] >= r && above < r) {
            s_pref = pref | ((unsigned)tid << shift);
            s_r    = r - above;
        }
        __syncthreads();
    }

    const unsigned thr  = s_pref;
    const unsigned need = s_r;

    unsigned vv[4] = {v0, v1, v2, v3};
    unsigned pos[4];
    unsigned myc = 0;
    #pragma unroll
    for (int j = 0; j < 4; j++) { pos[j] = myc; myc += (vv[j] == thr) ? 1u : 0u; }
    sc[tid] = myc;
    __syncthreads();
    for (int off = 1; off < 256; off <<= 1) {
        unsigned add = (tid >= off) ? sc[tid - off] : 0u;
        __syncthreads();
        sc[tid] += add;
        __syncthreads();
    }
    const unsigned base = sc[tid] - myc;

    float h[4] = {hv.x, hv.y, hv.z, hv.w};
    uint32_t w0[2], w1[2];
    #pragma unroll
    for (int e = 0; e < 2; e++) {
        __half hh[2], ll[2];
        #pragma unroll
        for (int q = 0; q < 2; q++) {
            int j = 2 * e + q;
            bool keep = (vv[j] > thr) || (vv[j] == thr && (base + pos[j]) < need);
            float o = (keep ? h[j] : 0.0f) * 512.f;
            hh[q] = __float2half_rn(o);
            ll[q] = __float2half_rn(o - __half2float(hh[q]));
        }
        w0[e] = pack_h2(hh[0], hh[1]);
        w1[e] = pack_h2(ll[0], ll[1]);
    }
    ((uint2*)(o0 + row))[tid] = make_uint2(w0[0], w0[1]);
    ((uint2*)(o1 + row))[tid] = make_uint2(w1[0], w1[1]);
}

// ---------------------------------------------------------------------------
// kernel_launch
// ---------------------------------------------------------------------------
extern "C" void kernel_launch(void* const* d_in, const int* in_sizes, int n_in,
                              void* d_out, int out_size)
{
    const float* x         = (const float*)d_in[0];
    const float* mask_prev = (const float*)d_in[1];
    const bool inter = (in_sizes[4] == HDIM * 512);

    const float *ew[4], *eb[4], *dw[4], *db[4];
    for (int i = 0; i < 4; i++) {
        if (inter) {
            ew[i] = (const float*)d_in[2 + 4 * i]; eb[i] = (const float*)d_in[3 + 4 * i];
            dw[i] = (const float*)d_in[4 + 4 * i]; db[i] = (const float*)d_in[5 + 4 * i];
        } else {
            ew[i] = (const float*)d_in[2 + 2 * i]; eb[i] = (const float*)d_in[3 + 2 * i];
            dw[i] = (const float*)d_in[10 + 2 * i]; db[i] = (const float*)d_in[11 + 2 * i];
        }
    }

    __half *a0, *a1, *a2, *b0, *b1, *b2, *w0, *w1, *w2;
    float* hF;
    cudaGetSymbolAddress((void**)&a0, g_a0); cudaGetSymbolAddress((void**)&a1, g_a1);
    cudaGetSymbolAddress((void**)&a2, g_a2); cudaGetSymbolAddress((void**)&b0, g_b0);
    cudaGetSymbolAddress((void**)&b1, g_b1); cudaGetSymbolAddress((void**)&b2, g_b2);
    cudaGetSymbolAddress((void**)&w0, g_w0); cudaGetSymbolAddress((void**)&w1, g_w1);
    cudaGetSymbolAddress((void**)&w2, g_w2); cudaGetSymbolAddress((void**)&hF, g_hF);

    const int SM_ENC = 3 * 3 * (8192 + 4096);   // 110592/CTA (2 CTAs/SM)
    const int SM_DEC = 3 * 2 * (8192 + 4096);   // 73728/CTA  (3 CTAs/SM)
    cudaFuncSetAttribute(gemm_enc, cudaFuncAttributeMaxDynamicSharedMemorySize, SM_ENC);
    cudaFuncSetAttribute(gemm_dec, cudaFuncAttributeMaxDynamicSharedMemorySize, SM_DEC);

    // ---- weight conversion (one fused launch) ----
    struct { const float* w; int K, N; unsigned off; int np; } L[8] = {
        {ew[0], 512, 512, 0, 3},        {ew[1], 512, 512, 262144, 3},
        {ew[2], 512, 512, 524288, 3},   {ew[3], 512, 1024, 786432, 3},
        {dw[0], 1024, 512, 1310720, 2}, {dw[1], 512, 512, 1835008, 2},
        {dw[2], 512, 512, 2097152, 2},  {dw[3], 512, 512, 2359296, 2}};
    WArgs wa;
    for (int l = 0; l < 8; l++) {
        wa.src[l] = L[l].w;
        wa.off[l] = L[l].off;
        wa.ksh[l] = (L[l].K == 1024) ? 10 : 9;
        wa.N[l]   = L[l].N;
        wa.np[l]  = L[l].np;
    }
    conv_w_all<<<dim3(2048, 8), 256>>>(wa, w0, w1, w2);

    // ---- x split ----
    conv_x_kernel<<<(MTOK * 512 / 2) / 256, 256>>>(x, a0, a1, a2);

    const dim3 blk(256);
    // ---- encoder (3-way split, 6 terms, debiased accumulation) ----
    gemm_enc<<<dim3(8, 512), blk, SM_ENC>>>(a0, a1, a2,
        w0 + L[0].off, w1 + L[0].off, w2 + L[0].off, eb[0], nullptr,
        b0, b1, b2, nullptr, 512, 512, 1);
    gemm_enc<<<dim3(8, 512), blk, SM_ENC>>>(b0, b1, b2,
        w0 + L[1].off, w1 + L[1].off, w2 + L[1].off, eb[1], nullptr,
        a0, a1, a2, nullptr, 512, 512, 1);
    gemm_enc<<<dim3(8, 512), blk, SM_ENC>>>(a0, a1, a2,
        w0 + L[2].off, w1 + L[2].off, w2 + L[2].off, eb[2], nullptr,
        b0, b1, b2, nullptr, 512, 512, 1);
    gemm_enc<<<dim3(16, 512), blk, SM_ENC>>>(b0, b1, b2,
        w0 + L[3].off, w1 + L[3].off, w2 + L[3].off, eb[3], mask_prev,
        nullptr, nullptr, nullptr, hF, 1024, 512, 0);

    // ---- top-k sparsify -> split decoder input ----
    topk_mask_kernel<<<MTOK, 256>>>(hF, a0, a1);

    // ---- decoder (2-way split, 3 terms, 3 CTAs/SM) ----
    gemm_dec<<<dim3(8, 512), blk, SM_DEC>>>(a0, a1,
        w0 + L[4].off, w1 + L[4].off, db[0],
        b0, b1, nullptr, 512, 1024, 1);
    gemm_dec<<<dim3(8, 512), blk, SM_DEC>>>(b0, b1,
        w0 + L[5].off, w1 + L[5].off, db[1],
        a0, a1, nullptr, 512, 512, 1);
    gemm_dec<<<dim3(8, 512), blk, SM_DEC>>>(a0, a1,
        w0 + L[6].off, w1 + L[6].off, db[2],
        b0, b1, nullptr, 512, 512, 1);
    gemm_dec<<<dim3(8, 512), blk, SM_DEC>>>(b0, b1,
        w0 + L[7].off, w1 + L[7].off, db[3],
        nullptr, nullptr, (float*)d_out, 512, 512, 0);
}

// round 15
// speedup vs baseline: 2.1432x; 1.2310x over previous
#include <cuda_runtime.h>
#include <cuda_fp16.h>
#include <cstdint>

#define MTOK   65536
#define HDIM   1024
#define KSEL   256

// ---------------------------------------------------------------------------
// Static scratch. Activations: 2-part fp16 splits of (value * 512).
// Weights: transposed [N,K] 2-part splits of (value * 512).
// ---------------------------------------------------------------------------
__device__ __half g_a0[(size_t)MTOK * HDIM];
__device__ __half g_a1[(size_t)MTOK * HDIM];
__device__ __half g_b0[(size_t)MTOK * HDIM];
__device__ __half g_b1[(size_t)MTOK * HDIM];
__device__ float  g_hF[(size_t)MTOK * HDIM];
#define WT_TOTAL 2621440
__device__ __half g_w0[WT_TOTAL];
__device__ __half g_w1[WT_TOTAL];

// ---------------------------------------------------------------------------
// Helpers
// ---------------------------------------------------------------------------
__device__ __forceinline__ uint32_t smem_u32(const void* p) {
    uint32_t a;
    asm("{ .reg .u64 t; cvta.to.shared.u64 t, %1; cvt.u32.u64 %0, t; }" : "=r"(a) : "l"(p));
    return a;
}
__device__ __forceinline__ void ldsm4(uint32_t* r, uint32_t addr) {
    asm volatile("ldmatrix.sync.aligned.m8n8.x4.shared.b16 {%0,%1,%2,%3}, [%4];"
                 : "=r"(r[0]), "=r"(r[1]), "=r"(r[2]), "=r"(r[3]) : "r"(addr));
}
__device__ __forceinline__ void cp16(uint32_t dst, const void* src) {
    asm volatile("cp.async.cg.shared.global [%0], [%1], 16;" :: "r"(dst), "l"(src) : "memory");
}
__device__ __forceinline__ void mma16816(float* c, const uint32_t* a, uint32_t b0, uint32_t b1) {
    asm volatile(
        "mma.sync.aligned.m16n8k16.row.col.f32.f16.f16.f32 "
        "{%0,%1,%2,%3}, {%4,%5,%6,%7}, {%8,%9}, {%0,%1,%2,%3};"
        : "+f"(c[0]), "+f"(c[1]), "+f"(c[2]), "+f"(c[3])
        : "r"(a[0]), "r"(a[1]), "r"(a[2]), "r"(a[3]), "r"(b0), "r"(b1));
}
// D = A*B + 0  (fresh accumulator: no inherited C-chain truncation bias)
__device__ __forceinline__ void mma16816_z(float* d, const uint32_t* a, uint32_t b0, uint32_t b1) {
    asm volatile(
        "mma.sync.aligned.m16n8k16.row.col.f32.f16.f16.f32 "
        "{%0,%1,%2,%3}, {%4,%5,%6,%7}, {%8,%9}, {%10,%11,%12,%13};"
        : "=f"(d[0]), "=f"(d[1]), "=f"(d[2]), "=f"(d[3])
        : "r"(a[0]), "r"(a[1]), "r"(a[2]), "r"(a[3]), "r"(b0), "r"(b1),
          "f"(0.0f), "f"(0.0f), "f"(0.0f), "f"(0.0f));
}
__device__ __forceinline__ uint32_t pack_h2(__half a, __half b) {
    __half2 h2 = __halves2half2(a, b);
    return *reinterpret_cast<uint32_t*>(&h2);
}
// 64B-row smem swizzle: 16B-chunk ch of row -> ch ^ ((row>>1)&3).
__device__ __forceinline__ uint32_t sw64(uint32_t row, uint32_t ch) {
    return row * 64u + ((ch ^ ((row >> 1) & 3u)) << 4);
}

// ---------------------------------------------------------------------------
// ENCODER GEMM.  true C = act( 2^-18 * sum_{4 terms} A_pa @ B_pb^T + bias )
// 2 parts each side, terms {a0b0, a1b0, a0b1, a1b1}; per-k16 fresh-accumulator
// extraction + RN FADD folding (debiased). CTA 128x64, 256 threads,
// 3-stage cp.async, 1 barrier/chunk, 2 CTAs/SM.
// ---------------------------------------------------------------------------
__global__ __launch_bounds__(256, 2)
void gemm_enc(const __half* __restrict__ A0, const __half* __restrict__ A1,
              const __half* __restrict__ W0, const __half* __restrict__ W1,
              const float* __restrict__ bias, const float* __restrict__ mask,
              __half* __restrict__ O0, __half* __restrict__ O1,
              float* __restrict__ OF,
              int N, int K, int relu)
{
    constexpr int NPA = 2, NT = 4;
    constexpr uint32_t PARTA = 8192;
    constexpr uint32_t PARTB = 4096;
    constexpr uint32_t BOFF  = NPA * PARTA;
    constexpr uint32_t STAGE = NPA * (PARTA + PARTB);
    constexpr int TOT = NPA * 512 + NPA * 256;
    constexpr int PA_[4] = {0, 1, 0, 1};
    constexpr int PB_[4] = {0, 0, 1, 1};

    extern __shared__ __align__(16) char smem_raw[];
    const uint32_t smb = smem_u32(smem_raw);

    const int tid    = threadIdx.x;
    const int wid    = tid >> 5;
    const int lane   = tid & 31;
    const int warp_m = wid & 3;
    const int warp_n = wid >> 2;
    const int g      = lane >> 2;
    const int tg     = lane & 3;
    const int bm     = blockIdx.y * 128;
    const int bn     = blockIdx.x * 64;
    const int C      = K >> 5;

    const __half* Pp[4] = {A0, A1, W0, W1};

    auto load_stage = [&](int c, int slot) {
        const uint32_t sbase = smb + (uint32_t)slot * STAGE;
        #pragma unroll
        for (int s = 0; s < TOT / 256; s++) {
            int i = s * 256 + tid;
            const __half* src;
            uint32_t dst;
            if (i < NPA * 512) {
                int p = i >> 9, j = i & 511;
                uint32_t row = (uint32_t)(j >> 2), ch = (uint32_t)(j & 3);
                src = Pp[p] + (size_t)(bm + row) * K + c * 32 + ch * 8;
                dst = sbase + (uint32_t)p * PARTA + sw64(row, ch);
            } else {
                int q = i - NPA * 512;
                int p = q >> 8, j = q & 255;
                uint32_t row = (uint32_t)(j >> 2), ch = (uint32_t)(j & 3);
                src = Pp[NPA + p] + (size_t)(bn + row) * K + c * 32 + ch * 8;
                dst = sbase + BOFF + (uint32_t)p * PARTB + sw64(row, ch);
            }
            cp16(dst, src);
        }
        asm volatile("cp.async.commit_group;" ::: "memory");
    };

    load_stage(0, 0);
    if (C > 1) load_stage(1, 1);

    float acc[2][4][4];
    #pragma unroll
    for (int i = 0; i < 2; i++)
        #pragma unroll
        for (int j = 0; j < 4; j++)
            #pragma unroll
            for (int e = 0; e < 4; e++) acc[i][j][e] = 0.0f;

    const uint32_t lrA = (uint32_t)((lane & 7) + ((lane >> 3) & 1) * 8);
    const uint32_t lcA = (uint32_t)((lane >> 4) & 1);
    const uint32_t lrB = (uint32_t)((lane & 7) + ((lane >> 4) & 1) * 8);
    const uint32_t lcB = (uint32_t)((lane >> 3) & 1);
    uint32_t laneA[2], laneB[2];
    #pragma unroll
    for (int kh = 0; kh < 2; kh++) {
        laneA[kh] = (uint32_t)(warp_m * 32) * 64u + sw64(lrA, lcA + 2u * kh);
        laneB[kh] = (uint32_t)(warp_n * 32) * 64u + sw64(lrB, lcB + 2u * kh);
    }

    for (int c = 0; c < C; c++) {
        if (c + 1 < C) asm volatile("cp.async.wait_group 1;" ::: "memory");
        else           asm volatile("cp.async.wait_group 0;" ::: "memory");
        __syncthreads();

        if (c + 2 < C) load_stage(c + 2, (c + 2) % 3);

        const uint32_t sb0 = smb + (uint32_t)(c % 3) * STAGE;

        #pragma unroll
        for (int kh = 0; kh < 2; kh++) {
            float tmp[2][4][4];
            #pragma unroll
            for (int t = 0; t < NT; t++) {
                const uint32_t aBase = sb0 + (uint32_t)PA_[t] * PARTA + laneA[kh];
                const uint32_t bBase = sb0 + BOFF + (uint32_t)PB_[t] * PARTB + laneB[kh];
                uint32_t af[2][4], bf[2][4];
                ldsm4(af[0], aBase);
                ldsm4(af[1], aBase + 16u * 64u);
                ldsm4(bf[0], bBase);
                ldsm4(bf[1], bBase + 16u * 64u);
                #pragma unroll
                for (int nt = 0; nt < 4; nt++) {
                    uint32_t b0 = bf[nt >> 1][(nt & 1) * 2];
                    uint32_t b1 = bf[nt >> 1][(nt & 1) * 2 + 1];
                    #pragma unroll
                    for (int mt = 0; mt < 2; mt++) {
                        if (t == 0) mma16816_z(tmp[mt][nt], af[mt], b0, b1);
                        else        mma16816(tmp[mt][nt], af[mt], b0, b1);
                    }
                }
            }
            #pragma unroll
            for (int mt = 0; mt < 2; mt++)
                #pragma unroll
                for (int nt = 0; nt < 4; nt++)
                    #pragma unroll
                    for (int e = 0; e < 4; e++)
                        acc[mt][nt][e] += tmp[mt][nt][e];
        }
    }

    // ---- epilogue ----
    const float SCL = 1.0f / 262144.0f;       // 2^-18
    #pragma unroll
    for (int mt = 0; mt < 2; mt++) {
        #pragma unroll
        for (int nt = 0; nt < 4; nt++) {
            const int row = bm + warp_m * 32 + mt * 16 + g;
            const int col = bn + warp_n * 32 + nt * 8 + tg * 2;
            const float bz0 = __ldg(bias + col);
            const float bz1 = __ldg(bias + col + 1);
            float v0 = acc[mt][nt][0] * SCL + bz0;
            float v1 = acc[mt][nt][1] * SCL + bz1;
            float v2 = acc[mt][nt][2] * SCL + bz0;   // row + 8
            float v3 = acc[mt][nt][3] * SCL + bz1;
            if (relu) {
                v0 = fmaxf(v0, 0.f); v1 = fmaxf(v1, 0.f);
                v2 = fmaxf(v2, 0.f); v3 = fmaxf(v3, 0.f);
            }
            const size_t i0 = (size_t)row * N + col;
            const size_t i1 = (size_t)(row + 8) * N + col;
            if (OF) {
                if (mask) {
                    const float2 m0 = *(const float2*)(mask + i0);
                    const float2 m1 = *(const float2*)(mask + i1);
                    if (m0.x > 0.f) v0 = 0.f;
                    if (m0.y > 0.f) v1 = 0.f;
                    if (m1.x > 0.f) v2 = 0.f;
                    if (m1.y > 0.f) v3 = 0.f;
                }
                *(float2*)(OF + i0) = make_float2(v0, v1);
                *(float2*)(OF + i1) = make_float2(v2, v3);
            } else {
                float s0 = v0 * 512.f, s1 = v1 * 512.f;
                float s2 = v2 * 512.f, s3 = v3 * 512.f;
                __half h0 = __float2half_rn(s0), h1 = __float2half_rn(s1);
                __half h2 = __float2half_rn(s2), h3 = __float2half_rn(s3);
                float r0 = s0 - __half2float(h0), r1 = s1 - __half2float(h1);
                float r2 = s2 - __half2float(h2), r3 = s3 - __half2float(h3);
                *(uint32_t*)(O0 + i0) = pack_h2(h0, h1);
                *(uint32_t*)(O0 + i1) = pack_h2(h2, h3);
                *(uint32_t*)(O1 + i0) = pack_h2(__float2half_rn(r0), __float2half_rn(r1));
                *(uint32_t*)(O1 + i1) = pack_h2(__float2half_rn(r2), __float2half_rn(r3));
            }
        }
    }
}

// ---------------------------------------------------------------------------
// DECODER GEMM — unchanged from Round 14 (3 terms, chained, 3 CTAs/SM).
// ---------------------------------------------------------------------------
__global__ __launch_bounds__(256, 3)
void gemm_dec(const __half* __restrict__ A0, const __half* __restrict__ A1,
              const __half* __restrict__ W0, const __half* __restrict__ W1,
              const float* __restrict__ bias,
              __half* __restrict__ O0, __half* __restrict__ O1,
              float* __restrict__ OF,
              int N, int K, int relu)
{
    constexpr int NPA = 2, NT = 3;
    constexpr uint32_t PARTA = 8192;
    constexpr uint32_t PARTB = 4096;
    constexpr uint32_t BOFF  = NPA * PARTA;
    constexpr uint32_t STAGE = NPA * (PARTA + PARTB);
    constexpr int TOT = NPA * 512 + NPA * 256;
    constexpr int PA_[3] = {0, 1, 0};
    constexpr int PB_[3] = {0, 0, 1};

    extern __shared__ __align__(16) char smem_raw[];
    const uint32_t smb = smem_u32(smem_raw);

    const int tid    = threadIdx.x;
    const int wid    = tid >> 5;
    const int lane   = tid & 31;
    const int warp_m = wid & 3;
    const int warp_n = wid >> 2;
    const int g      = lane >> 2;
    const int tg     = lane & 3;
    const int bm     = blockIdx.y * 128;
    const int bn     = blockIdx.x * 64;
    const int C      = K >> 5;

    const __half* Pp[4] = {A0, A1, W0, W1};

    auto load_stage = [&](int c, int slot) {
        const uint32_t sbase = smb + (uint32_t)slot * STAGE;
        #pragma unroll
        for (int s = 0; s < TOT / 256; s++) {
            int i = s * 256 + tid;
            const __half* src;
            uint32_t dst;
            if (i < NPA * 512) {
                int p = i >> 9, j = i & 511;
                uint32_t row = (uint32_t)(j >> 2), ch = (uint32_t)(j & 3);
                src = Pp[p] + (size_t)(bm + row) * K + c * 32 + ch * 8;
                dst = sbase + (uint32_t)p * PARTA + sw64(row, ch);
            } else {
                int q = i - NPA * 512;
                int p = q >> 8, j = q & 255;
                uint32_t row = (uint32_t)(j >> 2), ch = (uint32_t)(j & 3);
                src = Pp[NPA + p] + (size_t)(bn + row) * K + c * 32 + ch * 8;
                dst = sbase + BOFF + (uint32_t)p * PARTB + sw64(row, ch);
            }
            cp16(dst, src);
        }
        asm volatile("cp.async.commit_group;" ::: "memory");
    };

    load_stage(0, 0);
    if (C > 1) load_stage(1, 1);

    float acc[2][4][4];
    #pragma unroll
    for (int i = 0; i < 2; i++)
        #pragma unroll
        for (int j = 0; j < 4; j++)
            #pragma unroll
            for (int e = 0; e < 4; e++) acc[i][j][e] = 0.0f;

    const uint32_t lrA = (uint32_t)((lane & 7) + ((lane >> 3) & 1) * 8);
    const uint32_t lcA = (uint32_t)((lane >> 4) & 1);
    const uint32_t lrB = (uint32_t)((lane & 7) + ((lane >> 4) & 1) * 8);
    const uint32_t lcB = (uint32_t)((lane >> 3) & 1);
    uint32_t laneA[2], laneB[2];
    #pragma unroll
    for (int kh = 0; kh < 2; kh++) {
        laneA[kh] = (uint32_t)(warp_m * 32) * 64u + sw64(lrA, lcA + 2u * kh);
        laneB[kh] = (uint32_t)(warp_n * 32) * 64u + sw64(lrB, lcB + 2u * kh);
    }

    for (int c = 0; c < C; c++) {
        if (c + 1 < C) asm volatile("cp.async.wait_group 1;" ::: "memory");
        else           asm volatile("cp.async.wait_group 0;" ::: "memory");
        __syncthreads();

        if (c + 2 < C) load_stage(c + 2, (c + 2) % 3);

        const uint32_t sb0 = smb + (uint32_t)(c % 3) * STAGE;

        #pragma unroll
        for (int t = 0; t < NT; t++) {
            #pragma unroll
            for (int kh = 0; kh < 2; kh++) {
                const uint32_t aBase = sb0 + (uint32_t)PA_[t] * PARTA + laneA[kh];
                const uint32_t bBase = sb0 + BOFF + (uint32_t)PB_[t] * PARTB + laneB[kh];
                uint32_t af[2][4], bf[2][4];
                ldsm4(af[0], aBase);
                ldsm4(af[1], aBase + 16u * 64u);
                ldsm4(bf[0], bBase);
                ldsm4(bf[1], bBase + 16u * 64u);
                #pragma unroll
                for (int nt = 0; nt < 4; nt++) {
                    uint32_t b0 = bf[nt >> 1][(nt & 1) * 2];
                    uint32_t b1 = bf[nt >> 1][(nt & 1) * 2 + 1];
                    #pragma unroll
                    for (int mt = 0; mt < 2; mt++)
                        mma16816(acc[mt][nt], af[mt], b0, b1);
                }
            }
        }
    }

    const float SCL = 1.0f / 262144.0f;       // 2^-18
    #pragma unroll
    for (int mt = 0; mt < 2; mt++) {
        #pragma unroll
        for (int nt = 0; nt < 4; nt++) {
            const int row = bm + warp_m * 32 + mt * 16 + g;
            const int col = bn + warp_n * 32 + nt * 8 + tg * 2;
            const float bz0 = __ldg(bias + col);
            const float bz1 = __ldg(bias + col + 1);
            float v0 = acc[mt][nt][0] * SCL + bz0;
            float v1 = acc[mt][nt][1] * SCL + bz1;
            float v2 = acc[mt][nt][2] * SCL + bz0;   // row + 8
            float v3 = acc[mt][nt][3] * SCL + bz1;
            if (relu) {
                v0 = fmaxf(v0, 0.f); v1 = fmaxf(v1, 0.f);
                v2 = fmaxf(v2, 0.f); v3 = fmaxf(v3, 0.f);
            }
            const size_t i0 = (size_t)row * N + col;
            const size_t i1 = (size_t)(row + 8) * N + col;
            if (OF) {
                *(float2*)(OF + i0) = make_float2(v0, v1);
                *(float2*)(OF + i1) = make_float2(v2, v3);
            } else {
                float s0 = v0 * 512.f, s1 = v1 * 512.f;
                float s2 = v2 * 512.f, s3 = v3 * 512.f;
                __half h0 = __float2half_rn(s0), h1 = __float2half_rn(s1);
                __half h2 = __float2half_rn(s2), h3 = __float2half_rn(s3);
                float r0 = s0 - __half2float(h0), r1 = s1 - __half2float(h1);
                float r2 = s2 - __half2float(h2), r3 = s3 - __half2float(h3);
                *(uint32_t*)(O0 + i0) = pack_h2(h0, h1);
                *(uint32_t*)(O0 + i1) = pack_h2(h2, h3);
                *(uint32_t*)(O1 + i0) = pack_h2(__float2half_rn(r0), __float2half_rn(r1));
                *(uint32_t*)(O1 + i1) = pack_h2(__float2half_rn(r2), __float2half_rn(r3));
            }
        }
    }
}

// ---------------------------------------------------------------------------
// x -> 2-part fp16 split (scaled by 512)
// ---------------------------------------------------------------------------
__global__ void conv_x_kernel(const float* __restrict__ x,
                              __half* __restrict__ o0, __half* __restrict__ o1)
{
    size_t i = ((size_t)blockIdx.x * blockDim.x + threadIdx.x) * 2;
    float x0 = x[i] * 512.f, x1 = x[i + 1] * 512.f;
    __half h0 = __float2half_rn(x0), h1 = __float2half_rn(x1);
    float r0 = x0 - __half2float(h0), r1 = x1 - __half2float(h1);
    *(uint32_t*)(o0 + i) = pack_h2(h0, h1);
    *(uint32_t*)(o1 + i) = pack_h2(__float2half_rn(r0), __float2half_rn(r1));
}

// ---------------------------------------------------------------------------
// Fused weight conversion (one launch): W[K,N] -> transposed 2-part splits.
// ---------------------------------------------------------------------------
struct WArgs {
    const float* src[8];
    unsigned off[8];
    int ksh[8];
    int N[8];
};
__global__ void conv_w_all(WArgs A, __half* __restrict__ o0, __half* __restrict__ o1)
{
    const int l = blockIdx.y;
    const int tot = A.N[l] << A.ksh[l];
    const int idx = blockIdx.x * blockDim.x + threadIdx.x;
    if (idx >= tot) return;
    const int n = idx >> A.ksh[l];
    const int k = idx & ((1 << A.ksh[l]) - 1);
    float w = A.src[l][(size_t)k * A.N[l] + n] * 512.f;
    __half h = __float2half_rn(w);
    const unsigned o = A.off[l] + idx;
    o0[o] = h;
    o1[o] = __float2half_rn(w - __half2float(h));
}

// ---------------------------------------------------------------------------
// Exact per-token top-256-of-1024 by h^2 (radix select on float bit pattern).
// Output = 2-way fp16 split (scaled by 512) of (kept ? h : 0).
// ---------------------------------------------------------------------------
__global__ __launch_bounds__(256)
void topk_mask_kernel(const float* __restrict__ H,
                      __half* __restrict__ o0, __half* __restrict__ o1)
{
    const int tid = threadIdx.x;
    const size_t row = (size_t)blockIdx.x * HDIM;

    __shared__ unsigned ebits[HDIM];
    __shared__ unsigned hist[256];
    __shared__ unsigned sc[256];
    __shared__ unsigned s_pref, s_r;

    float4 hv = ((const float4*)(H + row))[tid];
    unsigned v0 = __float_as_uint(hv.x * hv.x);
    unsigned v1 = __float_as_uint(hv.y * hv.y);
    unsigned v2 = __float_as_uint(hv.z * hv.z);
    unsigned v3 = __float_as_uint(hv.w * hv.w);
    ebits[4 * tid + 0] = v0; ebits[4 * tid + 1] = v1;
    ebits[4 * tid + 2] = v2; ebits[4 * tid + 3] = v3;
    if (tid == 0) { s_pref = 0u; s_r = KSEL; }
    __syncthreads();

    #pragma unroll
    for (int pass = 0; pass < 4; pass++) {
        const int shift = 24 - 8 * pass;
        const unsigned pref = s_pref;
        const unsigned r    = s_r;
        hist[tid] = 0u;
        __syncthreads();
        #pragma unroll
        for (int j = 0; j < 4; j++) {
            unsigned v = ebits[4 * tid + j];
            bool cand = (pass == 0) || ((v >> (shift + 8)) == (pref >> (shift + 8)));
            if (cand) atomicAdd(&hist[(v >> shift) & 0xFFu], 1u);
        }
        __syncthreads();
        sc[tid] = hist[tid];
        __syncthreads();
        for (int off = 1; off < 256; off <<= 1) {
            unsigned add = (tid + off < 256) ? sc[tid + off] : 0u;
            __syncthreads();
            sc[tid] += add;
            __syncthreads();
        }
        unsigned above = (tid == 255) ? 0u : sc[tid + 1];
        if (sc[tid] >= r && above < r) {
            s_pref = pref | ((unsigned)tid << shift);
            s_r    = r - above;
        }
        __syncthreads();
    }

    const unsigned thr  = s_pref;
    const unsigned need = s_r;

    unsigned vv[4] = {v0, v1, v2, v3};
    unsigned pos[4];
    unsigned myc = 0;
    #pragma unroll
    for (int j = 0; j < 4; j++) { pos[j] = myc; myc += (vv[j] == thr) ? 1u : 0u; }
    sc[tid] = myc;
    __syncthreads();
    for (int off = 1; off < 256; off <<= 1) {
        unsigned add = (tid >= off) ? sc[tid - off] : 0u;
        __syncthreads();
        sc[tid] += add;
        __syncthreads();
    }
    const unsigned base = sc[tid] - myc;

    float h[4] = {hv.x, hv.y, hv.z, hv.w};
    uint32_t w0[2], w1[2];
    #pragma unroll
    for (int e = 0; e < 2; e++) {
        __half hh[2], ll[2];
        #pragma unroll
        for (int q = 0; q < 2; q++) {
            int j = 2 * e + q;
            bool keep = (vv[j] > thr) || (vv[j] == thr && (base + pos[j]) < need);
            float o = (keep ? h[j] : 0.0f) * 512.f;
            hh[q] = __float2half_rn(o);
            ll[q] = __float2half_rn(o - __half2float(hh[q]));
        }
        w0[e] = pack_h2(hh[0], hh[1]);
        w1[e] = pack_h2(ll[0], ll[1]);
    }
    ((uint2*)(o0 + row))[tid] = make_uint2(w0[0], w0[1]);
    ((uint2*)(o1 + row))[tid] = make_uint2(w1[0], w1[1]);
}

// ---------------------------------------------------------------------------
// kernel_launch
// ---------------------------------------------------------------------------
extern "C" void kernel_launch(void* const* d_in, const int* in_sizes, int n_in,
                              void* d_out, int out_size)
{
    const float* x         = (const float*)d_in[0];
    const float* mask_prev = (const float*)d_in[1];
    const bool inter = (in_sizes[4] == HDIM * 512);

    const float *ew[4], *eb[4], *dw[4], *db[4];
    for (int i = 0; i < 4; i++) {
        if (inter) {
            ew[i] = (const float*)d_in[2 + 4 * i]; eb[i] = (const float*)d_in[3 + 4 * i];
            dw[i] = (const float*)d_in[4 + 4 * i]; db[i] = (const float*)d_in[5 + 4 * i];
        } else {
            ew[i] = (const float*)d_in[2 + 2 * i]; eb[i] = (const float*)d_in[3 + 2 * i];
            dw[i] = (const float*)d_in[10 + 2 * i]; db[i] = (const float*)d_in[11 + 2 * i];
        }
    }

    __half *a0, *a1, *b0, *b1, *w0, *w1;
    float* hF;
    cudaGetSymbolAddress((void**)&a0, g_a0); cudaGetSymbolAddress((void**)&a1, g_a1);
    cudaGetSymbolAddress((void**)&b0, g_b0); cudaGetSymbolAddress((void**)&b1, g_b1);
    cudaGetSymbolAddress((void**)&w0, g_w0); cudaGetSymbolAddress((void**)&w1, g_w1);
    cudaGetSymbolAddress((void**)&hF, g_hF);

    const int SM_GEMM = 3 * 2 * (8192 + 4096);   // 73728/CTA
    cudaFuncSetAttribute(gemm_enc, cudaFuncAttributeMaxDynamicSharedMemorySize, SM_GEMM);
    cudaFuncSetAttribute(gemm_dec, cudaFuncAttributeMaxDynamicSharedMemorySize, SM_GEMM);

    // ---- weight conversion (one fused launch) ----
    struct { const float* w; int K, N; unsigned off; } L[8] = {
        {ew[0], 512, 512, 0},        {ew[1], 512, 512, 262144},
        {ew[2], 512, 512, 524288},   {ew[3], 512, 1024, 786432},
        {dw[0], 1024, 512, 1310720}, {dw[1], 512, 512, 1835008},
        {dw[2], 512, 512, 2097152},  {dw[3], 512, 512, 2359296}};
    WArgs wa;
    for (int l = 0; l < 8; l++) {
        wa.src[l] = L[l].w;
        wa.off[l] = L[l].off;
        wa.ksh[l] = (L[l].K == 1024) ? 10 : 9;
        wa.N[l]   = L[l].N;
    }
    conv_w_all<<<dim3(2048, 8), 256>>>(wa, w0, w1);

    // ---- x split ----
    conv_x_kernel<<<(MTOK * 512 / 2) / 256, 256>>>(x, a0, a1);

    const dim3 blk(256);
    // ---- encoder (2-part, 4 terms, debiased accumulation) ----
    gemm_enc<<<dim3(8, 512), blk, SM_GEMM>>>(a0, a1,
        w0 + L[0].off, w1 + L[0].off, eb[0], nullptr,
        b0, b1, nullptr, 512, 512, 1);
    gemm_enc<<<dim3(8, 512), blk, SM_GEMM>>>(b0, b1,
        w0 + L[1].off, w1 + L[1].off, eb[1], nullptr,
        a0, a1, nullptr, 512, 512, 1);
    gemm_enc<<<dim3(8, 512), blk, SM_GEMM>>>(a0, a1,
        w0 + L[2].off, w1 + L[2].off, eb[2], nullptr,
        b0, b1, nullptr, 512, 512, 1);
    gemm_enc<<<dim3(16, 512), blk, SM_GEMM>>>(b0, b1,
        w0 + L[3].off, w1 + L[3].off, eb[3], mask_prev,
        nullptr, nullptr, hF, 1024, 512, 0);

    // ---- top-k sparsify -> split decoder input ----
    topk_mask_kernel<<<MTOK, 256>>>(hF, a0, a1);

    // ---- decoder (2-way split, 3 terms, 3 CTAs/SM) ----
    gemm_dec<<<dim3(8, 512), blk, SM_GEMM>>>(a0, a1,
        w0 + L[4].off, w1 + L[4].off, db[0],
        b0, b1, nullptr, 512, 1024, 1);
    gemm_dec<<<dim3(8, 512), blk, SM_GEMM>>>(b0, b1,
        w0 + L[5].off, w1 + L[5].off, db[1],
        a0, a1, nullptr, 512, 512, 1);
    gemm_dec<<<dim3(8, 512), blk, SM_GEMM>>>(a0, a1,
        w0 + L[6].off, w1 + L[6].off, db[2],
        b0, b1, nullptr, 512, 512, 1);
    gemm_dec<<<dim3(8, 512), blk, SM_GEMM>>>(b0, b1,
        w0 + L[7].off, w1 + L[7].off, db[3],
        nullptr, nullptr, (float*)d_out, 512, 512, 0);
}

// round 16
// speedup vs baseline: 2.1806x; 1.0175x over previous
#include <cuda_runtime.h>
#include <cuda_fp16.h>
#include <cstdint>

#define MTOK   65536
#define HDIM   1024
#define KSEL   256

// ---------------------------------------------------------------------------
// Static scratch. Activations: 2-part fp16 splits of (value * 512).
// Weights: transposed [N,K] 2-part splits of (value * 512).
// ---------------------------------------------------------------------------
__device__ __half g_a0[(size_t)MTOK * HDIM];
__device__ __half g_a1[(size_t)MTOK * HDIM];
__device__ __half g_b0[(size_t)MTOK * HDIM];
__device__ __half g_b1[(size_t)MTOK * HDIM];
__device__ float  g_hF[(size_t)MTOK * HDIM];
#define WT_TOTAL 2621440
__device__ __half g_w0[WT_TOTAL];
__device__ __half g_w1[WT_TOTAL];

// ---------------------------------------------------------------------------
// Helpers
// ---------------------------------------------------------------------------
__device__ __forceinline__ uint32_t smem_u32(const void* p) {
    uint32_t a;
    asm("{ .reg .u64 t; cvta.to.shared.u64 t, %1; cvt.u32.u64 %0, t; }" : "=r"(a) : "l"(p));
    return a;
}
__device__ __forceinline__ void ldsm4(uint32_t* r, uint32_t addr) {
    asm volatile("ldmatrix.sync.aligned.m8n8.x4.shared.b16 {%0,%1,%2,%3}, [%4];"
                 : "=r"(r[0]), "=r"(r[1]), "=r"(r[2]), "=r"(r[3]) : "r"(addr));
}
__device__ __forceinline__ void cp16(uint32_t dst, const void* src) {
    asm volatile("cp.async.cg.shared.global [%0], [%1], 16;" :: "r"(dst), "l"(src) : "memory");
}
__device__ __forceinline__ void mma16816(float* c, const uint32_t* a, uint32_t b0, uint32_t b1) {
    asm volatile(
        "mma.sync.aligned.m16n8k16.row.col.f32.f16.f16.f32 "
        "{%0,%1,%2,%3}, {%4,%5,%6,%7}, {%8,%9}, {%0,%1,%2,%3};"
        : "+f"(c[0]), "+f"(c[1]), "+f"(c[2]), "+f"(c[3])
        : "r"(a[0]), "r"(a[1]), "r"(a[2]), "r"(a[3]), "r"(b0), "r"(b1));
}
// D = A*B + 0  (fresh accumulator: no inherited C-chain truncation bias)
__device__ __forceinline__ void mma16816_z(float* d, const uint32_t* a, uint32_t b0, uint32_t b1) {
    asm volatile(
        "mma.sync.aligned.m16n8k16.row.col.f32.f16.f16.f32 "
        "{%0,%1,%2,%3}, {%4,%5,%6,%7}, {%8,%9}, {%10,%11,%12,%13};"
        : "=f"(d[0]), "=f"(d[1]), "=f"(d[2]), "=f"(d[3])
        : "r"(a[0]), "r"(a[1]), "r"(a[2]), "r"(a[3]), "r"(b0), "r"(b1),
          "f"(0.0f), "f"(0.0f), "f"(0.0f), "f"(0.0f));
}
__device__ __forceinline__ uint32_t pack_h2(__half a, __half b) {
    __half2 h2 = __halves2half2(a, b);
    return *reinterpret_cast<uint32_t*>(&h2);
}
// 64B-row smem swizzle: 16B-chunk ch of row -> ch ^ ((row>>1)&3).
__device__ __forceinline__ uint32_t sw64(uint32_t row, uint32_t ch) {
    return row * 64u + ((ch ^ ((row >> 1) & 3u)) << 4);
}

// ---------------------------------------------------------------------------
// ENCODER GEMM.  true C = act( 2^-18 * sum_{4 terms} A_pa @ B_pb^T + bias )
// Terms {a0b0, a1b0, a0b1, a1b1}; per-k16 fresh-accumulator extraction +
// RN FADD folding. Fragment loads HOISTED per k-half (8 ldsm4, each part
// loaded once) — frag values and mma issue order identical to Round 15,
// so hF (and thus top-k and rel_err) is bit-frozen.
// CTA 128x64, 256 threads, 3-stage cp.async, 1 barrier/chunk, 2 CTAs/SM.
// ---------------------------------------------------------------------------
__global__ __launch_bounds__(256, 2)
void gemm_enc(const __half* __restrict__ A0, const __half* __restrict__ A1,
              const __half* __restrict__ W0, const __half* __restrict__ W1,
              const float* __restrict__ bias, const float* __restrict__ mask,
              __half* __restrict__ O0, __half* __restrict__ O1,
              float* __restrict__ OF,
              int N, int K, int relu)
{
    constexpr int NPA = 2, NT = 4;
    constexpr uint32_t PARTA = 8192;
    constexpr uint32_t PARTB = 4096;
    constexpr uint32_t BOFF  = NPA * PARTA;
    constexpr uint32_t STAGE = NPA * (PARTA + PARTB);
    constexpr int TOT = NPA * 512 + NPA * 256;
    constexpr int PA_[4] = {0, 1, 0, 1};
    constexpr int PB_[4] = {0, 0, 1, 1};

    extern __shared__ __align__(16) char smem_raw[];
    const uint32_t smb = smem_u32(smem_raw);

    const int tid    = threadIdx.x;
    const int wid    = tid >> 5;
    const int lane   = tid & 31;
    const int warp_m = wid & 3;
    const int warp_n = wid >> 2;
    const int g      = lane >> 2;
    const int tg     = lane & 3;
    const int bm     = blockIdx.y * 128;
    const int bn     = blockIdx.x * 64;
    const int C      = K >> 5;

    const __half* Pp[4] = {A0, A1, W0, W1};

    auto load_stage = [&](int c, int slot) {
        const uint32_t sbase = smb + (uint32_t)slot * STAGE;
        #pragma unroll
        for (int s = 0; s < TOT / 256; s++) {
            int i = s * 256 + tid;
            const __half* src;
            uint32_t dst;
            if (i < NPA * 512) {
                int p = i >> 9, j = i & 511;
                uint32_t row = (uint32_t)(j >> 2), ch = (uint32_t)(j & 3);
                src = Pp[p] + (size_t)(bm + row) * K + c * 32 + ch * 8;
                dst = sbase + (uint32_t)p * PARTA + sw64(row, ch);
            } else {
                int q = i - NPA * 512;
                int p = q >> 8, j = q & 255;
                uint32_t row = (uint32_t)(j >> 2), ch = (uint32_t)(j & 3);
                src = Pp[NPA + p] + (size_t)(bn + row) * K + c * 32 + ch * 8;
                dst = sbase + BOFF + (uint32_t)p * PARTB + sw64(row, ch);
            }
            cp16(dst, src);
        }
        asm volatile("cp.async.commit_group;" ::: "memory");
    };

    load_stage(0, 0);
    if (C > 1) load_stage(1, 1);

    float acc[2][4][4];
    #pragma unroll
    for (int i = 0; i < 2; i++)
        #pragma unroll
        for (int j = 0; j < 4; j++)
            #pragma unroll
            for (int e = 0; e < 4; e++) acc[i][j][e] = 0.0f;

    const uint32_t lrA = (uint32_t)((lane & 7) + ((lane >> 3) & 1) * 8);
    const uint32_t lcA = (uint32_t)((lane >> 4) & 1);
    const uint32_t lrB = (uint32_t)((lane & 7) + ((lane >> 4) & 1) * 8);
    const uint32_t lcB = (uint32_t)((lane >> 3) & 1);
    uint32_t laneA[2], laneB[2];
    #pragma unroll
    for (int kh = 0; kh < 2; kh++) {
        laneA[kh] = (uint32_t)(warp_m * 32) * 64u + sw64(lrA, lcA + 2u * kh);
        laneB[kh] = (uint32_t)(warp_n * 32) * 64u + sw64(lrB, lcB + 2u * kh);
    }

    for (int c = 0; c < C; c++) {
        if (c + 1 < C) asm volatile("cp.async.wait_group 1;" ::: "memory");
        else           asm volatile("cp.async.wait_group 0;" ::: "memory");
        __syncthreads();

        if (c + 2 < C) load_stage(c + 2, (c + 2) % 3);

        const uint32_t sb0 = smb + (uint32_t)(c % 3) * STAGE;

        #pragma unroll
        for (int kh = 0; kh < 2; kh++) {
            // Hoisted fragment loads: each part loaded exactly once per kh.
            uint32_t af[2][2][4];   // [part][mt]
            uint32_t bf[2][2][4];   // [part][quad]
            #pragma unroll
            for (int p = 0; p < 2; p++) {
                const uint32_t aB = sb0 + (uint32_t)p * PARTA + laneA[kh];
                ldsm4(af[p][0], aB);
                ldsm4(af[p][1], aB + 16u * 64u);
                const uint32_t bB = sb0 + BOFF + (uint32_t)p * PARTB + laneB[kh];
                ldsm4(bf[p][0], bB);
                ldsm4(bf[p][1], bB + 16u * 64u);
            }
            float tmp[2][4][4];
            #pragma unroll
            for (int t = 0; t < NT; t++) {
                const int pa = PA_[t], pb = PB_[t];
                #pragma unroll
                for (int nt = 0; nt < 4; nt++) {
                    uint32_t b0 = bf[pb][nt >> 1][(nt & 1) * 2];
                    uint32_t b1 = bf[pb][nt >> 1][(nt & 1) * 2 + 1];
                    #pragma unroll
                    for (int mt = 0; mt < 2; mt++) {
                        if (t == 0) mma16816_z(tmp[mt][nt], af[pa][mt], b0, b1);
                        else        mma16816(tmp[mt][nt], af[pa][mt], b0, b1);
                    }
                }
            }
            #pragma unroll
            for (int mt = 0; mt < 2; mt++)
                #pragma unroll
                for (int nt = 0; nt < 4; nt++)
                    #pragma unroll
                    for (int e = 0; e < 4; e++)
                        acc[mt][nt][e] += tmp[mt][nt][e];
        }
    }

    // ---- epilogue (identical per-element math to Round 15) ----
    const float SCL = 1.0f / 262144.0f;       // 2^-18
    #pragma unroll
    for (int mt = 0; mt < 2; mt++) {
        #pragma unroll
        for (int nt = 0; nt < 4; nt++) {
            const int row = bm + warp_m * 32 + mt * 16 + g;
            const int col = bn + warp_n * 32 + nt * 8 + tg * 2;
            const float bz0 = __ldg(bias + col);
            const float bz1 = __ldg(bias + col + 1);
            float v0 = acc[mt][nt][0] * SCL + bz0;
            float v1 = acc[mt][nt][1] * SCL + bz1;
            float v2 = acc[mt][nt][2] * SCL + bz0;   // row + 8
            float v3 = acc[mt][nt][3] * SCL + bz1;
            if (relu) {
                v0 = fmaxf(v0, 0.f); v1 = fmaxf(v1, 0.f);
                v2 = fmaxf(v2, 0.f); v3 = fmaxf(v3, 0.f);
            }
            const size_t i0 = (size_t)row * N + col;
            const size_t i1 = (size_t)(row + 8) * N + col;
            if (OF) {
                if (mask) {
                    const float2 m0 = *(const float2*)(mask + i0);
                    const float2 m1 = *(const float2*)(mask + i1);
                    if (m0.x > 0.f) v0 = 0.f;
                    if (m0.y > 0.f) v1 = 0.f;
                    if (m1.x > 0.f) v2 = 0.f;
                    if (m1.y > 0.f) v3 = 0.f;
                }
                *(float2*)(OF + i0) = make_float2(v0, v1);
                *(float2*)(OF + i1) = make_float2(v2, v3);
            } else {
                float s0 = v0 * 512.f, s1 = v1 * 512.f;
                float s2 = v2 * 512.f, s3 = v3 * 512.f;
                __half h0 = __float2half_rn(s0), h1 = __float2half_rn(s1);
                __half h2 = __float2half_rn(s2), h3 = __float2half_rn(s3);
                float r0 = s0 - __half2float(h0), r1 = s1 - __half2float(h1);
                float r2 = s2 - __half2float(h2), r3 = s3 - __half2float(h3);
                *(uint32_t*)(O0 + i0) = pack_h2(h0, h1);
                *(uint32_t*)(O0 + i1) = pack_h2(h2, h3);
                *(uint32_t*)(O1 + i0) = pack_h2(__float2half_rn(r0), __float2half_rn(r1));
                *(uint32_t*)(O1 + i1) = pack_h2(__float2half_rn(r2), __float2half_rn(r3));
            }
        }
    }
}

// ---------------------------------------------------------------------------
// DECODER GEMM.  3 terms {a0b0, a1b0, a0b1}, direct HW chaining.
// Loop reordered c -> kh -> t to enable the same fragment hoisting (decoder is
// downstream of top-k; its accumulation-order change is a smooth ~1e-7 shift).
// 3 CTAs/SM; hoisting also LOWERS register pressure (no redundant frags).
// ---------------------------------------------------------------------------
__global__ __launch_bounds__(256, 3)
void gemm_dec(const __half* __restrict__ A0, const __half* __restrict__ A1,
              const __half* __restrict__ W0, const __half* __restrict__ W1,
              const float* __restrict__ bias,
              __half* __restrict__ O0, __half* __restrict__ O1,
              float* __restrict__ OF,
              int N, int K, int relu)
{
    constexpr int NPA = 2, NT = 3;
    constexpr uint32_t PARTA = 8192;
    constexpr uint32_t PARTB = 4096;
    constexpr uint32_t BOFF  = NPA * PARTA;
    constexpr uint32_t STAGE = NPA * (PARTA + PARTB);
    constexpr int TOT = NPA * 512 + NPA * 256;
    constexpr int PA_[3] = {0, 1, 0};
    constexpr int PB_[3] = {0, 0, 1};

    extern __shared__ __align__(16) char smem_raw[];
    const uint32_t smb = smem_u32(smem_raw);

    const int tid    = threadIdx.x;
    const int wid    = tid >> 5;
    const int lane   = tid & 31;
    const int warp_m = wid & 3;
    const int warp_n = wid >> 2;
    const int g      = lane >> 2;
    const int tg     = lane & 3;
    const int bm     = blockIdx.y * 128;
    const int bn     = blockIdx.x * 64;
    const int C      = K >> 5;

    const __half* Pp[4] = {A0, A1, W0, W1};

    auto load_stage = [&](int c, int slot) {
        const uint32_t sbase = smb + (uint32_t)slot * STAGE;
        #pragma unroll
        for (int s = 0; s < TOT / 256; s++) {
            int i = s * 256 + tid;
            const __half* src;
            uint32_t dst;
            if (i < NPA * 512) {
                int p = i >> 9, j = i & 511;
                uint32_t row = (uint32_t)(j >> 2), ch = (uint32_t)(j & 3);
                src = Pp[p] + (size_t)(bm + row) * K + c * 32 + ch * 8;
                dst = sbase + (uint32_t)p * PARTA + sw64(row, ch);
            } else {
                int q = i - NPA * 512;
                int p = q >> 8, j = q & 255;
                uint32_t row = (uint32_t)(j >> 2), ch = (uint32_t)(j & 3);
                src = Pp[NPA + p] + (size_t)(bn + row) * K + c * 32 + ch * 8;
                dst = sbase + BOFF + (uint32_t)p * PARTB + sw64(row, ch);
            }
            cp16(dst, src);
        }
        asm volatile("cp.async.commit_group;" ::: "memory");
    };

    load_stage(0, 0);
    if (C > 1) load_stage(1, 1);

    float acc[2][4][4];
    #pragma unroll
    for (int i = 0; i < 2; i++)
        #pragma unroll
        for (int j = 0; j < 4; j++)
            #pragma unroll
            for (int e = 0; e < 4; e++) acc[i][j][e] = 0.0f;

    const uint32_t lrA = (uint32_t)((lane & 7) + ((lane >> 3) & 1) * 8);
    const uint32_t lcA = (uint32_t)((lane >> 4) & 1);
    const uint32_t lrB = (uint32_t)((lane & 7) + ((lane >> 4) & 1) * 8);
    const uint32_t lcB = (uint32_t)((lane >> 3) & 1);
    uint32_t laneA[2], laneB[2];
    #pragma unroll
    for (int kh = 0; kh < 2; kh++) {
        laneA[kh] = (uint32_t)(warp_m * 32) * 64u + sw64(lrA, lcA + 2u * kh);
        laneB[kh] = (uint32_t)(warp_n * 32) * 64u + sw64(lrB, lcB + 2u * kh);
    }

    for (int c = 0; c < C; c++) {
        if (c + 1 < C) asm volatile("cp.async.wait_group 1;" ::: "memory");
        else           asm volatile("cp.async.wait_group 0;" ::: "memory");
        __syncthreads();

        if (c + 2 < C) load_stage(c + 2, (c + 2) % 3);

        const uint32_t sb0 = smb + (uint32_t)(c % 3) * STAGE;

        #pragma unroll
        for (int kh = 0; kh < 2; kh++) {
            uint32_t af[2][2][4];
            uint32_t bf[2][2][4];
            #pragma unroll
            for (int p = 0; p < 2; p++) {
                const uint32_t aB = sb0 + (uint32_t)p * PARTA + laneA[kh];
                ldsm4(af[p][0], aB);
                ldsm4(af[p][1], aB + 16u * 64u);
                const uint32_t bB = sb0 + BOFF + (uint32_t)p * PARTB + laneB[kh];
                ldsm4(bf[p][0], bB);
                ldsm4(bf[p][1], bB + 16u * 64u);
            }
            #pragma unroll
            for (int t = 0; t < NT; t++) {
                const int pa = PA_[t], pb = PB_[t];
                #pragma unroll
                for (int nt = 0; nt < 4; nt++) {
                    uint32_t b0 = bf[pb][nt >> 1][(nt & 1) * 2];
                    uint32_t b1 = bf[pb][nt >> 1][(nt & 1) * 2 + 1];
                    #pragma unroll
                    for (int mt = 0; mt < 2; mt++)
                        mma16816(acc[mt][nt], af[pa][mt], b0, b1);
                }
            }
        }
    }

    const float SCL = 1.0f / 262144.0f;       // 2^-18
    #pragma unroll
    for (int mt = 0; mt < 2; mt++) {
        #pragma unroll
        for (int nt = 0; nt < 4; nt++) {
            const int row = bm + warp_m * 32 + mt * 16 + g;
            const int col = bn + warp_n * 32 + nt * 8 + tg * 2;
            const float bz0 = __ldg(bias + col);
            const float bz1 = __ldg(bias + col + 1);
            float v0 = acc[mt][nt][0] * SCL + bz0;
            float v1 = acc[mt][nt][1] * SCL + bz1;
            float v2 = acc[mt][nt][2] * SCL + bz0;   // row + 8
            float v3 = acc[mt][nt][3] * SCL + bz1;
            if (relu) {
                v0 = fmaxf(v0, 0.f); v1 = fmaxf(v1, 0.f);
                v2 = fmaxf(v2, 0.f); v3 = fmaxf(v3, 0.f);
            }
            const size_t i0 = (size_t)row * N + col;
            const size_t i1 = (size_t)(row + 8) * N + col;
            if (OF) {
                *(float2*)(OF + i0) = make_float2(v0, v1);
                *(float2*)(OF + i1) = make_float2(v2, v3);
            } else {
                float s0 = v0 * 512.f, s1 = v1 * 512.f;
                float s2 = v2 * 512.f, s3 = v3 * 512.f;
                __half h0 = __float2half_rn(s0), h1 = __float2half_rn(s1);
                __half h2 = __float2half_rn(s2), h3 = __float2half_rn(s3);
                float r0 = s0 - __half2float(h0), r1 = s1 - __half2float(h1);
                float r2 = s2 - __half2float(h2), r3 = s3 - __half2float(h3);
                *(uint32_t*)(O0 + i0) = pack_h2(h0, h1);
                *(uint32_t*)(O0 + i1) = pack_h2(h2, h3);
                *(uint32_t*)(O1 + i0) = pack_h2(__float2half_rn(r0), __float2half_rn(r1));
                *(uint32_t*)(O1 + i1) = pack_h2(__float2half_rn(r2), __float2half_rn(r3));
            }
        }
    }
}

// ---------------------------------------------------------------------------
// x -> 2-part fp16 split (scaled by 512)
// ---------------------------------------------------------------------------
__global__ void conv_x_kernel(const float* __restrict__ x,
                              __half* __restrict__ o0, __half* __restrict__ o1)
{
    size_t i = ((size_t)blockIdx.x * blockDim.x + threadIdx.x) * 2;
    float x0 = x[i] * 512.f, x1 = x[i + 1] * 512.f;
    __half h0 = __float2half_rn(x0), h1 = __float2half_rn(x1);
    float r0 = x0 - __half2float(h0), r1 = x1 - __half2float(h1);
    *(uint32_t*)(o0 + i) = pack_h2(h0, h1);
    *(uint32_t*)(o1 + i) = pack_h2(__float2half_rn(r0), __float2half_rn(r1));
}

// ---------------------------------------------------------------------------
// Fused weight conversion (one launch): W[K,N] -> transposed 2-part splits.
// ---------------------------------------------------------------------------
struct WArgs {
    const float* src[8];
    unsigned off[8];
    int ksh[8];
    int N[8];
};
__global__ void conv_w_all(WArgs A, __half* __restrict__ o0, __half* __restrict__ o1)
{
    const int l = blockIdx.y;
    const int tot = A.N[l] << A.ksh[l];
    const int idx = blockIdx.x * blockDim.x + threadIdx.x;
    if (idx >= tot) return;
    const int n = idx >> A.ksh[l];
    const int k = idx & ((1 << A.ksh[l]) - 1);
    float w = A.src[l][(size_t)k * A.N[l] + n] * 512.f;
    __half h = __float2half_rn(w);
    const unsigned o = A.off[l] + idx;
    o0[o] = h;
    o1[o] = __float2half_rn(w - __half2float(h));
}

// ---------------------------------------------------------------------------
// Exact per-token top-256-of-1024 by h^2 (radix select on float bit pattern).
// Output = 2-way fp16 split (scaled by 512) of (kept ? h : 0).
// ---------------------------------------------------------------------------
__global__ __launch_bounds__(256)
void topk_mask_kernel(const float* __restrict__ H,
                      __half* __restrict__ o0, __half* __restrict__ o1)
{
    const int tid = threadIdx.x;
    const size_t row = (size_t)blockIdx.x * HDIM;

    __shared__ unsigned ebits[HDIM];
    __shared__ unsigned hist[256];
    __shared__ unsigned sc[256];
    __shared__ unsigned s_pref, s_r;

    float4 hv = ((const float4*)(H + row))[tid];
    unsigned v0 = __float_as_uint(hv.x * hv.x);
    unsigned v1 = __float_as_uint(hv.y * hv.y);
    unsigned v2 = __float_as_uint(hv.z * hv.z);
    unsigned v3 = __float_as_uint(hv.w * hv.w);
    ebits[4 * tid + 0] = v0; ebits[4 * tid + 1] = v1;
    ebits[4 * tid + 2] = v2; ebits[4 * tid + 3] = v3;
    if (tid == 0) { s_pref = 0u; s_r = KSEL; }
    __syncthreads();

    #pragma unroll
    for (int pass = 0; pass < 4; pass++) {
        const int shift = 24 - 8 * pass;
        const unsigned pref = s_pref;
        const unsigned r    = s_r;
        hist[tid] = 0u;
        __syncthreads();
        #pragma unroll
        for (int j = 0; j < 4; j++) {
            unsigned v = ebits[4 * tid + j];
            bool cand = (pass == 0) || ((v >> (shift + 8)) == (pref >> (shift + 8)));
            if (cand) atomicAdd(&hist[(v >> shift) & 0xFFu], 1u);
        }
        __syncthreads();
        sc[tid] = hist[tid];
        __syncthreads();
        for (int off = 1; off < 256; off <<= 1) {
            unsigned add = (tid + off < 256) ? sc[tid + off] : 0u;
            __syncthreads();
            sc[tid] += add;
            __syncthreads();
        }
        unsigned above = (tid == 255) ? 0u : sc[tid + 1];
        if (sc[tid] >= r && above < r) {
            s_pref = pref | ((unsigned)tid << shift);
            s_r    = r - above;
        }
        __syncthreads();
    }

    const unsigned thr  = s_pref;
    const unsigned need = s_r;

    unsigned vv[4] = {v0, v1, v2, v3};
    unsigned pos[4];
    unsigned myc = 0;
    #pragma unroll
    for (int j = 0; j < 4; j++) { pos[j] = myc; myc += (vv[j] == thr) ? 1u : 0u; }
    sc[tid] = myc;
    __syncthreads();
    for (int off = 1; off < 256; off <<= 1) {
        unsigned add = (tid >= off) ? sc[tid - off] : 0u;
        __syncthreads();
        sc[tid] += add;
        __syncthreads();
    }
    const unsigned base = sc[tid] - myc;

    float h[4] = {hv.x, hv.y, hv.z, hv.w};
    uint32_t w0[2], w1[2];
    #pragma unroll
    for (int e = 0; e < 2; e++) {
        __half hh[2], ll[2];
        #pragma unroll
        for (int q = 0; q < 2; q++) {
            int j = 2 * e + q;
            bool keep = (vv[j] > thr) || (vv[j] == thr && (base + pos[j]) < need);
            float o = (keep ? h[j] : 0.0f) * 512.f;
            hh[q] = __float2half_rn(o);
            ll[q] = __float2half_rn(o - __half2float(hh[q]));
        }
        w0[e] = pack_h2(hh[0], hh[1]);
        w1[e] = pack_h2(ll[0], ll[1]);
    }
    ((uint2*)(o0 + row))[tid] = make_uint2(w0[0], w0[1]);
    ((uint2*)(o1 + row))[tid] = make_uint2(w1[0], w1[1]);
}

// ---------------------------------------------------------------------------
// kernel_launch
// ---------------------------------------------------------------------------
extern "C" void kernel_launch(void* const* d_in, const int* in_sizes, int n_in,
                              void* d_out, int out_size)
{
    const float* x         = (const float*)d_in[0];
    const float* mask_prev = (const float*)d_in[1];
    const bool inter = (in_sizes[4] == HDIM * 512);

    const float *ew[4], *eb[4], *dw[4], *db[4];
    for (int i = 0; i < 4; i++) {
        if (inter) {
            ew[i] = (const float*)d_in[2 + 4 * i]; eb[i] = (const float*)d_in[3 + 4 * i];
            dw[i] = (const float*)d_in[4 + 4 * i]; db[i] = (const float*)d_in[5 + 4 * i];
        } else {
            ew[i] = (const float*)d_in[2 + 2 * i]; eb[i] = (const float*)d_in[3 + 2 * i];
            dw[i] = (const float*)d_in[10 + 2 * i]; db[i] = (const float*)d_in[11 + 2 * i];
        }
    }

    __half *a0, *a1, *b0, *b1, *w0, *w1;
    float* hF;
    cudaGetSymbolAddress((void**)&a0, g_a0); cudaGetSymbolAddress((void**)&a1, g_a1);
    cudaGetSymbolAddress((void**)&b0, g_b0); cudaGetSymbolAddress((void**)&b1, g_b1);
    cudaGetSymbolAddress((void**)&w0, g_w0); cudaGetSymbolAddress((void**)&w1, g_w1);
    cudaGetSymbolAddress((void**)&hF, g_hF);

    const int SM_GEMM = 3 * 2 * (8192 + 4096);   // 73728/CTA
    cudaFuncSetAttribute(gemm_enc, cudaFuncAttributeMaxDynamicSharedMemorySize, SM_GEMM);
    cudaFuncSetAttribute(gemm_dec, cudaFuncAttributeMaxDynamicSharedMemorySize, SM_GEMM);

    // ---- weight conversion (one fused launch) ----
    struct { const float* w; int K, N; unsigned off; } L[8] = {
        {ew[0], 512, 512, 0},        {ew[1], 512, 512, 262144},
        {ew[2], 512, 512, 524288},   {ew[3], 512, 1024, 786432},
        {dw[0], 1024, 512, 1310720}, {dw[1], 512, 512, 1835008},
        {dw[2], 512, 512, 2097152},  {dw[3], 512, 512, 2359296}};
    WArgs wa;
    for (int l = 0; l < 8; l++) {
        wa.src[l] = L[l].w;
        wa.off[l] = L[l].off;
        wa.ksh[l] = (L[l].K == 1024) ? 10 : 9;
        wa.N[l]   = L[l].N;
    }
    conv_w_all<<<dim3(2048, 8), 256>>>(wa, w0, w1);

    // ---- x split ----
    conv_x_kernel<<<(MTOK * 512 / 2) / 256, 256>>>(x, a0, a1);

    const dim3 blk(256);
    // ---- encoder (2-part, 4 terms, debiased accumulation) ----
    gemm_enc<<<dim3(8, 512), blk, SM_GEMM>>>(a0, a1,
        w0 + L[0].off, w1 + L[0].off, eb[0], nullptr,
        b0, b1, nullptr, 512, 512, 1);
    gemm_enc<<<dim3(8, 512), blk, SM_GEMM>>>(b0, b1,
        w0 + L[1].off, w1 + L[1].off, eb[1], nullptr,
        a0, a1, nullptr, 512, 512, 1);
    gemm_enc<<<dim3(8, 512), blk, SM_GEMM>>>(a0, a1,
        w0 + L[2].off, w1 + L[2].off, eb[2], nullptr,
        b0, b1, nullptr, 512, 512, 1);
    gemm_enc<<<dim3(16, 512), blk, SM_GEMM>>>(b0, b1,
        w0 + L[3].off, w1 + L[3].off, eb[3], mask_prev,
        nullptr, nullptr, hF, 1024, 512, 0);

    // ---- top-k sparsify -> split decoder input ----
    topk_mask_kernel<<<MTOK, 256>>>(hF, a0, a1);

    // ---- decoder (2-way split, 3 terms, 3 CTAs/SM) ----
    gemm_dec<<<dim3(8, 512), blk, SM_GEMM>>>(a0, a1,
        w0 + L[4].off, w1 + L[4].off, db[0],
        b0, b1, nullptr, 512, 1024, 1);
    gemm_dec<<<dim3(8, 512), blk, SM_GEMM>>>(b0, b1,
        w0 + L[5].off, w1 + L[5].off, db[1],
        a0, a1, nullptr, 512, 512, 1);
    gemm_dec<<<dim3(8, 512), blk, SM_GEMM>>>(a0, a1,
        w0 + L[6].off, w1 + L[6].off, db[2],
        b0, b1, nullptr, 512, 512, 1);
    gemm_dec<<<dim3(8, 512), blk, SM_GEMM>>>(b0, b1,
        w0 + L[7].off, w1 + L[7].off, db[3],
        nullptr, nullptr, (float*)d_out, 512, 512, 0);
}

// round 17
// speedup vs baseline: 2.3246x; 1.0660x over previous
#include <cuda_runtime.h>
#include <cuda_fp16.h>
#include <cstdint>

#define MTOK   65536
#define HDIM   1024
#define KSEL   256

// ---------------------------------------------------------------------------
// Static scratch. Activations: 2-part fp16 splits of (value * 512).
// Weights: transposed [N,K] 2-part splits of (value * 512).
// ---------------------------------------------------------------------------
__device__ __half g_a0[(size_t)MTOK * HDIM];
__device__ __half g_a1[(size_t)MTOK * HDIM];
__device__ __half g_b0[(size_t)MTOK * HDIM];
__device__ __half g_b1[(size_t)MTOK * HDIM];
__device__ float  g_hF[(size_t)MTOK * HDIM];
#define WT_TOTAL 2621440
__device__ __half g_w0[WT_TOTAL];
__device__ __half g_w1[WT_TOTAL];

// ---------------------------------------------------------------------------
// Helpers
// ---------------------------------------------------------------------------
__device__ __forceinline__ uint32_t smem_u32(const void* p) {
    uint32_t a;
    asm("{ .reg .u64 t; cvta.to.shared.u64 t, %1; cvt.u32.u64 %0, t; }" : "=r"(a) : "l"(p));
    return a;
}
__device__ __forceinline__ void ldsm4(uint32_t* r, uint32_t addr) {
    asm volatile("ldmatrix.sync.aligned.m8n8.x4.shared.b16 {%0,%1,%2,%3}, [%4];"
                 : "=r"(r[0]), "=r"(r[1]), "=r"(r[2]), "=r"(r[3]) : "r"(addr));
}
__device__ __forceinline__ void cp16(uint32_t dst, const void* src) {
    asm volatile("cp.async.cg.shared.global [%0], [%1], 16;" :: "r"(dst), "l"(src) : "memory");
}
__device__ __forceinline__ void mma16816(float* c, const uint32_t* a, uint32_t b0, uint32_t b1) {
    asm volatile(
        "mma.sync.aligned.m16n8k16.row.col.f32.f16.f16.f32 "
        "{%0,%1,%2,%3}, {%4,%5,%6,%7}, {%8,%9}, {%0,%1,%2,%3};"
        : "+f"(c[0]), "+f"(c[1]), "+f"(c[2]), "+f"(c[3])
        : "r"(a[0]), "r"(a[1]), "r"(a[2]), "r"(a[3]), "r"(b0), "r"(b1));
}
// D = A*B + 0  (fresh accumulator: no inherited C-chain truncation bias)
__device__ __forceinline__ void mma16816_z(float* d, const uint32_t* a, uint32_t b0, uint32_t b1) {
    asm volatile(
        "mma.sync.aligned.m16n8k16.row.col.f32.f16.f16.f32 "
        "{%0,%1,%2,%3}, {%4,%5,%6,%7}, {%8,%9}, {%10,%11,%12,%13};"
        : "=f"(d[0]), "=f"(d[1]), "=f"(d[2]), "=f"(d[3])
        : "r"(a[0]), "r"(a[1]), "r"(a[2]), "r"(a[3]), "r"(b0), "r"(b1),
          "f"(0.0f), "f"(0.0f), "f"(0.0f), "f"(0.0f));
}
__device__ __forceinline__ uint32_t pack_h2(__half a, __half b) {
    __half2 h2 = __halves2half2(a, b);
    return *reinterpret_cast<uint32_t*>(&h2);
}
// 64B-row smem swizzle: 16B-chunk ch of row -> ch ^ ((row>>1)&3).
__device__ __forceinline__ uint32_t sw64(uint32_t row, uint32_t ch) {
    return row * 64u + ((ch ^ ((row >> 1) & 3u)) << 4);
}

// ---------------------------------------------------------------------------
// ENCODER GEMM.  true C = act( 2^-18 * sum_{3 terms} A_pa @ B_pb^T + bias )
// Terms {a0b0, a1b0, a0b1} — the a1b1 term (2^-22 relative, below existing
// split-truncation noise) is dropped. Per-k16 fresh-accumulator extraction +
// RN FADD folding (debias). Hoisted fragment loads.
// CTA 128x64, 256 threads, 3-stage cp.async, 1 barrier/chunk, 2 CTAs/SM.
// ---------------------------------------------------------------------------
__global__ __launch_bounds__(256, 2)
void gemm_enc(const __half* __restrict__ A0, const __half* __restrict__ A1,
              const __half* __restrict__ W0, const __half* __restrict__ W1,
              const float* __restrict__ bias, const float* __restrict__ mask,
              __half* __restrict__ O0, __half* __restrict__ O1,
              float* __restrict__ OF,
              int N, int K, int relu)
{
    constexpr int NPA = 2, NT = 3;
    constexpr uint32_t PARTA = 8192;
    constexpr uint32_t PARTB = 4096;
    constexpr uint32_t BOFF  = NPA * PARTA;
    constexpr uint32_t STAGE = NPA * (PARTA + PARTB);
    constexpr int TOT = NPA * 512 + NPA * 256;
    constexpr int PA_[3] = {0, 1, 0};
    constexpr int PB_[3] = {0, 0, 1};

    extern __shared__ __align__(16) char smem_raw[];
    const uint32_t smb = smem_u32(smem_raw);

    const int tid    = threadIdx.x;
    const int wid    = tid >> 5;
    const int lane   = tid & 31;
    const int warp_m = wid & 3;
    const int warp_n = wid >> 2;
    const int g      = lane >> 2;
    const int tg     = lane & 3;
    const int bm     = blockIdx.y * 128;
    const int bn     = blockIdx.x * 64;
    const int C      = K >> 5;

    const __half* Pp[4] = {A0, A1, W0, W1};

    auto load_stage = [&](int c, int slot) {
        const uint32_t sbase = smb + (uint32_t)slot * STAGE;
        #pragma unroll
        for (int s = 0; s < TOT / 256; s++) {
            int i = s * 256 + tid;
            const __half* src;
            uint32_t dst;
            if (i < NPA * 512) {
                int p = i >> 9, j = i & 511;
                uint32_t row = (uint32_t)(j >> 2), ch = (uint32_t)(j & 3);
                src = Pp[p] + (size_t)(bm + row) * K + c * 32 + ch * 8;
                dst = sbase + (uint32_t)p * PARTA + sw64(row, ch);
            } else {
                int q = i - NPA * 512;
                int p = q >> 8, j = q & 255;
                uint32_t row = (uint32_t)(j >> 2), ch = (uint32_t)(j & 3);
                src = Pp[NPA + p] + (size_t)(bn + row) * K + c * 32 + ch * 8;
                dst = sbase + BOFF + (uint32_t)p * PARTB + sw64(row, ch);
            }
            cp16(dst, src);
        }
        asm volatile("cp.async.commit_group;" ::: "memory");
    };

    load_stage(0, 0);
    if (C > 1) load_stage(1, 1);

    float acc[2][4][4];
    #pragma unroll
    for (int i = 0; i < 2; i++)
        #pragma unroll
        for (int j = 0; j < 4; j++)
            #pragma unroll
            for (int e = 0; e < 4; e++) acc[i][j][e] = 0.0f;

    const uint32_t lrA = (uint32_t)((lane & 7) + ((lane >> 3) & 1) * 8);
    const uint32_t lcA = (uint32_t)((lane >> 4) & 1);
    const uint32_t lrB = (uint32_t)((lane & 7) + ((lane >> 4) & 1) * 8);
    const uint32_t lcB = (uint32_t)((lane >> 3) & 1);
    uint32_t laneA[2], laneB[2];
    #pragma unroll
    for (int kh = 0; kh < 2; kh++) {
        laneA[kh] = (uint32_t)(warp_m * 32) * 64u + sw64(lrA, lcA + 2u * kh);
        laneB[kh] = (uint32_t)(warp_n * 32) * 64u + sw64(lrB, lcB + 2u * kh);
    }

    for (int c = 0; c < C; c++) {
        if (c + 1 < C) asm volatile("cp.async.wait_group 1;" ::: "memory");
        else           asm volatile("cp.async.wait_group 0;" ::: "memory");
        __syncthreads();

        if (c + 2 < C) load_stage(c + 2, (c + 2) % 3);

        const uint32_t sb0 = smb + (uint32_t)(c % 3) * STAGE;

        #pragma unroll
        for (int kh = 0; kh < 2; kh++) {
            uint32_t af[2][2][4];   // [part][mt]
            uint32_t bf[2][2][4];   // [part][quad]
            #pragma unroll
            for (int p = 0; p < 2; p++) {
                const uint32_t aB = sb0 + (uint32_t)p * PARTA + laneA[kh];
                ldsm4(af[p][0], aB);
                ldsm4(af[p][1], aB + 16u * 64u);
                const uint32_t bB = sb0 + BOFF + (uint32_t)p * PARTB + laneB[kh];
                ldsm4(bf[p][0], bB);
                ldsm4(bf[p][1], bB + 16u * 64u);
            }
            float tmp[2][4][4];
            #pragma unroll
            for (int t = 0; t < NT; t++) {
                const int pa = PA_[t], pb = PB_[t];
                #pragma unroll
                for (int nt = 0; nt < 4; nt++) {
                    uint32_t b0 = bf[pb][nt >> 1][(nt & 1) * 2];
                    uint32_t b1 = bf[pb][nt >> 1][(nt & 1) * 2 + 1];
                    #pragma unroll
                    for (int mt = 0; mt < 2; mt++) {
                        if (t == 0) mma16816_z(tmp[mt][nt], af[pa][mt], b0, b1);
                        else        mma16816(tmp[mt][nt], af[pa][mt], b0, b1);
                    }
                }
            }
            #pragma unroll
            for (int mt = 0; mt < 2; mt++)
                #pragma unroll
                for (int nt = 0; nt < 4; nt++)
                    #pragma unroll
                    for (int e = 0; e < 4; e++)
                        acc[mt][nt][e] += tmp[mt][nt][e];
        }
    }

    // ---- epilogue ----
    const float SCL = 1.0f / 262144.0f;       // 2^-18
    #pragma unroll
    for (int mt = 0; mt < 2; mt++) {
        #pragma unroll
        for (int nt = 0; nt < 4; nt++) {
            const int row = bm + warp_m * 32 + mt * 16 + g;
            const int col = bn + warp_n * 32 + nt * 8 + tg * 2;
            const float bz0 = __ldg(bias + col);
            const float bz1 = __ldg(bias + col + 1);
            float v0 = acc[mt][nt][0] * SCL + bz0;
            float v1 = acc[mt][nt][1] * SCL + bz1;
            float v2 = acc[mt][nt][2] * SCL + bz0;   // row + 8
            float v3 = acc[mt][nt][3] * SCL + bz1;
            if (relu) {
                v0 = fmaxf(v0, 0.f); v1 = fmaxf(v1, 0.f);
                v2 = fmaxf(v2, 0.f); v3 = fmaxf(v3, 0.f);
            }
            const size_t i0 = (size_t)row * N + col;
            const size_t i1 = (size_t)(row + 8) * N + col;
            if (OF) {
                if (mask) {
                    const float2 m0 = *(const float2*)(mask + i0);
                    const float2 m1 = *(const float2*)(mask + i1);
                    if (m0.x > 0.f) v0 = 0.f;
                    if (m0.y > 0.f) v1 = 0.f;
                    if (m1.x > 0.f) v2 = 0.f;
                    if (m1.y > 0.f) v3 = 0.f;
                }
                *(float2*)(OF + i0) = make_float2(v0, v1);
                *(float2*)(OF + i1) = make_float2(v2, v3);
            } else {
                float s0 = v0 * 512.f, s1 = v1 * 512.f;
                float s2 = v2 * 512.f, s3 = v3 * 512.f;
                __half h0 = __float2half_rn(s0), h1 = __float2half_rn(s1);
                __half h2 = __float2half_rn(s2), h3 = __float2half_rn(s3);
                float r0 = s0 - __half2float(h0), r1 = s1 - __half2float(h1);
                float r2 = s2 - __half2float(h2), r3 = s3 - __half2float(h3);
                *(uint32_t*)(O0 + i0) = pack_h2(h0, h1);
                *(uint32_t*)(O0 + i1) = pack_h2(h2, h3);
                *(uint32_t*)(O1 + i0) = pack_h2(__float2half_rn(r0), __float2half_rn(r1));
                *(uint32_t*)(O1 + i1) = pack_h2(__float2half_rn(r2), __float2half_rn(r3));
            }
        }
    }
}

// ---------------------------------------------------------------------------
// DECODER GEMM.  3 terms {a0b0, a1b0, a0b1}, direct HW chaining, c->kh->t,
// hoisted fragments. 3 CTAs/SM. Unchanged from Round 16.
// ---------------------------------------------------------------------------
__global__ __launch_bounds__(256, 3)
void gemm_dec(const __half* __restrict__ A0, const __half* __restrict__ A1,
              const __half* __restrict__ W0, const __half* __restrict__ W1,
              const float* __restrict__ bias,
              __half* __restrict__ O0, __half* __restrict__ O1,
              float* __restrict__ OF,
              int N, int K, int relu)
{
    constexpr int NPA = 2, NT = 3;
    constexpr uint32_t PARTA = 8192;
    constexpr uint32_t PARTB = 4096;
    constexpr uint32_t BOFF  = NPA * PARTA;
    constexpr uint32_t STAGE = NPA * (PARTA + PARTB);
    constexpr int TOT = NPA * 512 + NPA * 256;
    constexpr int PA_[3] = {0, 1, 0};
    constexpr int PB_[3] = {0, 0, 1};

    extern __shared__ __align__(16) char smem_raw[];
    const uint32_t smb = smem_u32(smem_raw);

    const int tid    = threadIdx.x;
    const int wid    = tid >> 5;
    const int lane   = tid & 31;
    const int warp_m = wid & 3;
    const int warp_n = wid >> 2;
    const int g      = lane >> 2;
    const int tg     = lane & 3;
    const int bm     = blockIdx.y * 128;
    const int bn     = blockIdx.x * 64;
    const int C      = K >> 5;

    const __half* Pp[4] = {A0, A1, W0, W1};

    auto load_stage = [&](int c, int slot) {
        const uint32_t sbase = smb + (uint32_t)slot * STAGE;
        #pragma unroll
        for (int s = 0; s < TOT / 256; s++) {
            int i = s * 256 + tid;
            const __half* src;
            uint32_t dst;
            if (i < NPA * 512) {
                int p = i >> 9, j = i & 511;
                uint32_t row = (uint32_t)(j >> 2), ch = (uint32_t)(j & 3);
                src = Pp[p] + (size_t)(bm + row) * K + c * 32 + ch * 8;
                dst = sbase + (uint32_t)p * PARTA + sw64(row, ch);
            } else {
                int q = i - NPA * 512;
                int p = q >> 8, j = q & 255;
                uint32_t row = (uint32_t)(j >> 2), ch = (uint32_t)(j & 3);
                src = Pp[NPA + p] + (size_t)(bn + row) * K + c * 32 + ch * 8;
                dst = sbase + BOFF + (uint32_t)p * PARTB + sw64(row, ch);
            }
            cp16(dst, src);
        }
        asm volatile("cp.async.commit_group;" ::: "memory");
    };

    load_stage(0, 0);
    if (C > 1) load_stage(1, 1);

    float acc[2][4][4];
    #pragma unroll
    for (int i = 0; i < 2; i++)
        #pragma unroll
        for (int j = 0; j < 4; j++)
            #pragma unroll
            for (int e = 0; e < 4; e++) acc[i][j][e] = 0.0f;

    const uint32_t lrA = (uint32_t)((lane & 7) + ((lane >> 3) & 1) * 8);
    const uint32_t lcA = (uint32_t)((lane >> 4) & 1);
    const uint32_t lrB = (uint32_t)((lane & 7) + ((lane >> 4) & 1) * 8);
    const uint32_t lcB = (uint32_t)((lane >> 3) & 1);
    uint32_t laneA[2], laneB[2];
    #pragma unroll
    for (int kh = 0; kh < 2; kh++) {
        laneA[kh] = (uint32_t)(warp_m * 32) * 64u + sw64(lrA, lcA + 2u * kh);
        laneB[kh] = (uint32_t)(warp_n * 32) * 64u + sw64(lrB, lcB + 2u * kh);
    }

    for (int c = 0; c < C; c++) {
        if (c + 1 < C) asm volatile("cp.async.wait_group 1;" ::: "memory");
        else           asm volatile("cp.async.wait_group 0;" ::: "memory");
        __syncthreads();

        if (c + 2 < C) load_stage(c + 2, (c + 2) % 3);

        const uint32_t sb0 = smb + (uint32_t)(c % 3) * STAGE;

        #pragma unroll
        for (int kh = 0; kh < 2; kh++) {
            uint32_t af[2][2][4];
            uint32_t bf[2][2][4];
            #pragma unroll
            for (int p = 0; p < 2; p++) {
                const uint32_t aB = sb0 + (uint32_t)p * PARTA + laneA[kh];
                ldsm4(af[p][0], aB);
                ldsm4(af[p][1], aB + 16u * 64u);
                const uint32_t bB = sb0 + BOFF + (uint32_t)p * PARTB + laneB[kh];
                ldsm4(bf[p][0], bB);
                ldsm4(bf[p][1], bB + 16u * 64u);
            }
            #pragma unroll
            for (int t = 0; t < NT; t++) {
                const int pa = PA_[t], pb = PB_[t];
                #pragma unroll
                for (int nt = 0; nt < 4; nt++) {
                    uint32_t b0 = bf[pb][nt >> 1][(nt & 1) * 2];
                    uint32_t b1 = bf[pb][nt >> 1][(nt & 1) * 2 + 1];
                    #pragma unroll
                    for (int mt = 0; mt < 2; mt++)
                        mma16816(acc[mt][nt], af[pa][mt], b0, b1);
                }
            }
        }
    }

    const float SCL = 1.0f / 262144.0f;       // 2^-18
    #pragma unroll
    for (int mt = 0; mt < 2; mt++) {
        #pragma unroll
        for (int nt = 0; nt < 4; nt++) {
            const int row = bm + warp_m * 32 + mt * 16 + g;
            const int col = bn + warp_n * 32 + nt * 8 + tg * 2;
            const float bz0 = __ldg(bias + col);
            const float bz1 = __ldg(bias + col + 1);
            float v0 = acc[mt][nt][0] * SCL + bz0;
            float v1 = acc[mt][nt][1] * SCL + bz1;
            float v2 = acc[mt][nt][2] * SCL + bz0;   // row + 8
            float v3 = acc[mt][nt][3] * SCL + bz1;
            if (relu) {
                v0 = fmaxf(v0, 0.f); v1 = fmaxf(v1, 0.f);
                v2 = fmaxf(v2, 0.f); v3 = fmaxf(v3, 0.f);
            }
            const size_t i0 = (size_t)row * N + col;
            const size_t i1 = (size_t)(row + 8) * N + col;
            if (OF) {
                *(float2*)(OF + i0) = make_float2(v0, v1);
                *(float2*)(OF + i1) = make_float2(v2, v3);
            } else {
                float s0 = v0 * 512.f, s1 = v1 * 512.f;
                float s2 = v2 * 512.f, s3 = v3 * 512.f;
                __half h0 = __float2half_rn(s0), h1 = __float2half_rn(s1);
                __half h2 = __float2half_rn(s2), h3 = __float2half_rn(s3);
                float r0 = s0 - __half2float(h0), r1 = s1 - __half2float(h1);
                float r2 = s2 - __half2float(h2), r3 = s3 - __half2float(h3);
                *(uint32_t*)(O0 + i0) = pack_h2(h0, h1);
                *(uint32_t*)(O0 + i1) = pack_h2(h2, h3);
                *(uint32_t*)(O1 + i0) = pack_h2(__float2half_rn(r0), __float2half_rn(r1));
                *(uint32_t*)(O1 + i1) = pack_h2(__float2half_rn(r2), __float2half_rn(r3));
            }
        }
    }
}

// ---------------------------------------------------------------------------
// x -> 2-part fp16 split (scaled by 512)
// ---------------------------------------------------------------------------
__global__ void conv_x_kernel(const float* __restrict__ x,
                              __half* __restrict__ o0, __half* __restrict__ o1)
{
    size_t i = ((size_t)blockIdx.x * blockDim.x + threadIdx.x) * 2;
    float x0 = x[i] * 512.f, x1 = x[i + 1] * 512.f;
    __half h0 = __float2half_rn(x0), h1 = __float2half_rn(x1);
    float r0 = x0 - __half2float(h0), r1 = x1 - __half2float(h1);
    *(uint32_t*)(o0 + i) = pack_h2(h0, h1);
    *(uint32_t*)(o1 + i) = pack_h2(__float2half_rn(r0), __float2half_rn(r1));
}

// ---------------------------------------------------------------------------
// Fused weight conversion (one launch): W[K,N] -> transposed 2-part splits.
// ---------------------------------------------------------------------------
struct WArgs {
    const float* src[8];
    unsigned off[8];
    int ksh[8];
    int N[8];
};
__global__ void conv_w_all(WArgs A, __half* __restrict__ o0, __half* __restrict__ o1)
{
    const int l = blockIdx.y;
    const int tot = A.N[l] << A.ksh[l];
    const int idx = blockIdx.x * blockDim.x + threadIdx.x;
    if (idx >= tot) return;
    const int n = idx >> A.ksh[l];
    const int k = idx & ((1 << A.ksh[l]) - 1);
    float w = A.src[l][(size_t)k * A.N[l] + n] * 512.f;
    __half h = __float2half_rn(w);
    const unsigned o = A.off[l] + idx;
    o0[o] = h;
    o1[o] = __float2half_rn(w - __half2float(h));
}

// ---------------------------------------------------------------------------
// Exact per-token top-256-of-1024 by h^2 (radix select on float bit pattern).
// Output = 2-way fp16 split (scaled by 512) of (kept ? h : 0).
// ---------------------------------------------------------------------------
__global__ __launch_bounds__(256)
void topk_mask_kernel(const float* __restrict__ H,
                      __half* __restrict__ o0, __half* __restrict__ o1)
{
    const int tid = threadIdx.x;
    const size_t row = (size_t)blockIdx.x * HDIM;

    __shared__ unsigned ebits[HDIM];
    __shared__ unsigned hist[256];
    __shared__ unsigned sc[256];
    __shared__ unsigned s_pref, s_r;

    float4 hv = ((const float4*)(H + row))[tid];
    unsigned v0 = __float_as_uint(hv.x * hv.x);
    unsigned v1 = __float_as_uint(hv.y * hv.y);
    unsigned v2 = __float_as_uint(hv.z * hv.z);
    unsigned v3 = __float_as_uint(hv.w * hv.w);
    ebits[4 * tid + 0] = v0; ebits[4 * tid + 1] = v1;
    ebits[4 * tid + 2] = v2; ebits[4 * tid + 3] = v3;
    if (tid == 0) { s_pref = 0u; s_r = KSEL; }
    __syncthreads();

    #pragma unroll
    for (int pass = 0; pass < 4; pass++) {
        const int shift = 24 - 8 * pass;
        const unsigned pref = s_pref;
        const unsigned r    = s_r;
        hist[tid] = 0u;
        __syncthreads();
        #pragma unroll
        for (int j = 0; j < 4; j++) {
            unsigned v = ebits[4 * tid + j];
            bool cand = (pass == 0) || ((v >> (shift + 8)) == (pref >> (shift + 8)));
            if (cand) atomicAdd(&hist[(v >> shift) & 0xFFu], 1u);
        }
        __syncthreads();
        sc[tid] = hist[tid];
        __syncthreads();
        for (int off = 1; off < 256; off <<= 1) {
            unsigned add = (tid + off < 256) ? sc[tid + off] : 0u;
            __syncthreads();
            sc[tid] += add;
            __syncthreads();
        }
        unsigned above = (tid == 255) ? 0u : sc[tid + 1];
        if (sc[tid] >= r && above < r) {
            s_pref = pref | ((unsigned)tid << shift);
            s_r    = r - above;
        }
        __syncthreads();
    }

    const unsigned thr  = s_pref;
    const unsigned need = s_r;

    unsigned vv[4] = {v0, v1, v2, v3};
    unsigned pos[4];
    unsigned myc = 0;
    #pragma unroll
    for (int j = 0; j < 4; j++) { pos[j] = myc; myc += (vv[j] == thr) ? 1u : 0u; }
    sc[tid] = myc;
    __syncthreads();
    for (int off = 1; off < 256; off <<= 1) {
        unsigned add = (tid >= off) ? sc[tid - off] : 0u;
        __syncthreads();
        sc[tid] += add;
        __syncthreads();
    }
    const unsigned base = sc[tid] - myc;

    float h[4] = {hv.x, hv.y, hv.z, hv.w};
    uint32_t w0[2], w1[2];
    #pragma unroll
    for (int e = 0; e < 2; e++) {
        __half hh[2], ll[2];
        #pragma unroll
        for (int q = 0; q < 2; q++) {
            int j = 2 * e + q;
            bool keep = (vv[j] > thr) || (vv[j] == thr && (base + pos[j]) < need);
            float o = (keep ? h[j] : 0.0f) * 512.f;
            hh[q] = __float2half_rn(o);
            ll[q] = __float2half_rn(o - __half2float(hh[q]));
        }
        w0[e] = pack_h2(hh[0], hh[1]);
        w1[e] = pack_h2(ll[0], ll[1]);
    }
    ((uint2*)(o0 + row))[tid] = make_uint2(w0[0], w0[1]);
    ((uint2*)(o1 + row))[tid] = make_uint2(w1[0], w1[1]);
}

// ---------------------------------------------------------------------------
// kernel_launch
// ---------------------------------------------------------------------------
extern "C" void kernel_launch(void* const* d_in, const int* in_sizes, int n_in,
                              void* d_out, int out_size)
{
    const float* x         = (const float*)d_in[0];
    const float* mask_prev = (const float*)d_in[1];
    const bool inter = (in_sizes[4] == HDIM * 512);

    const float *ew[4], *eb[4], *dw[4], *db[4];
    for (int i = 0; i < 4; i++) {
        if (inter) {
            ew[i] = (const float*)d_in[2 + 4 * i]; eb[i] = (const float*)d_in[3 + 4 * i];
            dw[i] = (const float*)d_in[4 + 4 * i]; db[i] = (const float*)d_in[5 + 4 * i];
        } else {
            ew[i] = (const float*)d_in[2 + 2 * i]; eb[i] = (const float*)d_in[3 + 2 * i];
            dw[i] = (const float*)d_in[10 + 2 * i]; db[i] = (const float*)d_in[11 + 2 * i];
        }
    }

    __half *a0, *a1, *b0, *b1, *w0, *w1;
    float* hF;
    cudaGetSymbolAddress((void**)&a0, g_a0); cudaGetSymbolAddress((void**)&a1, g_a1);
    cudaGetSymbolAddress((void**)&b0, g_b0); cudaGetSymbolAddress((void**)&b1, g_b1);
    cudaGetSymbolAddress((void**)&w0, g_w0); cudaGetSymbolAddress((void**)&w1, g_w1);
    cudaGetSymbolAddress((void**)&hF, g_hF);

    const int SM_GEMM = 3 * 2 * (8192 + 4096);   // 73728/CTA
    cudaFuncSetAttribute(gemm_enc, cudaFuncAttributeMaxDynamicSharedMemorySize, SM_GEMM);
    cudaFuncSetAttribute(gemm_dec, cudaFuncAttributeMaxDynamicSharedMemorySize, SM_GEMM);

    // ---- weight conversion (one fused launch) ----
    struct { const float* w; int K, N; unsigned off; } L[8] = {
        {ew[0], 512, 512, 0},        {ew[1], 512, 512, 262144},
        {ew[2], 512, 512, 524288},   {ew[3], 512, 1024, 786432},
        {dw[0], 1024, 512, 1310720}, {dw[1], 512, 512, 1835008},
        {dw[2], 512, 512, 2097152},  {dw[3], 512, 512, 2359296}};
    WArgs wa;
    for (int l = 0; l < 8; l++) {
        wa.src[l] = L[l].w;
        wa.off[l] = L[l].off;
        wa.ksh[l] = (L[l].K == 1024) ? 10 : 9;
        wa.N[l]   = L[l].N;
    }
    conv_w_all<<<dim3(2048, 8), 256>>>(wa, w0, w1);

    // ---- x split ----
    conv_x_kernel<<<(MTOK * 512 / 2) / 256, 256>>>(x, a0, a1);

    const dim3 blk(256);
    // ---- encoder (2-part, 3 terms, debiased accumulation) ----
    gemm_enc<<<dim3(8, 512), blk, SM_GEMM>>>(a0, a1,
        w0 + L[0].off, w1 + L[0].off, eb[0], nullptr,
        b0, b1, nullptr, 512, 512, 1);
    gemm_enc<<<dim3(8, 512), blk, SM_GEMM>>>(b0, b1,
        w0 + L[1].off, w1 + L[1].off, eb[1], nullptr,
        a0, a1, nullptr, 512, 512, 1);
    gemm_enc<<<dim3(8, 512), blk, SM_GEMM>>>(a0, a1,
        w0 + L[2].off, w1 + L[2].off, eb[2], nullptr,
        b0, b1, nullptr, 512, 512, 1);
    gemm_enc<<<dim3(16, 512), blk, SM_GEMM>>>(b0, b1,
        w0 + L[3].off, w1 + L[3].off, eb[3], mask_prev,
        nullptr, nullptr, hF, 1024, 512, 0);

    // ---- top-k sparsify -> split decoder input ----
    topk_mask_kernel<<<MTOK, 256>>>(hF, a0, a1);

    // ---- decoder (2-way split, 3 terms, 3 CTAs/SM) ----
    gemm_dec<<<dim3(8, 512), blk, SM_GEMM>>>(a0, a1,
        w0 + L[4].off, w1 + L[4].off, db[0],
        b0, b1, nullptr, 512, 1024, 1);
    gemm_dec<<<dim3(8, 512), blk, SM_GEMM>>>(b0, b1,
        w0 + L[5].off, w1 + L[5].off, db[1],
        a0, a1, nullptr, 512, 512, 1);
    gemm_dec<<<dim3(8, 512), blk, SM_GEMM>>>(a0, a1,
        w0 + L[6].off, w1 + L[6].off, db[2],
        b0, b1, nullptr, 512, 512, 1);
    gemm_dec<<<dim3(8, 512), blk, SM_GEMM>>>(b0, b1,
        w0 + L[7].off, w1 + L[7].off, db[3],
        nullptr, nullptr, (float*)d_out, 512, 512, 0);
}